// round 2
// baseline (speedup 1.0000x reference)
#include <cuda_runtime.h>
#include <cstdint>
#include <cstddef>

#define LAT 128
#define NNODES 50000
#define NEDGES 400000
#define EPSV 1e-5f

// Scratch: h0, h1, agg (node-sized) + e0, e1 (edge-sized), all [*,128] fp32.
__device__ float g_scratch[(size_t)(3 * NNODES + 2 * NEDGES) * LAT];

// ---------------------------------------------------------------------------
// Fused: gather/concat -> Linear(K,128)+ReLU -> Linear(128,128)+ReLU -> LN
//        -> (optional residual add) -> (store | atomic scatter-add)
// GMODE 0: raw dense input [nRows, KREAL] (encoders; K padded to 16)
// GMODE 1: 3-block gather  [ hA[idxA[r]] | hB[idxB[r]] | eIn[r] ]  (K=384)
// GMODE 2: 2-block direct  [ hA[r] | hB[r] ]                      (K=256)
// ATOMIC:  atomicAdd rows into outp[scatIdx[r]] instead of storing at r.
// ---------------------------------------------------------------------------
template <int K, int KREAL, int GMODE, bool ATOMIC>
__global__ __launch_bounds__(256) void fused_mlp(
    const float* __restrict__ raw,
    const float* __restrict__ hA, const float* __restrict__ hB,
    const float* __restrict__ eIn,
    const int* __restrict__ idxA, const int* __restrict__ idxB,
    const float* __restrict__ W1, const float* __restrict__ B1,
    const float* __restrict__ W2, const float* __restrict__ B2,
    const float* __restrict__ G, const float* __restrict__ BE,
    const float* __restrict__ res,
    float* __restrict__ outp,
    const int* __restrict__ scatIdx,
    int nRows)
{
    extern __shared__ float smem[];
    float* As = smem;               // [16][129]
    float* Bs = As + 16 * 129;      // [16][128]
    float* H1 = Bs + 16 * 128;      // [128][129]  (hidden, then reused for LN)

    const int tid = threadIdx.x;
    const int tx = tid & 15, ty = tid >> 4;
    const int blockRow = blockIdx.x * 128;

    float c[8][8];
#pragma unroll
    for (int i = 0; i < 8; i++)
#pragma unroll
        for (int j = 0; j < 8; j++) c[i][j] = 0.f;

    // Per-thread fixed gather coordinates for A-tile loads.
    const int r0 = tid >> 2;            // 0..63
    const int r1 = r0 + 64;             // 64..127
    const int kq = (tid & 3) * 4;       // 0,4,8,12 within 16-wide k tile
    const int g0 = blockRow + r0;
    const int g1 = blockRow + r1;
    int iA0 = 0, iA1 = 0, iB0 = 0, iB1 = 0;
    if constexpr (GMODE == 1) {
        iA0 = (g0 < nRows) ? idxA[g0] : 0;
        iA1 = (g1 < nRows) ? idxA[g1] : 0;
        iB0 = (g0 < nRows) ? idxB[g0] : 0;
        iB1 = (g1 < nRows) ? idxB[g1] : 0;
    }

    // ---------------- layer 1: [128 rows, K] @ [K, 128] ----------------
    constexpr int NT = K / 16;
    for (int kt = 0; kt < NT; kt++) {
        if constexpr (GMODE == 0) {
#pragma unroll
            for (int it = 0; it < 8; it++) {
                int idx = tid + 256 * it;
                int row = idx >> 4, k = idx & 15;
                int gr = blockRow + row;
                float v = (k < KREAL && gr < nRows) ? raw[(size_t)gr * KREAL + k] : 0.f;
                As[k * 129 + row] = v;
            }
        } else {
            const int blk = kt >> 3;
            const int kk0 = (kt & 7) * 16;
            const float* base;
            int ri0, ri1;
            if constexpr (GMODE == 2) {
                base = (blk == 0) ? hA : hB;
                ri0 = g0; ri1 = g1;
            } else {
                if (blk == 0)      { base = hA;  ri0 = iA0; ri1 = iA1; }
                else if (blk == 1) { base = hB;  ri0 = iB0; ri1 = iB1; }
                else               { base = eIn; ri0 = g0;  ri1 = g1;  }
            }
            float4 v0 = make_float4(0.f, 0.f, 0.f, 0.f), v1 = v0;
            if (g0 < nRows) v0 = *(const float4*)&base[(size_t)ri0 * LAT + kk0 + kq];
            if (g1 < nRows) v1 = *(const float4*)&base[(size_t)ri1 * LAT + kk0 + kq];
            As[(kq + 0) * 129 + r0] = v0.x;
            As[(kq + 1) * 129 + r0] = v0.y;
            As[(kq + 2) * 129 + r0] = v0.z;
            As[(kq + 3) * 129 + r0] = v0.w;
            As[(kq + 0) * 129 + r1] = v1.x;
            As[(kq + 1) * 129 + r1] = v1.y;
            As[(kq + 2) * 129 + r1] = v1.z;
            As[(kq + 3) * 129 + r1] = v1.w;
        }
        // W1 tile [16, 128]
#pragma unroll
        for (int it = 0; it < 2; it++) {
            int f = tid + 256 * it;           // float4 index among 512
            int krow = f >> 5, col4 = (f & 31) * 4;
            int kk = kt * 16 + krow;
            float4 bv = make_float4(0.f, 0.f, 0.f, 0.f);
            if (KREAL == K || kk < KREAL)
                bv = *(const float4*)&W1[(size_t)kk * LAT + col4];
            *(float4*)&Bs[krow * LAT + col4] = bv;
        }
        __syncthreads();
#pragma unroll
        for (int k = 0; k < 16; k++) {
            float a[8];
#pragma unroll
            for (int i = 0; i < 8; i++) a[i] = As[k * 129 + ty * 8 + i];
            float4 bb0 = *(float4*)&Bs[k * LAT + tx * 8];
            float4 bb1 = *(float4*)&Bs[k * LAT + tx * 8 + 4];
            float b[8] = {bb0.x, bb0.y, bb0.z, bb0.w, bb1.x, bb1.y, bb1.z, bb1.w};
#pragma unroll
            for (int i = 0; i < 8; i++)
#pragma unroll
                for (int j = 0; j < 8; j++) c[i][j] = fmaf(a[i], b[j], c[i][j]);
        }
        __syncthreads();
    }

    // bias1 + ReLU -> H1[hid][row] (transposed so layer2 reads it like As)
    {
        float4 q0 = *(const float4*)&B1[tx * 8];
        float4 q1 = *(const float4*)&B1[tx * 8 + 4];
        float bb[8] = {q0.x, q0.y, q0.z, q0.w, q1.x, q1.y, q1.z, q1.w};
#pragma unroll
        for (int i = 0; i < 8; i++)
#pragma unroll
            for (int j = 0; j < 8; j++)
                H1[(tx * 8 + j) * 129 + ty * 8 + i] = fmaxf(c[i][j] + bb[j], 0.f);
    }
    __syncthreads();

    // ---------------- layer 2: [128,128] @ [128,128] ----------------
#pragma unroll
    for (int i = 0; i < 8; i++)
#pragma unroll
        for (int j = 0; j < 8; j++) c[i][j] = 0.f;

    for (int kt = 0; kt < 8; kt++) {
#pragma unroll
        for (int it = 0; it < 2; it++) {
            int f = tid + 256 * it;
            int krow = f >> 5, col4 = (f & 31) * 4;
            *(float4*)&Bs[krow * LAT + col4] =
                *(const float4*)&W2[(size_t)(kt * 16 + krow) * LAT + col4];
        }
        __syncthreads();
#pragma unroll
        for (int k = 0; k < 16; k++) {
            float a[8];
#pragma unroll
            for (int i = 0; i < 8; i++) a[i] = H1[(kt * 16 + k) * 129 + ty * 8 + i];
            float4 bb0 = *(float4*)&Bs[k * LAT + tx * 8];
            float4 bb1 = *(float4*)&Bs[k * LAT + tx * 8 + 4];
            float b[8] = {bb0.x, bb0.y, bb0.z, bb0.w, bb1.x, bb1.y, bb1.z, bb1.w};
#pragma unroll
            for (int i = 0; i < 8; i++)
#pragma unroll
                for (int j = 0; j < 8; j++) c[i][j] = fmaf(a[i], b[j], c[i][j]);
        }
        __syncthreads();
    }

    // bias2 + ReLU -> H1 reused as S[row][col]
    {
        float4 q0 = *(const float4*)&B2[tx * 8];
        float4 q1 = *(const float4*)&B2[tx * 8 + 4];
        float bb[8] = {q0.x, q0.y, q0.z, q0.w, q1.x, q1.y, q1.z, q1.w};
#pragma unroll
        for (int i = 0; i < 8; i++)
#pragma unroll
            for (int j = 0; j < 8; j++)
                H1[(ty * 8 + i) * 129 + tx * 8 + j] = fmaxf(c[i][j] + bb[j], 0.f);
    }
    __syncthreads();

    // ---------------- LayerNorm + residual + output ----------------
    const int warp = tid >> 5, lane = tid & 31;
    float gq[4], beq[4];
#pragma unroll
    for (int q = 0; q < 4; q++) {
        gq[q] = G[lane + 32 * q];
        beq[q] = BE[lane + 32 * q];
    }
    for (int rr = 0; rr < 16; rr++) {
        int row = warp * 16 + rr;
        int grow = blockRow + row;
        float v[4];
#pragma unroll
        for (int q = 0; q < 4; q++) v[q] = H1[row * 129 + lane + 32 * q];
        float s = v[0] + v[1] + v[2] + v[3];
#pragma unroll
        for (int o = 16; o > 0; o >>= 1) s += __shfl_xor_sync(0xffffffffu, s, o);
        float mu = s * (1.0f / 128.0f);
        float sq = 0.f;
#pragma unroll
        for (int q = 0; q < 4; q++) {
            float d = v[q] - mu;
            sq = fmaf(d, d, sq);
        }
#pragma unroll
        for (int o = 16; o > 0; o >>= 1) sq += __shfl_xor_sync(0xffffffffu, sq, o);
        float rs = rsqrtf(sq * (1.0f / 128.0f) + EPSV);

        if (grow < nRows) {
            if constexpr (ATOMIC) {
                int drow = scatIdx[grow];
#pragma unroll
                for (int q = 0; q < 4; q++) {
                    int cc = lane + 32 * q;
                    float ov = (v[q] - mu) * rs * gq[q] + beq[q];
                    atomicAdd(&outp[(size_t)drow * LAT + cc], ov);
                }
            } else {
#pragma unroll
                for (int q = 0; q < 4; q++) {
                    int cc = lane + 32 * q;
                    float ov = (v[q] - mu) * rs * gq[q] + beq[q];
                    if (res) ov += res[(size_t)grow * LAT + cc];
                    outp[(size_t)grow * LAT + cc] = ov;
                }
            }
        }
    }
}

// ---------------------------------------------------------------------------
// Decoder: relu(h @ W1 + b1) @ W2 + b2, out width 3. One warp per row.
// ---------------------------------------------------------------------------
__global__ __launch_bounds__(256) void decoder_kernel(
    const float* __restrict__ h,
    const float* __restrict__ W1, const float* __restrict__ B1,
    const float* __restrict__ W2, const float* __restrict__ B2,
    float* __restrict__ out, int n)
{
    extern __shared__ float s[];
    float* W1s = s;              // [128][128]
    float* hs = s + 128 * 128;   // [8][128]
    int tid = threadIdx.x;
#pragma unroll
    for (int it = 0; it < 16; it++) {
        int f = tid + 256 * it;  // float4 index among 4096
        *(float4*)&W1s[f * 4] = *(const float4*)&W1[f * 4];
    }
    int warp = tid >> 5, lane = tid & 31;
    int row = blockIdx.x * 8 + warp;
#pragma unroll
    for (int q = 0; q < 4; q++)
        hs[warp * 128 + lane + 32 * q] =
            (row < n) ? h[(size_t)row * LAT + lane + 32 * q] : 0.f;
    __syncthreads();

    float acc[4];
#pragma unroll
    for (int q = 0; q < 4; q++) acc[q] = B1[lane + 32 * q];
    for (int k = 0; k < 128; k++) {
        float hv = hs[warp * 128 + k];
#pragma unroll
        for (int q = 0; q < 4; q++)
            acc[q] = fmaf(hv, W1s[k * 128 + lane + 32 * q], acc[q]);
    }
#pragma unroll
    for (int q = 0; q < 4; q++) acc[q] = fmaxf(acc[q], 0.f);

    float o[3];
#pragma unroll
    for (int oo = 0; oo < 3; oo++) {
        float p = 0.f;
#pragma unroll
        for (int q = 0; q < 4; q++)
            p = fmaf(acc[q], W2[(size_t)(lane + 32 * q) * 3 + oo], p);
#pragma unroll
        for (int off = 16; off > 0; off >>= 1)
            p += __shfl_xor_sync(0xffffffffu, p, off);
        o[oo] = p;
    }
    if (lane == 0 && row < n) {
        out[(size_t)row * 3 + 0] = o[0] + B2[0];
        out[(size_t)row * 3 + 1] = o[1] + B2[1];
        out[(size_t)row * 3 + 2] = o[2] + B2[2];
    }
}

__global__ void zero_kernel(float* __restrict__ p, int n)
{
    int i = blockIdx.x * blockDim.x + threadIdx.x;
    if (i < n) p[i] = 0.f;
}

// ---------------------------------------------------------------------------
extern "C" void kernel_launch(void* const* d_in, const int* in_sizes, int n_in,
                              void* d_out, int out_size)
{
    (void)in_sizes; (void)n_in; (void)out_size;
    const float* x  = (const float*)d_in[0];
    const float* ea = (const float*)d_in[1];
    const int*   ei = (const int*)d_in[2];
    const int* src = ei;             // edge_index[0]
    const int* dst = ei + NEDGES;    // edge_index[1]

    const float* ne_w1 = (const float*)d_in[3];
    const float* ne_b1 = (const float*)d_in[4];
    const float* ne_w2 = (const float*)d_in[5];
    const float* ne_b2 = (const float*)d_in[6];
    const float* ne_g  = (const float*)d_in[7];
    const float* ne_be = (const float*)d_in[8];
    const float* ee_w1 = (const float*)d_in[9];
    const float* ee_b1 = (const float*)d_in[10];
    const float* ee_w2 = (const float*)d_in[11];
    const float* ee_b2 = (const float*)d_in[12];
    const float* ee_g  = (const float*)d_in[13];
    const float* ee_be = (const float*)d_in[14];
    const float* em_w1 = (const float*)d_in[15];
    const float* em_b1 = (const float*)d_in[16];
    const float* em_w2 = (const float*)d_in[17];
    const float* em_b2 = (const float*)d_in[18];
    const float* em_g  = (const float*)d_in[19];
    const float* em_be = (const float*)d_in[20];
    const float* nm_w1 = (const float*)d_in[21];
    const float* nm_b1 = (const float*)d_in[22];
    const float* nm_w2 = (const float*)d_in[23];
    const float* nm_b2 = (const float*)d_in[24];
    const float* nm_g  = (const float*)d_in[25];
    const float* nm_be = (const float*)d_in[26];
    const float* dw1   = (const float*)d_in[27];
    const float* db1   = (const float*)d_in[28];
    const float* dw2   = (const float*)d_in[29];
    const float* db2   = (const float*)d_in[30];

    float* base = nullptr;
    cudaGetSymbolAddress((void**)&base, g_scratch);
    float* h0  = base;
    float* h1  = h0 + (size_t)NNODES * LAT;
    float* agg = h1 + (size_t)NNODES * LAT;
    float* e0  = agg + (size_t)NNODES * LAT;
    float* e1  = e0 + (size_t)NEDGES * LAT;

    const int SM = (16 * 129 + 16 * 128 + 128 * 129) * (int)sizeof(float);  // 82496
    const int DSM = (128 * 128 + 8 * 128) * (int)sizeof(float);             // 69632
    cudaFuncSetAttribute(fused_mlp<16, 3, 0, false>,
                         cudaFuncAttributeMaxDynamicSharedMemorySize, SM);
    cudaFuncSetAttribute(fused_mlp<16, 4, 0, false>,
                         cudaFuncAttributeMaxDynamicSharedMemorySize, SM);
    cudaFuncSetAttribute(fused_mlp<384, 384, 1, true>,
                         cudaFuncAttributeMaxDynamicSharedMemorySize, SM);
    cudaFuncSetAttribute(fused_mlp<384, 384, 1, false>,
                         cudaFuncAttributeMaxDynamicSharedMemorySize, SM);
    cudaFuncSetAttribute(fused_mlp<256, 256, 2, false>,
                         cudaFuncAttributeMaxDynamicSharedMemorySize, SM);
    cudaFuncSetAttribute(decoder_kernel,
                         cudaFuncAttributeMaxDynamicSharedMemorySize, DSM);

    dim3 blk(256);
    const int ntiles = (NNODES + 127) / 128;  // 391
    const int etiles = NEDGES / 128;          // 3125

    // Encoders
    fused_mlp<16, 3, 0, false><<<ntiles, blk, SM>>>(
        x, nullptr, nullptr, nullptr, nullptr, nullptr,
        ne_w1, ne_b1, ne_w2, ne_b2, ne_g, ne_be,
        nullptr, h0, nullptr, NNODES);
    fused_mlp<16, 4, 0, false><<<etiles, blk, SM>>>(
        ea, nullptr, nullptr, nullptr, nullptr, nullptr,
        ee_w1, ee_b1, ee_w2, ee_b2, ee_g, ee_be,
        nullptr, e0, nullptr, NEDGES);

    float *hc = h0, *hn = h1, *ec = e0, *en = e1;
    for (int s = 0; s < 5; s++) {
        zero_kernel<<<(NNODES * LAT + 1023) / 1024, 1024>>>(agg, NNODES * LAT);
        // messages: ln_mlp(cat(h[dst], h[src], e)) scattered-add into agg[dst]
        fused_mlp<384, 384, 1, true><<<etiles, blk, SM>>>(
            nullptr, hc, hc, ec, dst, src,
            em_w1, em_b1, em_w2, em_b2, em_g, em_be,
            nullptr, agg, dst, NEDGES);
        // edge update: ln_mlp(cat(h[src], h[dst], e)) + e
        fused_mlp<384, 384, 1, false><<<etiles, blk, SM>>>(
            nullptr, hc, hc, ec, src, dst,
            em_w1, em_b1, em_w2, em_b2, em_g, em_be,
            ec, en, nullptr, NEDGES);
        // node update: ln_mlp(cat(agg, h)) + h
        fused_mlp<256, 256, 2, false><<<ntiles, blk, SM>>>(
            nullptr, agg, hc, nullptr, nullptr, nullptr,
            nm_w1, nm_b1, nm_w2, nm_b2, nm_g, nm_be,
            hc, hn, nullptr, NNODES);
        float* t;
        t = hc; hc = hn; hn = t;
        t = ec; ec = en; en = t;
    }

    decoder_kernel<<<(NNODES + 7) / 8, blk, DSM>>>(
        hc, dw1, db1, dw2, db2, (float*)d_out, NNODES);
}

// round 5
// speedup vs baseline: 1.3069x; 1.3069x over previous
#include <cuda_runtime.h>
#include <cuda_bf16.h>
#include <cstdint>
#include <cstddef>

#define LAT 128
#define NNODES 50000
#define NEDGES 400000
#define EPSV 1e-5f

__device__ float g_scratch[(size_t)(3 * NNODES + 2 * NEDGES) * LAT];
__device__ __align__(16) __nv_bfloat16 g_planes[294912];

__device__ __forceinline__ uint32_t smem_u32(const void* p) {
    uint32_t a;
    asm("{ .reg .u64 t; cvta.to.shared.u64 t, %1; cvt.u32.u64 %0, t; }" : "=r"(a) : "l"(p));
    return a;
}
__device__ __forceinline__ void ldsm4(uint32_t addr, uint32_t* r) {
    asm volatile("ldmatrix.sync.aligned.m8n8.x4.shared.b16 {%0,%1,%2,%3}, [%4];"
                 : "=r"(r[0]), "=r"(r[1]), "=r"(r[2]), "=r"(r[3]) : "r"(addr));
}
__device__ __forceinline__ void mma_bf16(float* d, const uint32_t* a, const uint32_t* b) {
    asm volatile("mma.sync.aligned.m16n8k16.row.col.f32.bf16.bf16.f32 "
                 "{%0,%1,%2,%3}, {%4,%5,%6,%7}, {%8,%9}, {%0,%1,%2,%3};"
                 : "+f"(d[0]), "+f"(d[1]), "+f"(d[2]), "+f"(d[3])
                 : "r"(a[0]), "r"(a[1]), "r"(a[2]), "r"(a[3]), "r"(b[0]), "r"(b[1]));
}
__device__ __forceinline__ uint32_t swz(uint32_t bo) { return bo ^ ((bo >> 3) & 0x70); }
__device__ __forceinline__ void split_pair(float a, float b, uint32_t& hi, uint32_t& lo) {
    __nv_bfloat16 ah = __float2bfloat16(a), bh = __float2bfloat16(b);
    __nv_bfloat162 hp; hp.x = ah; hp.y = bh;
    __nv_bfloat162 lp;
    lp.x = __float2bfloat16(a - __bfloat162float(ah));
    lp.y = __float2bfloat16(b - __bfloat162float(bh));
    hi = *reinterpret_cast<uint32_t*>(&hp);
    lo = *reinterpret_cast<uint32_t*>(&lp);
}

// SMEM layout (byte offsets from 1KB-aligned base)
#define OFF_CA_HI 0
#define OFF_CA_LO 16384
#define OFF_CW_HI 32768
#define OFF_CW_LO 49152
#define OFF_H     65536      /* [2 chunks][hi 16K | lo 16K] = 64KB */
#define OFF_IDX   131072
#define OFF_B1    132096
#define OFF_B2    132608
#define OFF_G     133120
#define OFF_BE    133632
#define OFF_LN    134144     /* 2KB: sums[256], vars[256] */
#define OFF_W1RAW 136192     /* 2KB */
#define SMEM_DYN  (138240 + 1024)

// gather/concat -> Lin(K,128)+ReLU -> Lin(128,128)+ReLU -> LN [+res] -> store|scatter
// GMODE 0: raw fp32 (encoder, SIMT layer1). 1: [hA[idxA]|hB[idxB]|eIn] K=384. 2: [hA|hB] K=256.
template <int KTOT, int GMODE, bool ATOMIC>
__global__ __launch_bounds__(256, 1) void gnn_mma(
    const float* __restrict__ raw, const float* __restrict__ W1raw, int kreal,
    const float* __restrict__ hA, const float* __restrict__ hB,
    const float* __restrict__ eIn,
    const int* __restrict__ idxA, const int* __restrict__ idxB,
    const __nv_bfloat16* __restrict__ W1hi, const __nv_bfloat16* __restrict__ W1lo,
    const float* __restrict__ B1,
    const __nv_bfloat16* __restrict__ W2hi, const __nv_bfloat16* __restrict__ W2lo,
    const float* __restrict__ B2,
    const float* __restrict__ G, const float* __restrict__ BE,
    const float* __restrict__ res, float* __restrict__ outp,
    const int* __restrict__ scatIdx, int nRows)
{
    extern __shared__ char smraw[];
    char* smp = (char*)((((uintptr_t)smraw) + 1023) & ~(uintptr_t)1023);
    const uint32_t sb = smem_u32(smp);

    const int tid = threadIdx.x;
    const int wid = tid >> 5, lane = tid & 31;
    const int mwarp = wid & 3, nwarp = wid >> 2;
    const int blockRow = blockIdx.x * 128;

    int* idxs = (int*)(smp + OFF_IDX);
    float* b1s = (float*)(smp + OFF_B1);
    float* b2s = (float*)(smp + OFF_B2);
    float* Gs  = (float*)(smp + OFF_G);
    float* BEs = (float*)(smp + OFF_BE);
    float* lnb = (float*)(smp + OFF_LN);
    float* w1r = (float*)(smp + OFF_W1RAW);

    if constexpr (GMODE == 1) {
        if (tid < 128) idxs[tid] = idxA[min(blockRow + tid, nRows - 1)];
        else idxs[tid] = idxB[min(blockRow + tid - 128, nRows - 1)];
    }
    if (tid < 128) {
        b1s[tid] = B1[tid]; b2s[tid] = B2[tid];
        Gs[tid] = G[tid];   BEs[tid] = BE[tid];
    }
    if constexpr (GMODE == 0) {
        for (int i = tid; i < kreal * 128; i += 256) w1r[i] = W1raw[i];
    }
    __syncthreads();

    // per-lane ldmatrix addressing
    const int lrow = lane & 7, lg = lane >> 3;
    const uint32_t xm = (uint32_t)lrow << 4;            // SW128 XOR mask (row&7)<<4
    const int a_row0 = mwarp * 32 + lrow + 8 * (lg & 1);
    const int a_kx = lg >> 1;
    const int b_row0 = nwarp * 64 + lrow + 8 * (lg >> 1);
    const int b_kx = lg & 1;

    float c[2][8][4];
#pragma unroll
    for (int mt = 0; mt < 2; mt++)
#pragma unroll
        for (int i = 0; i < 8; i++)
#pragma unroll
            for (int j = 0; j < 4; j++) c[mt][i][j] = 0.f;

    if constexpr (KTOT > 16) {
        constexpr int NC = KTOT / 64;
        for (int ch = 0; ch < NC; ch++) {
            // ---- fill gathered A chunk (fp32 -> bf16 hi/lo, SW128) ----
            {
                const int sel = ch >> 1;
                const float* bp;
                if constexpr (GMODE == 1) bp = (sel == 0) ? hA : (sel == 1 ? hB : eIn);
                else                      bp = (sel == 0) ? hA : hB;
                const int koff = (ch & 1) * 64;
#pragma unroll
                for (int p = 0; p < 8; p++) {
                    int idx = tid + 256 * p;
                    int row = idx >> 4, f4 = idx & 15;
                    int gr = blockRow + row;
                    int ri;
                    if constexpr (GMODE == 1) ri = (sel == 2) ? min(gr, nRows - 1)
                                                             : idxs[sel * 128 + row];
                    else                      ri = min(gr, nRows - 1);
                    float4 v = *(const float4*)&bp[(size_t)ri * LAT + koff + f4 * 4];
                    uint32_t h0, h1, l0, l1;
                    split_pair(v.x, v.y, h0, l0);
                    split_pair(v.z, v.w, h1, l1);
                    uint32_t sw = swz((uint32_t)(row * 128 + f4 * 8));
                    *(uint2*)(smp + OFF_CA_HI + sw) = make_uint2(h0, h1);
                    *(uint2*)(smp + OFF_CA_LO + sw) = make_uint2(l0, l1);
                }
            }
            // ---- fill W1 chunk from pre-split [n][KTOT] planes ----
            {
#pragma unroll
                for (int p = 0; p < 4; p++) {
                    int idx = tid + 256 * p;
                    int row = idx >> 3, q = idx & 7;
                    const size_t go = (size_t)row * KTOT + ch * 64 + q * 8;
                    uint4 vh = *(const uint4*)(W1hi + go);
                    uint4 vl = *(const uint4*)(W1lo + go);
                    uint32_t sw = swz((uint32_t)(row * 128 + q * 16));
                    *(uint4*)(smp + OFF_CW_HI + sw) = vh;
                    *(uint4*)(smp + OFF_CW_LO + sw) = vl;
                }
            }
            __syncthreads();
            // ---- 4 ksteps of m16n8k16, 3 split passes ----
#pragma unroll
            for (int ks = 0; ks < 4; ks++) {
                const uint32_t kcA = (uint32_t)((ks * 2 + a_kx) * 16) ^ xm;
                const uint32_t kcB = (uint32_t)((ks * 2 + b_kx) * 16) ^ xm;
                uint32_t ah[2][4], al[2][4];
#pragma unroll
                for (int mt = 0; mt < 2; mt++) {
                    uint32_t ro = (uint32_t)((a_row0 + mt * 16) * 128);
                    ldsm4(sb + OFF_CA_HI + ro + kcA, ah[mt]);
                    ldsm4(sb + OFF_CA_LO + ro + kcA, al[mt]);
                }
                uint32_t bh[4][4], bl[4][4];
#pragma unroll
                for (int g = 0; g < 4; g++) {
                    uint32_t ro = (uint32_t)((b_row0 + g * 16) * 128);
                    ldsm4(sb + OFF_CW_HI + ro + kcB, bh[g]);
                    ldsm4(sb + OFF_CW_LO + ro + kcB, bl[g]);
                }
#pragma unroll
                for (int mt = 0; mt < 2; mt++)
#pragma unroll
                    for (int g = 0; g < 4; g++)
#pragma unroll
                        for (int hf = 0; hf < 2; hf++) {
                            float* cc = c[mt][g * 2 + hf];
                            mma_bf16(cc, ah[mt], &bh[g][hf * 2]);
                            mma_bf16(cc, ah[mt], &bl[g][hf * 2]);
                            mma_bf16(cc, al[mt], &bh[g][hf * 2]);
                        }
            }
            __syncthreads();
        }
        // ---- hidden = relu(C + b1) -> bf16 hi/lo -> H smem ----
#pragma unroll
        for (int mt = 0; mt < 2; mt++)
#pragma unroll
            for (int idx = 0; idx < 8; idx++)
#pragma unroll
                for (int e = 0; e < 2; e++) {
                    int row = mwarp * 32 + mt * 16 + (lane >> 2) + 8 * e;
                    int col = nwarp * 64 + (idx >> 1) * 16 + (idx & 1) * 8 + 2 * (lane & 3);
                    float v0 = fmaxf(c[mt][idx][2 * e] + b1s[col], 0.f);
                    float v1 = fmaxf(c[mt][idx][2 * e + 1] + b1s[col + 1], 0.f);
                    uint32_t hi, lo;
                    split_pair(v0, v1, hi, lo);
                    uint32_t off = (uint32_t)(OFF_H + nwarp * 32768 + row * 128 +
                                              (((col & 63) * 2) ^ (((row & 7)) << 4)));
                    *(uint32_t*)(smp + off) = hi;
                    *(uint32_t*)(smp + off + 16384) = lo;
                }
#pragma unroll
        for (int mt = 0; mt < 2; mt++)
#pragma unroll
            for (int i = 0; i < 8; i++)
#pragma unroll
                for (int j = 0; j < 4; j++) c[mt][i][j] = 0.f;
        __syncthreads();
    } else {
        // encoder: SIMT layer1 (kreal <= 4)
        const int r = mwarp * 32 + lane;
        const int cb = nwarp * 64;
        int grc = min(blockRow + r, nRows - 1);
        float xv[4];
#pragma unroll
        for (int k = 0; k < 4; k++)
            xv[k] = (k < kreal) ? raw[(size_t)grc * kreal + k] : 0.f;
#pragma unroll 4
        for (int i = 0; i < 64; i += 2) {
            float v[2];
#pragma unroll
            for (int j = 0; j < 2; j++) {
                float acc = b1s[cb + i + j];
                for (int k = 0; k < kreal; k++)
                    acc = fmaf(xv[k], w1r[k * 128 + cb + i + j], acc);
                v[j] = fmaxf(acc, 0.f);
            }
            uint32_t hi, lo;
            split_pair(v[0], v[1], hi, lo);
            uint32_t off = (uint32_t)(OFF_H + nwarp * 32768 + r * 128 +
                                      ((i * 2) ^ ((lane & 7) << 4)));
            *(uint32_t*)(smp + off) = hi;
            *(uint32_t*)(smp + off + 16384) = lo;
        }
        __syncthreads();
    }

    // ---- layer 2: K=128 in 2 chunks; A from H, W2 chunk into CW ----
    for (int c2 = 0; c2 < 2; c2++) {
        {
#pragma unroll
            for (int p = 0; p < 4; p++) {
                int idx = tid + 256 * p;
                int row = idx >> 3, q = idx & 7;
                const size_t go = (size_t)row * 128 + c2 * 64 + q * 8;
                uint4 vh = *(const uint4*)(W2hi + go);
                uint4 vl = *(const uint4*)(W2lo + go);
                uint32_t sw = swz((uint32_t)(row * 128 + q * 16));
                *(uint4*)(smp + OFF_CW_HI + sw) = vh;
                *(uint4*)(smp + OFF_CW_LO + sw) = vl;
            }
        }
        __syncthreads();
        const uint32_t ab = sb + OFF_H + c2 * 32768;
#pragma unroll
        for (int ks = 0; ks < 4; ks++) {
            const uint32_t kcA = (uint32_t)((ks * 2 + a_kx) * 16) ^ xm;
            const uint32_t kcB = (uint32_t)((ks * 2 + b_kx) * 16) ^ xm;
            uint32_t ah[2][4], al[2][4];
#pragma unroll
            for (int mt = 0; mt < 2; mt++) {
                uint32_t ro = (uint32_t)((a_row0 + mt * 16) * 128);
                ldsm4(ab + ro + kcA, ah[mt]);
                ldsm4(ab + 16384 + ro + kcA, al[mt]);
            }
            uint32_t bh[4][4], bl[4][4];
#pragma unroll
            for (int g = 0; g < 4; g++) {
                uint32_t ro = (uint32_t)((b_row0 + g * 16) * 128);
                ldsm4(sb + OFF_CW_HI + ro + kcB, bh[g]);
                ldsm4(sb + OFF_CW_LO + ro + kcB, bl[g]);
            }
#pragma unroll
            for (int mt = 0; mt < 2; mt++)
#pragma unroll
                for (int g = 0; g < 4; g++)
#pragma unroll
                    for (int hf = 0; hf < 2; hf++) {
                        float* cc = c[mt][g * 2 + hf];
                        mma_bf16(cc, ah[mt], &bh[g][hf * 2]);
                        mma_bf16(cc, ah[mt], &bl[g][hf * 2]);
                        mma_bf16(cc, al[mt], &bh[g][hf * 2]);
                    }
        }
        __syncthreads();
    }

    // ---- bias2 + ReLU in regs ----
#pragma unroll
    for (int mt = 0; mt < 2; mt++)
#pragma unroll
        for (int idx = 0; idx < 8; idx++) {
            int col = nwarp * 64 + (idx >> 1) * 16 + (idx & 1) * 8 + 2 * (lane & 3);
#pragma unroll
            for (int j = 0; j < 4; j++)
                c[mt][idx][j] = fmaxf(c[mt][idx][j] + b2s[col + (j & 1)], 0.f);
        }

    // ---- LayerNorm: row sums via shfl + smem combine of the 2 n-warps ----
#pragma unroll
    for (int mt = 0; mt < 2; mt++)
#pragma unroll
        for (int e = 0; e < 2; e++) {
            float s = 0.f;
#pragma unroll
            for (int idx = 0; idx < 8; idx++)
                s += c[mt][idx][2 * e] + c[mt][idx][2 * e + 1];
            s += __shfl_xor_sync(0xffffffffu, s, 1);
            s += __shfl_xor_sync(0xffffffffu, s, 2);
            if ((lane & 3) == 0) {
                int row = mwarp * 32 + mt * 16 + (lane >> 2) + 8 * e;
                lnb[row * 2 + nwarp] = s;
            }
        }
    __syncthreads();
    float mu[2][2], rs[2][2];
#pragma unroll
    for (int mt = 0; mt < 2; mt++)
#pragma unroll
        for (int e = 0; e < 2; e++) {
            int row = mwarp * 32 + mt * 16 + (lane >> 2) + 8 * e;
            mu[mt][e] = (lnb[row * 2] + lnb[row * 2 + 1]) * (1.0f / 128.0f);
            float sq = 0.f;
#pragma unroll
            for (int idx = 0; idx < 8; idx++) {
                float d0 = c[mt][idx][2 * e] - mu[mt][e];
                float d1 = c[mt][idx][2 * e + 1] - mu[mt][e];
                sq = fmaf(d0, d0, sq);
                sq = fmaf(d1, d1, sq);
            }
            sq += __shfl_xor_sync(0xffffffffu, sq, 1);
            sq += __shfl_xor_sync(0xffffffffu, sq, 2);
            if ((lane & 3) == 0) lnb[256 + row * 2 + nwarp] = sq;
        }
    __syncthreads();
#pragma unroll
    for (int mt = 0; mt < 2; mt++)
#pragma unroll
        for (int e = 0; e < 2; e++) {
            int row = mwarp * 32 + mt * 16 + (lane >> 2) + 8 * e;
            rs[mt][e] = rsqrtf((lnb[256 + row * 2] + lnb[256 + row * 2 + 1]) *
                                   (1.0f / 128.0f) + EPSV);
        }

    // ---- output: normalize (+res | atomic scatter) ----
#pragma unroll
    for (int mt = 0; mt < 2; mt++)
#pragma unroll
        for (int e = 0; e < 2; e++) {
            int row = mwarp * 32 + mt * 16 + (lane >> 2) + 8 * e;
            int gr = blockRow + row;
            if (gr >= nRows) continue;
            float m = mu[mt][e], q = rs[mt][e];
            if constexpr (ATOMIC) {
                const int drow = scatIdx[gr];
                float* op = outp + (size_t)drow * LAT;
#pragma unroll
                for (int idx = 0; idx < 8; idx++) {
                    int col = nwarp * 64 + (idx >> 1) * 16 + (idx & 1) * 8 + 2 * (lane & 3);
                    atomicAdd(&op[col],     (c[mt][idx][2 * e]     - m) * q * Gs[col]     + BEs[col]);
                    atomicAdd(&op[col + 1], (c[mt][idx][2 * e + 1] - m) * q * Gs[col + 1] + BEs[col + 1]);
                }
            } else {
                float* op = outp + (size_t)gr * LAT;
#pragma unroll
                for (int idx = 0; idx < 8; idx++) {
                    int col = nwarp * 64 + (idx >> 1) * 16 + (idx & 1) * 8 + 2 * (lane & 3);
                    float2 o;
                    o.x = (c[mt][idx][2 * e]     - m) * q * Gs[col]     + BEs[col];
                    o.y = (c[mt][idx][2 * e + 1] - m) * q * Gs[col + 1] + BEs[col + 1];
                    if (res) {
                        float2 rv = *(const float2*)&res[(size_t)gr * LAT + col];
                        o.x += rv.x; o.y += rv.y;
                    }
                    *(float2*)&op[col] = o;
                }
            }
        }
}

// weight prep: transpose [K,128] -> [128,K] + bf16 hi/lo split
__global__ void prep_split(const float* __restrict__ W,
                           __nv_bfloat16* __restrict__ hi,
                           __nv_bfloat16* __restrict__ lo, int K)
{
    int i = blockIdx.x * blockDim.x + threadIdx.x;
    if (i >= K * 128) return;
    int k = i >> 7, n = i & 127;
    float v = W[i];
    __nv_bfloat16 h = __float2bfloat16(v);
    hi[(size_t)n * K + k] = h;
    lo[(size_t)n * K + k] = __float2bfloat16(v - __bfloat162float(h));
}

__global__ __launch_bounds__(256) void decoder_kernel(
    const float* __restrict__ h,
    const float* __restrict__ W1, const float* __restrict__ B1,
    const float* __restrict__ W2, const float* __restrict__ B2,
    float* __restrict__ out, int n)
{
    extern __shared__ float s[];
    float* W1s = s;
    float* hs = s + 128 * 128;
    int tid = threadIdx.x;
#pragma unroll
    for (int it = 0; it < 16; it++) {
        int f = tid + 256 * it;
        *(float4*)&W1s[f * 4] = *(const float4*)&W1[f * 4];
    }
    int warp = tid >> 5, lane = tid & 31;
    int row = blockIdx.x * 8 + warp;
#pragma unroll
    for (int q = 0; q < 4; q++)
        hs[warp * 128 + lane + 32 * q] =
            (row < n) ? h[(size_t)row * LAT + lane + 32 * q] : 0.f;
    __syncthreads();

    float acc[4];
#pragma unroll
    for (int q = 0; q < 4; q++) acc[q] = B1[lane + 32 * q];
    for (int k = 0; k < 128; k++) {
        float hv = hs[warp * 128 + k];
#pragma unroll
        for (int q = 0; q < 4; q++)
            acc[q] = fmaf(hv, W1s[k * 128 + lane + 32 * q], acc[q]);
    }
#pragma unroll
    for (int q = 0; q < 4; q++) acc[q] = fmaxf(acc[q], 0.f);

    float o[3];
#pragma unroll
    for (int oo = 0; oo < 3; oo++) {
        float p = 0.f;
#pragma unroll
        for (int q = 0; q < 4; q++)
            p = fmaf(acc[q], W2[(size_t)(lane + 32 * q) * 3 + oo], p);
#pragma unroll
        for (int off = 16; off > 0; off >>= 1)
            p += __shfl_xor_sync(0xffffffffu, p, off);
        o[oo] = p;
    }
    if (lane == 0 && row < n) {
        out[(size_t)row * 3 + 0] = o[0] + B2[0];
        out[(size_t)row * 3 + 1] = o[1] + B2[1];
        out[(size_t)row * 3 + 2] = o[2] + B2[2];
    }
}

__global__ void zero_kernel(float* __restrict__ p, int n)
{
    int i = blockIdx.x * blockDim.x + threadIdx.x;
    if (i < n) p[i] = 0.f;
}

extern "C" void kernel_launch(void* const* d_in, const int* in_sizes, int n_in,
                              void* d_out, int out_size)
{
    (void)in_sizes; (void)n_in; (void)out_size;
    const float* x  = (const float*)d_in[0];
    const float* ea = (const float*)d_in[1];
    const int*   ei = (const int*)d_in[2];
    const int* src = ei;
    const int* dst = ei + NEDGES;

    const float* ne_w1 = (const float*)d_in[3];
    const float* ne_b1 = (const float*)d_in[4];
    const float* ne_w2 = (const float*)d_in[5];
    const float* ne_b2 = (const float*)d_in[6];
    const float* ne_g  = (const float*)d_in[7];
    const float* ne_be = (const float*)d_in[8];
    const float* ee_w1 = (const float*)d_in[9];
    const float* ee_b1 = (const float*)d_in[10];
    const float* ee_w2 = (const float*)d_in[11];
    const float* ee_b2 = (const float*)d_in[12];
    const float* ee_g  = (const float*)d_in[13];
    const float* ee_be = (const float*)d_in[14];
    const float* em_w1 = (const float*)d_in[15];
    const float* em_b1 = (const float*)d_in[16];
    const float* em_w2 = (const float*)d_in[17];
    const float* em_b2 = (const float*)d_in[18];
    const float* em_g  = (const float*)d_in[19];
    const float* em_be = (const float*)d_in[20];
    const float* nm_w1 = (const float*)d_in[21];
    const float* nm_b1 = (const float*)d_in[22];
    const float* nm_w2 = (const float*)d_in[23];
    const float* nm_b2 = (const float*)d_in[24];
    const float* nm_g  = (const float*)d_in[25];
    const float* nm_be = (const float*)d_in[26];
    const float* dw1   = (const float*)d_in[27];
    const float* db1   = (const float*)d_in[28];
    const float* dw2   = (const float*)d_in[29];
    const float* db2   = (const float*)d_in[30];

    float* base = nullptr;
    cudaGetSymbolAddress((void**)&base, g_scratch);
    float* h0  = base;
    float* h1  = h0 + (size_t)NNODES * LAT;
    float* agg = h1 + (size_t)NNODES * LAT;
    float* e0  = agg + (size_t)NNODES * LAT;
    float* e1  = e0 + (size_t)NEDGES * LAT;

    __nv_bfloat16* pl = nullptr;
    cudaGetSymbolAddress((void**)&pl, g_planes);
    __nv_bfloat16* emW1h = pl;
    __nv_bfloat16* emW1l = pl + 49152;
    __nv_bfloat16* emW2h = pl + 98304;
    __nv_bfloat16* emW2l = pl + 114688;
    __nv_bfloat16* nmW1h = pl + 131072;
    __nv_bfloat16* nmW1l = pl + 163840;
    __nv_bfloat16* nmW2h = pl + 196608;
    __nv_bfloat16* nmW2l = pl + 212992;
    __nv_bfloat16* neW2h = pl + 229376;
    __nv_bfloat16* neW2l = pl + 245760;
    __nv_bfloat16* eeW2h = pl + 262144;
    __nv_bfloat16* eeW2l = pl + 278528;

    cudaFuncSetAttribute(gnn_mma<16, 0, false>,
                         cudaFuncAttributeMaxDynamicSharedMemorySize, SMEM_DYN);
    cudaFuncSetAttribute(gnn_mma<384, 1, true>,
                         cudaFuncAttributeMaxDynamicSharedMemorySize, SMEM_DYN);
    cudaFuncSetAttribute(gnn_mma<384, 1, false>,
                         cudaFuncAttributeMaxDynamicSharedMemorySize, SMEM_DYN);
    cudaFuncSetAttribute(gnn_mma<256, 2, false>,
                         cudaFuncAttributeMaxDynamicSharedMemorySize, SMEM_DYN);
    const int DSM = (128 * 128 + 8 * 128) * (int)sizeof(float);
    cudaFuncSetAttribute(decoder_kernel,
                         cudaFuncAttributeMaxDynamicSharedMemorySize, DSM);

    // weight prep
    prep_split<<<(384 * 128 + 255) / 256, 256>>>(em_w1, emW1h, emW1l, 384);
    prep_split<<<(128 * 128 + 255) / 256, 256>>>(em_w2, emW2h, emW2l, 128);
    prep_split<<<(256 * 128 + 255) / 256, 256>>>(nm_w1, nmW1h, nmW1l, 256);
    prep_split<<<(128 * 128 + 255) / 256, 256>>>(nm_w2, nmW2h, nmW2l, 128);
    prep_split<<<(128 * 128 + 255) / 256, 256>>>(ne_w2, neW2h, neW2l, 128);
    prep_split<<<(128 * 128 + 255) / 256, 256>>>(ee_w2, eeW2h, eeW2l, 128);

    dim3 blk(256);
    const int ntiles = (NNODES + 127) / 128;  // 391
    const int etiles = NEDGES / 128;          // 3125

    // Encoders
    gnn_mma<16, 0, false><<<ntiles, blk, SMEM_DYN>>>(
        x, ne_w1, 3, nullptr, nullptr, nullptr, nullptr, nullptr,
        nullptr, nullptr, ne_b1, neW2h, neW2l, ne_b2, ne_g, ne_be,
        nullptr, h0, nullptr, NNODES);
    gnn_mma<16, 0, false><<<etiles, blk, SMEM_DYN>>>(
        ea, ee_w1, 4, nullptr, nullptr, nullptr, nullptr, nullptr,
        nullptr, nullptr, ee_b1, eeW2h, eeW2l, ee_b2, ee_g, ee_be,
        nullptr, e0, nullptr, NEDGES);

    float *hc = h0, *hn = h1, *ec = e0, *en = e1;
    for (int s = 0; s < 5; s++) {
        zero_kernel<<<(NNODES * LAT + 1023) / 1024, 1024>>>(agg, NNODES * LAT);
        // messages: ln_mlp(cat(h[dst], h[src], e)) scatter-add into agg[dst]
        gnn_mma<384, 1, true><<<etiles, blk, SMEM_DYN>>>(
            nullptr, nullptr, 0, hc, hc, ec, dst, src,
            emW1h, emW1l, em_b1, emW2h, emW2l, em_b2, em_g, em_be,
            nullptr, agg, dst, NEDGES);
        // edge update: ln_mlp(cat(h[src], h[dst], e)) + e
        gnn_mma<384, 1, false><<<etiles, blk, SMEM_DYN>>>(
            nullptr, nullptr, 0, hc, hc, ec, src, dst,
            emW1h, emW1l, em_b1, emW2h, emW2l, em_b2, em_g, em_be,
            ec, en, nullptr, NEDGES);
        // node update: ln_mlp(cat(agg, h)) + h
        gnn_mma<256, 2, false><<<ntiles, blk, SMEM_DYN>>>(
            nullptr, nullptr, 0, agg, hc, nullptr, nullptr, nullptr,
            nmW1h, nmW1l, nm_b1, nmW2h, nmW2l, nm_b2, nm_g, nm_be,
            hc, hn, nullptr, NNODES);
        float* t;
        t = hc; hc = hn; hn = t;
        t = ec; ec = en; en = t;
    }

    decoder_kernel<<<(NNODES + 7) / 8, blk, DSM>>>(
        hc, dw1, db1, dw2, db2, (float*)d_out, NNODES);
}

// round 6
// speedup vs baseline: 2.3424x; 1.7923x over previous
#include <cuda_runtime.h>
#include <cuda_bf16.h>
#include <cstdint>
#include <cstddef>

#define LAT 128
#define NNODES 50000
#define NEDGES 400000
#define EPSV 1e-5f

// fp32 aggregation buffer (atomics) + bf16 hi/lo planes for h and e (ping-pong)
__device__ float g_agg[(size_t)NNODES * LAT];
__device__ __align__(16) __nv_bfloat16 g_hpl[(size_t)4 * NNODES * LAT];
__device__ __align__(16) __nv_bfloat16 g_epl[(size_t)4 * NEDGES * LAT];
__device__ __align__(16) __nv_bfloat16 g_planes[294912];  // weight hi/lo planes

__device__ __forceinline__ uint32_t smem_u32(const void* p) {
    uint32_t a;
    asm("{ .reg .u64 t; cvta.to.shared.u64 t, %1; cvt.u32.u64 %0, t; }" : "=r"(a) : "l"(p));
    return a;
}
__device__ __forceinline__ void ldsm4(uint32_t addr, uint32_t* r) {
    asm volatile("ldmatrix.sync.aligned.m8n8.x4.shared.b16 {%0,%1,%2,%3}, [%4];"
                 : "=r"(r[0]), "=r"(r[1]), "=r"(r[2]), "=r"(r[3]) : "r"(addr));
}
__device__ __forceinline__ void mma_bf16(float* d, const uint32_t* a, const uint32_t* b) {
    asm volatile("mma.sync.aligned.m16n8k16.row.col.f32.bf16.bf16.f32 "
                 "{%0,%1,%2,%3}, {%4,%5,%6,%7}, {%8,%9}, {%0,%1,%2,%3};"
                 : "+f"(d[0]), "+f"(d[1]), "+f"(d[2]), "+f"(d[3])
                 : "r"(a[0]), "r"(a[1]), "r"(a[2]), "r"(a[3]), "r"(b[0]), "r"(b[1]));
}
__device__ __forceinline__ uint32_t swz(uint32_t bo) { return bo ^ ((bo >> 3) & 0x70); }
__device__ __forceinline__ void split_pair(float a, float b, uint32_t& hi, uint32_t& lo) {
    __nv_bfloat16 ah = __float2bfloat16(a), bh = __float2bfloat16(b);
    __nv_bfloat162 hp; hp.x = ah; hp.y = bh;
    __nv_bfloat162 lp;
    lp.x = __float2bfloat16(a - __bfloat162float(ah));
    lp.y = __float2bfloat16(b - __bfloat162float(bh));
    hi = *reinterpret_cast<uint32_t*>(&hp);
    lo = *reinterpret_cast<uint32_t*>(&lp);
}
__device__ __forceinline__ float recon(uint32_t packed, int half) {
    __nv_bfloat162 v = *reinterpret_cast<__nv_bfloat162*>(&packed);
    return half ? __bfloat162float(v.y) : __bfloat162float(v.x);
}

// SMEM layout (byte offsets; regions overlap across phases — see sync notes)
#define OFF_CA_HI 0          /* layer1 A chunk hi (16K) */
#define OFF_CA_LO 16384
#define OFF_CW_HI 32768      /* layer1 W chunk hi (16K) */
#define OFF_CW_LO 49152
#define OFF_W2_HI 0          /* layer2 W chunk (reuses CA region after sync) */
#define OFF_W2_LO 16384
#define OFF_H_HI  32768      /* hidden hi, 2 k-chunks x 16K (reuses CW region after sync) */
#define OFF_H_LO  65536
#define OFF_IDX   98304
#define OFF_B1    99328
#define OFF_B2    99840
#define OFF_G     100352
#define OFF_BE    100864
#define OFF_LN    101376
#define OFF_W1RAW 103424
#define SMEM_DYN  106496

// gather/concat -> Lin(K,128)+ReLU -> Lin(128,128)+ReLU -> LN [+res] -> planes|scatter
// GMODE 0: raw fp32 (encoder, SIMT layer1). 1: [h[idxA]|h[idxB]|e] K=384. 2: [aggF|h] K=256.
template <int KTOT, int GMODE, bool ATOMIC>
__global__ __launch_bounds__(256, 2) void gnn_mma(
    const float* __restrict__ raw, const float* __restrict__ W1raw, int kreal,
    const float* __restrict__ aggF,
    const __nv_bfloat16* __restrict__ hHi, const __nv_bfloat16* __restrict__ hLo,
    const __nv_bfloat16* __restrict__ eHi, const __nv_bfloat16* __restrict__ eLo,
    const int* __restrict__ idxA, const int* __restrict__ idxB,
    const __nv_bfloat16* __restrict__ W1hi, const __nv_bfloat16* __restrict__ W1lo,
    const float* __restrict__ B1,
    const __nv_bfloat16* __restrict__ W2hi, const __nv_bfloat16* __restrict__ W2lo,
    const float* __restrict__ B2,
    const float* __restrict__ G, const float* __restrict__ BE,
    const __nv_bfloat16* __restrict__ resHi, const __nv_bfloat16* __restrict__ resLo,
    __nv_bfloat16* __restrict__ outHi, __nv_bfloat16* __restrict__ outLo,
    float* __restrict__ outF, const int* __restrict__ scatIdx, int nRows)
{
    extern __shared__ char smraw[];
    char* smp = smraw;
    const uint32_t sb = smem_u32(smp);

    const int tid = threadIdx.x;
    const int wid = tid >> 5, lane = tid & 31;
    const int mwarp = wid & 3, nwarp = wid >> 2;
    const int blockRow = blockIdx.x * 128;

    int* idxs = (int*)(smp + OFF_IDX);
    float* b1s = (float*)(smp + OFF_B1);
    float* b2s = (float*)(smp + OFF_B2);
    float* Gs  = (float*)(smp + OFF_G);
    float* BEs = (float*)(smp + OFF_BE);
    float* lnb = (float*)(smp + OFF_LN);
    float* w1r = (float*)(smp + OFF_W1RAW);

    if constexpr (GMODE == 1) {
        if (tid < 128) idxs[tid] = idxA[min(blockRow + tid, nRows - 1)];
        else idxs[tid] = idxB[min(blockRow + tid - 128, nRows - 1)];
    }
    if (tid < 128) {
        b1s[tid] = B1[tid]; b2s[tid] = B2[tid];
        Gs[tid] = G[tid];   BEs[tid] = BE[tid];
    }
    if constexpr (GMODE == 0) {
        for (int i = tid; i < kreal * 128; i += 256) w1r[i] = W1raw[i];
    }
    __syncthreads();

    // ldmatrix addressing
    const int lrow = lane & 7, lg = lane >> 3;
    const uint32_t xm = (uint32_t)lrow << 4;
    const int a_row0 = mwarp * 32 + lrow + 8 * (lg & 1);
    const int a_kx = lg >> 1;
    const int b_row0 = nwarp * 64 + lrow + 8 * (lg >> 1);
    const int b_kx = lg & 1;

    float c[2][8][4];
#pragma unroll
    for (int mt = 0; mt < 2; mt++)
#pragma unroll
        for (int i = 0; i < 8; i++)
#pragma unroll
            for (int j = 0; j < 4; j++) c[mt][i][j] = 0.f;

    if constexpr (KTOT > 16) {
        constexpr int NC = KTOT / 64;
        for (int ch = 0; ch < NC; ch++) {
            // ---- A chunk fill ----
            if ((GMODE == 2) && (ch < 2)) {
                // agg fp32 -> split on the fly
                const int koff = ch * 64;
#pragma unroll
                for (int p = 0; p < 8; p++) {
                    int idx = tid + 256 * p;
                    int row = idx >> 4, f4 = idx & 15;
                    int ri = min(blockRow + row, nRows - 1);
                    float4 v = *(const float4*)&aggF[(size_t)ri * LAT + koff + f4 * 4];
                    uint32_t h0, h1, l0, l1;
                    split_pair(v.x, v.y, h0, l0);
                    split_pair(v.z, v.w, h1, l1);
                    uint32_t sw = swz((uint32_t)(row * 128 + f4 * 8));
                    *(uint2*)(smp + OFF_CA_HI + sw) = make_uint2(h0, h1);
                    *(uint2*)(smp + OFF_CA_LO + sw) = make_uint2(l0, l1);
                }
            } else {
                // pre-split planes -> pure copy
                const __nv_bfloat16 *pHi, *pLo;
                int koff, ibase = 0;
                bool useIdx = false;
                if constexpr (GMODE == 1) {
                    int sel = ch >> 1;
                    koff = (ch & 1) * 64;
                    if (sel == 2) { pHi = eHi; pLo = eLo; }
                    else { pHi = hHi; pLo = hLo; useIdx = true; ibase = sel * 128; }
                } else {
                    pHi = hHi; pLo = hLo; koff = (ch - 2) * 64;
                }
#pragma unroll
                for (int p = 0; p < 4; p++) {
                    int idx = tid + 256 * p;
                    int row = idx >> 3, q = idx & 7;
                    int ri = useIdx ? idxs[ibase + row] : min(blockRow + row, nRows - 1);
                    size_t go = (size_t)ri * LAT + koff + q * 8;
                    uint4 vh = *(const uint4*)(pHi + go);
                    uint4 vl = *(const uint4*)(pLo + go);
                    uint32_t sw = swz((uint32_t)(row * 128 + q * 16));
                    *(uint4*)(smp + OFF_CA_HI + sw) = vh;
                    *(uint4*)(smp + OFF_CA_LO + sw) = vl;
                }
            }
            // ---- W1 chunk fill (pre-split [n][KTOT] planes) ----
#pragma unroll
            for (int p = 0; p < 4; p++) {
                int idx = tid + 256 * p;
                int row = idx >> 3, q = idx & 7;
                const size_t go = (size_t)row * KTOT + ch * 64 + q * 8;
                uint4 vh = *(const uint4*)(W1hi + go);
                uint4 vl = *(const uint4*)(W1lo + go);
                uint32_t sw = swz((uint32_t)(row * 128 + q * 16));
                *(uint4*)(smp + OFF_CW_HI + sw) = vh;
                *(uint4*)(smp + OFF_CW_LO + sw) = vl;
            }
            __syncthreads();
            // ---- 4 ksteps ----
#pragma unroll
            for (int ks = 0; ks < 4; ks++) {
                const uint32_t kcA = (uint32_t)((ks * 2 + a_kx) * 16) ^ xm;
                const uint32_t kcB = (uint32_t)((ks * 2 + b_kx) * 16) ^ xm;
                uint32_t ah[2][4], al[2][4];
#pragma unroll
                for (int mt = 0; mt < 2; mt++) {
                    uint32_t ro = (uint32_t)((a_row0 + mt * 16) * 128);
                    ldsm4(sb + OFF_CA_HI + ro + kcA, ah[mt]);
                    ldsm4(sb + OFF_CA_LO + ro + kcA, al[mt]);
                }
#pragma unroll
                for (int g = 0; g < 4; g++) {
                    uint32_t bh[4], bl[4];
                    uint32_t ro = (uint32_t)((b_row0 + g * 16) * 128);
                    ldsm4(sb + OFF_CW_HI + ro + kcB, bh);
                    ldsm4(sb + OFF_CW_LO + ro + kcB, bl);
#pragma unroll
                    for (int mt = 0; mt < 2; mt++)
#pragma unroll
                        for (int hf = 0; hf < 2; hf++) {
                            float* cc = c[mt][g * 2 + hf];
                            mma_bf16(cc, ah[mt], &bh[hf * 2]);
                            mma_bf16(cc, ah[mt], &bl[hf * 2]);
                            mma_bf16(cc, al[mt], &bh[hf * 2]);
                        }
                }
            }
            __syncthreads();
        }
        // ---- hidden = relu(C + b1) -> H smem (hi/lo, per-nwarp k-chunk) ----
#pragma unroll
        for (int mt = 0; mt < 2; mt++)
#pragma unroll
            for (int idx = 0; idx < 8; idx++)
#pragma unroll
                for (int e = 0; e < 2; e++) {
                    int row = mwarp * 32 + mt * 16 + (lane >> 2) + 8 * e;
                    int col = nwarp * 64 + (idx >> 1) * 16 + (idx & 1) * 8 + 2 * (lane & 3);
                    float v0 = fmaxf(c[mt][idx][2 * e] + b1s[col], 0.f);
                    float v1 = fmaxf(c[mt][idx][2 * e + 1] + b1s[col + 1], 0.f);
                    uint32_t hi, lo;
                    split_pair(v0, v1, hi, lo);
                    uint32_t off = (uint32_t)(nwarp * 16384 + row * 128 +
                                              (((col & 63) * 2) ^ ((row & 7) << 4)));
                    *(uint32_t*)(smp + OFF_H_HI + off) = hi;
                    *(uint32_t*)(smp + OFF_H_LO + off) = lo;
                }
#pragma unroll
        for (int mt = 0; mt < 2; mt++)
#pragma unroll
            for (int i = 0; i < 8; i++)
#pragma unroll
                for (int j = 0; j < 4; j++) c[mt][i][j] = 0.f;
    } else {
        // ---- encoder: SIMT layer1 straight into H ----
#pragma unroll
        for (int mt = 0; mt < 2; mt++)
#pragma unroll
            for (int e = 0; e < 2; e++) {
                int row = mwarp * 32 + mt * 16 + (lane >> 2) + 8 * e;
                int grc = min(blockRow + row, nRows - 1);
                float xv[4];
#pragma unroll
                for (int k = 0; k < 4; k++)
                    xv[k] = (k < kreal) ? raw[(size_t)grc * kreal + k] : 0.f;
#pragma unroll
                for (int idx = 0; idx < 8; idx++) {
                    int col = nwarp * 64 + (idx >> 1) * 16 + (idx & 1) * 8 + 2 * (lane & 3);
                    float v0 = b1s[col], v1 = b1s[col + 1];
                    for (int k = 0; k < kreal; k++) {
                        v0 = fmaf(xv[k], w1r[k * 128 + col], v0);
                        v1 = fmaf(xv[k], w1r[k * 128 + col + 1], v1);
                    }
                    v0 = fmaxf(v0, 0.f); v1 = fmaxf(v1, 0.f);
                    uint32_t hi, lo;
                    split_pair(v0, v1, hi, lo);
                    uint32_t off = (uint32_t)(nwarp * 16384 + row * 128 +
                                              (((col & 63) * 2) ^ ((row & 7) << 4)));
                    *(uint32_t*)(smp + OFF_H_HI + off) = hi;
                    *(uint32_t*)(smp + OFF_H_LO + off) = lo;
                }
            }
    }

    // ---- layer 2: K=128 in 2 chunks; A from H, W2 chunk at 0..32K ----
    for (int c2 = 0; c2 < 2; c2++) {
        if (c2 == 1) __syncthreads();
#pragma unroll
        for (int p = 0; p < 4; p++) {
            int idx = tid + 256 * p;
            int row = idx >> 3, q = idx & 7;
            const size_t go = (size_t)row * 128 + c2 * 64 + q * 8;
            uint4 vh = *(const uint4*)(W2hi + go);
            uint4 vl = *(const uint4*)(W2lo + go);
            uint32_t sw = swz((uint32_t)(row * 128 + q * 16));
            *(uint4*)(smp + OFF_W2_HI + sw) = vh;
            *(uint4*)(smp + OFF_W2_LO + sw) = vl;
        }
        __syncthreads();
        const uint32_t abH = sb + OFF_H_HI + c2 * 16384;
        const uint32_t abL = sb + OFF_H_LO + c2 * 16384;
#pragma unroll
        for (int ks = 0; ks < 4; ks++) {
            const uint32_t kcA = (uint32_t)((ks * 2 + a_kx) * 16) ^ xm;
            const uint32_t kcB = (uint32_t)((ks * 2 + b_kx) * 16) ^ xm;
            uint32_t ah[2][4], al[2][4];
#pragma unroll
            for (int mt = 0; mt < 2; mt++) {
                uint32_t ro = (uint32_t)((a_row0 + mt * 16) * 128);
                ldsm4(abH + ro + kcA, ah[mt]);
                ldsm4(abL + ro + kcA, al[mt]);
            }
#pragma unroll
            for (int g = 0; g < 4; g++) {
                uint32_t bh[4], bl[4];
                uint32_t ro = (uint32_t)((b_row0 + g * 16) * 128);
                ldsm4(sb + OFF_W2_HI + ro + kcB, bh);
                ldsm4(sb + OFF_W2_LO + ro + kcB, bl);
#pragma unroll
                for (int mt = 0; mt < 2; mt++)
#pragma unroll
                    for (int hf = 0; hf < 2; hf++) {
                        float* cc = c[mt][g * 2 + hf];
                        mma_bf16(cc, ah[mt], &bh[hf * 2]);
                        mma_bf16(cc, ah[mt], &bl[hf * 2]);
                        mma_bf16(cc, al[mt], &bh[hf * 2]);
                    }
            }
        }
    }

    // ---- bias2 + ReLU ----
#pragma unroll
    for (int mt = 0; mt < 2; mt++)
#pragma unroll
        for (int idx = 0; idx < 8; idx++) {
            int col = nwarp * 64 + (idx >> 1) * 16 + (idx & 1) * 8 + 2 * (lane & 3);
#pragma unroll
            for (int j = 0; j < 4; j++)
                c[mt][idx][j] = fmaxf(c[mt][idx][j] + b2s[col + (j & 1)], 0.f);
        }

    // ---- LayerNorm (shfl quad-reduce + cross-nwarp smem combine) ----
#pragma unroll
    for (int mt = 0; mt < 2; mt++)
#pragma unroll
        for (int e = 0; e < 2; e++) {
            float s = 0.f;
#pragma unroll
            for (int idx = 0; idx < 8; idx++)
                s += c[mt][idx][2 * e] + c[mt][idx][2 * e + 1];
            s += __shfl_xor_sync(0xffffffffu, s, 1);
            s += __shfl_xor_sync(0xffffffffu, s, 2);
            if ((lane & 3) == 0) {
                int row = mwarp * 32 + mt * 16 + (lane >> 2) + 8 * e;
                lnb[row * 2 + nwarp] = s;
            }
        }
    __syncthreads();
    float mu[2][2], rs[2][2];
#pragma unroll
    for (int mt = 0; mt < 2; mt++)
#pragma unroll
        for (int e = 0; e < 2; e++) {
            int row = mwarp * 32 + mt * 16 + (lane >> 2) + 8 * e;
            mu[mt][e] = (lnb[row * 2] + lnb[row * 2 + 1]) * (1.0f / 128.0f);
            float sq = 0.f;
#pragma unroll
            for (int idx = 0; idx < 8; idx++) {
                float d0 = c[mt][idx][2 * e] - mu[mt][e];
                float d1 = c[mt][idx][2 * e + 1] - mu[mt][e];
                sq = fmaf(d0, d0, sq);
                sq = fmaf(d1, d1, sq);
            }
            sq += __shfl_xor_sync(0xffffffffu, sq, 1);
            sq += __shfl_xor_sync(0xffffffffu, sq, 2);
            if ((lane & 3) == 0) lnb[256 + row * 2 + nwarp] = sq;
        }
    __syncthreads();
#pragma unroll
    for (int mt = 0; mt < 2; mt++)
#pragma unroll
        for (int e = 0; e < 2; e++) {
            int row = mwarp * 32 + mt * 16 + (lane >> 2) + 8 * e;
            rs[mt][e] = rsqrtf((lnb[256 + row * 2] + lnb[256 + row * 2 + 1]) *
                                   (1.0f / 128.0f) + EPSV);
        }

    // ---- output ----
#pragma unroll
    for (int mt = 0; mt < 2; mt++)
#pragma unroll
        for (int e = 0; e < 2; e++) {
            int row = mwarp * 32 + mt * 16 + (lane >> 2) + 8 * e;
            int gr = blockRow + row;
            if (gr >= nRows) continue;
            float m = mu[mt][e], q = rs[mt][e];
            if constexpr (ATOMIC) {
                const int drow = scatIdx[gr];
                float* op = outF + (size_t)drow * LAT;
#pragma unroll
                for (int idx = 0; idx < 8; idx++) {
                    int col = nwarp * 64 + (idx >> 1) * 16 + (idx & 1) * 8 + 2 * (lane & 3);
                    atomicAdd(&op[col],     (c[mt][idx][2 * e]     - m) * q * Gs[col]     + BEs[col]);
                    atomicAdd(&op[col + 1], (c[mt][idx][2 * e + 1] - m) * q * Gs[col + 1] + BEs[col + 1]);
                }
            } else {
#pragma unroll
                for (int idx = 0; idx < 8; idx++) {
                    int col = nwarp * 64 + (idx >> 1) * 16 + (idx & 1) * 8 + 2 * (lane & 3);
                    float v0 = (c[mt][idx][2 * e]     - m) * q * Gs[col]     + BEs[col];
                    float v1 = (c[mt][idx][2 * e + 1] - m) * q * Gs[col + 1] + BEs[col + 1];
                    if (resHi) {
                        uint32_t rh = *(const uint32_t*)&resHi[(size_t)gr * LAT + col];
                        uint32_t rl = *(const uint32_t*)&resLo[(size_t)gr * LAT + col];
                        v0 += recon(rh, 0) + recon(rl, 0);
                        v1 += recon(rh, 1) + recon(rl, 1);
                    }
                    uint32_t hi, lo;
                    split_pair(v0, v1, hi, lo);
                    *(uint32_t*)&outHi[(size_t)gr * LAT + col] = hi;
                    *(uint32_t*)&outLo[(size_t)gr * LAT + col] = lo;
                }
            }
        }
}

// weight prep: transpose [K,128] -> [128,K] + bf16 hi/lo split
__global__ void prep_split(const float* __restrict__ W,
                           __nv_bfloat16* __restrict__ hi,
                           __nv_bfloat16* __restrict__ lo, int K)
{
    int i = blockIdx.x * blockDim.x + threadIdx.x;
    if (i >= K * 128) return;
    int k = i >> 7, n = i & 127;
    float v = W[i];
    __nv_bfloat16 h = __float2bfloat16(v);
    hi[(size_t)n * K + k] = h;
    lo[(size_t)n * K + k] = __float2bfloat16(v - __bfloat162float(h));
}

__global__ __launch_bounds__(256) void decoder_kernel(
    const __nv_bfloat16* __restrict__ hHi, const __nv_bfloat16* __restrict__ hLo,
    const float* __restrict__ W1, const float* __restrict__ B1,
    const float* __restrict__ W2, const float* __restrict__ B2,
    float* __restrict__ out, int n)
{
    extern __shared__ float s[];
    float* W1s = s;
    float* hs = s + 128 * 128;
    int tid = threadIdx.x;
#pragma unroll
    for (int it = 0; it < 16; it++) {
        int f = tid + 256 * it;
        *(float4*)&W1s[f * 4] = *(const float4*)&W1[f * 4];
    }
    int warp = tid >> 5, lane = tid & 31;
    int row = blockIdx.x * 8 + warp;
    int rc = min(row, n - 1);
#pragma unroll
    for (int q = 0; q < 4; q++) {
        int cc = lane + 32 * q;
        hs[warp * 128 + cc] = __bfloat162float(hHi[(size_t)rc * LAT + cc]) +
                              __bfloat162float(hLo[(size_t)rc * LAT + cc]);
    }
    __syncthreads();

    float acc[4];
#pragma unroll
    for (int q = 0; q < 4; q++) acc[q] = B1[lane + 32 * q];
    for (int k = 0; k < 128; k++) {
        float hv = hs[warp * 128 + k];
#pragma unroll
        for (int q = 0; q < 4; q++)
            acc[q] = fmaf(hv, W1s[k * 128 + lane + 32 * q], acc[q]);
    }
#pragma unroll
    for (int q = 0; q < 4; q++) acc[q] = fmaxf(acc[q], 0.f);

    float o[3];
#pragma unroll
    for (int oo = 0; oo < 3; oo++) {
        float p = 0.f;
#pragma unroll
        for (int q = 0; q < 4; q++)
            p = fmaf(acc[q], W2[(size_t)(lane + 32 * q) * 3 + oo], p);
#pragma unroll
        for (int off = 16; off > 0; off >>= 1)
            p += __shfl_xor_sync(0xffffffffu, p, off);
        o[oo] = p;
    }
    if (lane == 0 && row < n) {
        out[(size_t)row * 3 + 0] = o[0] + B2[0];
        out[(size_t)row * 3 + 1] = o[1] + B2[1];
        out[(size_t)row * 3 + 2] = o[2] + B2[2];
    }
}

__global__ void zero_kernel(float4* __restrict__ p, int n4)
{
    int i = blockIdx.x * blockDim.x + threadIdx.x;
    if (i < n4) p[i] = make_float4(0.f, 0.f, 0.f, 0.f);
}

extern "C" void kernel_launch(void* const* d_in, const int* in_sizes, int n_in,
                              void* d_out, int out_size)
{
    (void)in_sizes; (void)n_in; (void)out_size;
    const float* x  = (const float*)d_in[0];
    const float* ea = (const float*)d_in[1];
    const int*   ei = (const int*)d_in[2];
    const int* src = ei;
    const int* dst = ei + NEDGES;

    const float* ne_w1 = (const float*)d_in[3];
    const float* ne_b1 = (const float*)d_in[4];
    const float* ne_w2 = (const float*)d_in[5];
    const float* ne_b2 = (const float*)d_in[6];
    const float* ne_g  = (const float*)d_in[7];
    const float* ne_be = (const float*)d_in[8];
    const float* ee_w1 = (const float*)d_in[9];
    const float* ee_b1 = (const float*)d_in[10];
    const float* ee_w2 = (const float*)d_in[11];
    const float* ee_b2 = (const float*)d_in[12];
    const float* ee_g  = (const float*)d_in[13];
    const float* ee_be = (const float*)d_in[14];
    const float* em_w1 = (const float*)d_in[15];
    const float* em_b1 = (const float*)d_in[16];
    const float* em_w2 = (const float*)d_in[17];
    const float* em_b2 = (const float*)d_in[18];
    const float* em_g  = (const float*)d_in[19];
    const float* em_be = (const float*)d_in[20];
    const float* nm_w1 = (const float*)d_in[21];
    const float* nm_b1 = (const float*)d_in[22];
    const float* nm_w2 = (const float*)d_in[23];
    const float* nm_b2 = (const float*)d_in[24];
    const float* nm_g  = (const float*)d_in[25];
    const float* nm_be = (const float*)d_in[26];
    const float* dw1   = (const float*)d_in[27];
    const float* db1   = (const float*)d_in[28];
    const float* dw2   = (const float*)d_in[29];
    const float* db2   = (const float*)d_in[30];

    float* agg = nullptr;
    cudaGetSymbolAddress((void**)&agg, g_agg);
    __nv_bfloat16* hp = nullptr;
    cudaGetSymbolAddress((void**)&hp, g_hpl);
    __nv_bfloat16* ep = nullptr;
    cudaGetSymbolAddress((void**)&ep, g_epl);
    const size_t HS = (size_t)NNODES * LAT, ES = (size_t)NEDGES * LAT;
    __nv_bfloat16 *hH0 = hp, *hL0 = hp + HS, *hH1 = hp + 2 * HS, *hL1 = hp + 3 * HS;
    __nv_bfloat16 *eH0 = ep, *eL0 = ep + ES, *eH1 = ep + 2 * ES, *eL1 = ep + 3 * ES;

    __nv_bfloat16* pl = nullptr;
    cudaGetSymbolAddress((void**)&pl, g_planes);
    __nv_bfloat16* emW1h = pl;
    __nv_bfloat16* emW1l = pl + 49152;
    __nv_bfloat16* emW2h = pl + 98304;
    __nv_bfloat16* emW2l = pl + 114688;
    __nv_bfloat16* nmW1h = pl + 131072;
    __nv_bfloat16* nmW1l = pl + 163840;
    __nv_bfloat16* nmW2h = pl + 196608;
    __nv_bfloat16* nmW2l = pl + 212992;
    __nv_bfloat16* neW2h = pl + 229376;
    __nv_bfloat16* neW2l = pl + 245760;
    __nv_bfloat16* eeW2h = pl + 262144;
    __nv_bfloat16* eeW2l = pl + 278528;

    cudaFuncSetAttribute(gnn_mma<16, 0, false>,
                         cudaFuncAttributeMaxDynamicSharedMemorySize, SMEM_DYN);
    cudaFuncSetAttribute(gnn_mma<384, 1, true>,
                         cudaFuncAttributeMaxDynamicSharedMemorySize, SMEM_DYN);
    cudaFuncSetAttribute(gnn_mma<384, 1, false>,
                         cudaFuncAttributeMaxDynamicSharedMemorySize, SMEM_DYN);
    cudaFuncSetAttribute(gnn_mma<256, 2, false>,
                         cudaFuncAttributeMaxDynamicSharedMemorySize, SMEM_DYN);
    const int DSM = (128 * 128 + 8 * 128) * (int)sizeof(float);
    cudaFuncSetAttribute(decoder_kernel,
                         cudaFuncAttributeMaxDynamicSharedMemorySize, DSM);

    prep_split<<<(384 * 128 + 255) / 256, 256>>>(em_w1, emW1h, emW1l, 384);
    prep_split<<<(128 * 128 + 255) / 256, 256>>>(em_w2, emW2h, emW2l, 128);
    prep_split<<<(256 * 128 + 255) / 256, 256>>>(nm_w1, nmW1h, nmW1l, 256);
    prep_split<<<(128 * 128 + 255) / 256, 256>>>(nm_w2, nmW2h, nmW2l, 128);
    prep_split<<<(128 * 128 + 255) / 256, 256>>>(ne_w2, neW2h, neW2l, 128);
    prep_split<<<(128 * 128 + 255) / 256, 256>>>(ee_w2, eeW2h, eeW2l, 128);

    dim3 blk(256);
    const int ntiles = (NNODES + 127) / 128;  // 391
    const int etiles = NEDGES / 128;          // 3125

    // Encoders -> planes
    gnn_mma<16, 0, false><<<ntiles, blk, SMEM_DYN>>>(
        x, ne_w1, 3, nullptr, nullptr, nullptr, nullptr, nullptr, nullptr, nullptr,
        nullptr, nullptr, ne_b1, neW2h, neW2l, ne_b2, ne_g, ne_be,
        nullptr, nullptr, hH0, hL0, nullptr, nullptr, NNODES);
    gnn_mma<16, 0, false><<<etiles, blk, SMEM_DYN>>>(
        ea, ee_w1, 4, nullptr, nullptr, nullptr, nullptr, nullptr, nullptr, nullptr,
        nullptr, nullptr, ee_b1, eeW2h, eeW2l, ee_b2, ee_g, ee_be,
        nullptr, nullptr, eH0, eL0, nullptr, nullptr, NEDGES);

    __nv_bfloat16 *hcH = hH0, *hcL = hL0, *hnH = hH1, *hnL = hL1;
    __nv_bfloat16 *ecH = eH0, *ecL = eL0, *enH = eH1, *enL = eL1;
    for (int s = 0; s < 5; s++) {
        zero_kernel<<<(NNODES * LAT / 4 + 255) / 256, 256>>>((float4*)agg, NNODES * LAT / 4);
        // messages: ln_mlp(cat(h[dst], h[src], e)) scatter-add into agg[dst]
        gnn_mma<384, 1, true><<<etiles, blk, SMEM_DYN>>>(
            nullptr, nullptr, 0, nullptr, hcH, hcL, ecH, ecL, dst, src,
            emW1h, emW1l, em_b1, emW2h, emW2l, em_b2, em_g, em_be,
            nullptr, nullptr, nullptr, nullptr, agg, dst, NEDGES);
        // edge update: ln_mlp(cat(h[src], h[dst], e)) + e
        gnn_mma<384, 1, false><<<etiles, blk, SMEM_DYN>>>(
            nullptr, nullptr, 0, nullptr, hcH, hcL, ecH, ecL, src, dst,
            emW1h, emW1l, em_b1, emW2h, emW2l, em_b2, em_g, em_be,
            ecH, ecL, enH, enL, nullptr, nullptr, NEDGES);
        // node update: ln_mlp(cat(agg, h)) + h
        gnn_mma<256, 2, false><<<ntiles, blk, SMEM_DYN>>>(
            nullptr, nullptr, 0, agg, hcH, hcL, nullptr, nullptr, nullptr, nullptr,
            nmW1h, nmW1l, nm_b1, nmW2h, nmW2l, nm_b2, nm_g, nm_be,
            hcH, hcL, hnH, hnL, nullptr, nullptr, NNODES);
        __nv_bfloat16* t;
        t = hcH; hcH = hnH; hnH = t;
        t = hcL; hcL = hnL; hnL = t;
        t = ecH; ecH = enH; enH = t;
        t = ecL; ecL = enL; enL = t;
    }

    decoder_kernel<<<(NNODES + 7) / 8, blk, DSM>>>(
        hcH, hcL, dw1, db1, dw2, db2, (float*)d_out, NNODES);
}

// round 7
// speedup vs baseline: 2.3967x; 1.0232x over previous
#include <cuda_runtime.h>
#include <cuda_bf16.h>
#include <cstdint>
#include <cstddef>

#define LAT 128
#define NNODES 50000
#define NEDGES 400000
#define EPSV 1e-5f

__device__ float g_agg[(size_t)NNODES * LAT];
__device__ __align__(16) __nv_bfloat16 g_hpl[(size_t)4 * NNODES * LAT];
__device__ __align__(16) __nv_bfloat16 g_epl[(size_t)4 * NEDGES * LAT];
__device__ __align__(16) __nv_bfloat16 g_planes[294912];

__device__ __forceinline__ uint32_t smem_u32(const void* p) {
    uint32_t a;
    asm("{ .reg .u64 t; cvta.to.shared.u64 t, %1; cvt.u32.u64 %0, t; }" : "=r"(a) : "l"(p));
    return a;
}
__device__ __forceinline__ void ldsm4(uint32_t addr, uint32_t* r) {
    asm volatile("ldmatrix.sync.aligned.m8n8.x4.shared.b16 {%0,%1,%2,%3}, [%4];"
                 : "=r"(r[0]), "=r"(r[1]), "=r"(r[2]), "=r"(r[3]) : "r"(addr));
}
__device__ __forceinline__ void mma_bf16(float* d, const uint32_t* a, const uint32_t* b) {
    asm volatile("mma.sync.aligned.m16n8k16.row.col.f32.bf16.bf16.f32 "
                 "{%0,%1,%2,%3}, {%4,%5,%6,%7}, {%8,%9}, {%0,%1,%2,%3};"
                 : "+f"(d[0]), "+f"(d[1]), "+f"(d[2]), "+f"(d[3])
                 : "r"(a[0]), "r"(a[1]), "r"(a[2]), "r"(a[3]), "r"(b[0]), "r"(b[1]));
}
__device__ __forceinline__ void cpa16(uint32_t saddr, const void* g) {
    asm volatile("cp.async.cg.shared.global [%0], [%1], 16;"
                 :: "r"(saddr), "l"(g) : "memory");
}
#define CPA_COMMIT() asm volatile("cp.async.commit_group;" ::: "memory")
#define CPA_WAIT(N)  asm volatile("cp.async.wait_group %0;" :: "n"(N) : "memory")
__device__ __forceinline__ void red2(float* addr, float v0, float v1) {
    asm volatile("red.global.add.v2.f32 [%0], {%1, %2};"
                 :: "l"(addr), "f"(v0), "f"(v1) : "memory");
}
__device__ __forceinline__ uint32_t swz(uint32_t bo) { return bo ^ ((bo >> 3) & 0x70); }
__device__ __forceinline__ void split_pair(float a, float b, uint32_t& hi, uint32_t& lo) {
    __nv_bfloat16 ah = __float2bfloat16(a), bh = __float2bfloat16(b);
    __nv_bfloat162 hp; hp.x = ah; hp.y = bh;
    __nv_bfloat162 lp;
    lp.x = __float2bfloat16(a - __bfloat162float(ah));
    lp.y = __float2bfloat16(b - __bfloat162float(bh));
    hi = *reinterpret_cast<uint32_t*>(&hp);
    lo = *reinterpret_cast<uint32_t*>(&lp);
}
__device__ __forceinline__ float recon(uint32_t packed, int half) {
    __nv_bfloat162 v = *reinterpret_cast<__nv_bfloat162*>(&packed);
    return half ? __bfloat162float(v.y) : __bfloat162float(v.x);
}

// SMEM: two 64KB chunk buffers, then misc.
// buf b (b*65536): A_HI +0, A_LO +16K, W_HI +32K, W_LO +48K
// After layer1 (last chunk always reads buf1): H -> buf0 (HI 0..32K, LO 32..64K),
// W2 (both k-chunks, hi+lo) -> buf1 (chunk c2 at 65536+c2*32768, lo at +16384).
#define OFF_BUF(b) ((b) * 65536)
#define OFF_H_HI   0
#define OFF_H_LO   32768
#define OFF_W2(c)  (65536 + (c) * 32768)
#define OFF_IDX    131072
#define OFF_B1     132096
#define OFF_B2     132608
#define OFF_G      133120
#define OFF_BE     133632
#define OFF_LN     134144
#define OFF_W1RAW  136192
#define SMEM_DYN   138240

// gather/concat -> Lin(K,128)+ReLU -> Lin(128,128)+ReLU -> LN [+res] -> planes|scatter
// GMODE 0: raw fp32 (encoder, SIMT layer1). 1: [h[idxA]|h[idxB]|e] K=384. 2: [aggF|h] K=256.
template <int KTOT, int GMODE, bool ATOMIC>
__global__ __launch_bounds__(256, 1) void gnn_mma(
    const float* __restrict__ raw, const float* __restrict__ W1raw, int kreal,
    const float* __restrict__ aggF,
    const __nv_bfloat16* __restrict__ hHi, const __nv_bfloat16* __restrict__ hLo,
    const __nv_bfloat16* __restrict__ eHi, const __nv_bfloat16* __restrict__ eLo,
    const int* __restrict__ idxA, const int* __restrict__ idxB,
    const __nv_bfloat16* __restrict__ W1hi, const __nv_bfloat16* __restrict__ W1lo,
    const float* __restrict__ B1,
    const __nv_bfloat16* __restrict__ W2hi, const __nv_bfloat16* __restrict__ W2lo,
    const float* __restrict__ B2,
    const float* __restrict__ G, const float* __restrict__ BE,
    const __nv_bfloat16* __restrict__ resHi, const __nv_bfloat16* __restrict__ resLo,
    __nv_bfloat16* __restrict__ outHi, __nv_bfloat16* __restrict__ outLo,
    float* __restrict__ outF, const int* __restrict__ scatIdx, int nRows)
{
    extern __shared__ char smp[];
    const uint32_t sb = smem_u32(smp);

    const int tid = threadIdx.x;
    const int wid = tid >> 5, lane = tid & 31;
    const int mwarp = wid & 3, nwarp = wid >> 2;
    const int blockRow = blockIdx.x * 128;

    int* idxs = (int*)(smp + OFF_IDX);
    float* b1s = (float*)(smp + OFF_B1);
    float* b2s = (float*)(smp + OFF_B2);
    float* Gs  = (float*)(smp + OFF_G);
    float* BEs = (float*)(smp + OFF_BE);
    float* lnb = (float*)(smp + OFF_LN);
    float* w1r = (float*)(smp + OFF_W1RAW);

    if constexpr (GMODE == 1) {
        if (tid < 128) idxs[tid] = idxA[min(blockRow + tid, nRows - 1)];
        else idxs[tid] = idxB[min(blockRow + tid - 128, nRows - 1)];
    }
    if (tid < 128) {
        b1s[tid] = B1[tid]; b2s[tid] = B2[tid];
        Gs[tid] = G[tid];   BEs[tid] = BE[tid];
    }
    if constexpr (GMODE == 0) {
        for (int i = tid; i < kreal * 128; i += 256) w1r[i] = W1raw[i];
    }
    __syncthreads();

    // ldmatrix addressing
    const int lrow = lane & 7, lg = lane >> 3;
    const uint32_t xm = (uint32_t)lrow << 4;
    const int a_row0 = mwarp * 32 + lrow + 8 * (lg & 1);
    const int a_kx = lg >> 1;
    const int b_row0 = nwarp * 64 + lrow + 8 * (lg >> 1);
    const int b_kx = lg & 1;

    float c[2][8][4];
#pragma unroll
    for (int mt = 0; mt < 2; mt++)
#pragma unroll
        for (int i = 0; i < 8; i++)
#pragma unroll
            for (int j = 0; j < 4; j++) c[mt][i][j] = 0.f;

    // ---- fill helper: stage chunk ch into buf[ch&1] (cp.async; agg = manual) ----
    auto fill = [&](int ch) {
        const uint32_t bbase = sb + OFF_BUF(ch & 1);
        char* bptr = smp + OFF_BUF(ch & 1);
        if ((GMODE == 2) && (ch < 2)) {
            const int koff = ch * 64;
#pragma unroll
            for (int p = 0; p < 8; p++) {
                int idx = tid + 256 * p;
                int row = idx >> 4, f4 = idx & 15;
                int ri = min(blockRow + row, nRows - 1);
                float4 v = *(const float4*)&aggF[(size_t)ri * LAT + koff + f4 * 4];
                uint32_t h0, h1, l0, l1;
                split_pair(v.x, v.y, h0, l0);
                split_pair(v.z, v.w, h1, l1);
                uint32_t sw = swz((uint32_t)(row * 128 + f4 * 8));
                *(uint2*)(bptr + sw) = make_uint2(h0, h1);
                *(uint2*)(bptr + 16384 + sw) = make_uint2(l0, l1);
            }
        } else {
            const __nv_bfloat16 *pHi, *pLo;
            int koff, ibase = 0;
            bool useIdx = false;
            if constexpr (GMODE == 1) {
                int sel = ch >> 1;
                koff = (ch & 1) * 64;
                if (sel == 2) { pHi = eHi; pLo = eLo; }
                else { pHi = hHi; pLo = hLo; useIdx = true; ibase = sel * 128; }
            } else {
                pHi = hHi; pLo = hLo; koff = (ch - 2) * 64;
            }
#pragma unroll
            for (int p = 0; p < 4; p++) {
                int idx = tid + 256 * p;
                int row = idx >> 3, q = idx & 7;
                int ri = useIdx ? idxs[ibase + row] : min(blockRow + row, nRows - 1);
                size_t go = (size_t)ri * LAT + koff + q * 8;
                uint32_t sw = swz((uint32_t)(row * 128 + q * 16));
                cpa16(bbase + sw, pHi + go);
                cpa16(bbase + 16384 + sw, pLo + go);
            }
        }
        // W1 chunk
#pragma unroll
        for (int p = 0; p < 4; p++) {
            int idx = tid + 256 * p;
            int row = idx >> 3, q = idx & 7;
            const size_t go = (size_t)row * KTOT + ch * 64 + q * 8;
            uint32_t sw = swz((uint32_t)(row * 128 + q * 16));
            cpa16(bbase + 32768 + sw, W1hi + go);
            cpa16(bbase + 49152 + sw, W1lo + go);
        }
    };
    auto fillW2 = [&]() {
#pragma unroll
        for (int p = 0; p < 8; p++) {
            int idx = tid + 256 * p;
            int row = idx >> 4, q = idx & 15;
            int c2 = q >> 3, qq = q & 7;
            size_t go = (size_t)row * 128 + c2 * 64 + qq * 8;
            uint32_t sw = swz((uint32_t)(row * 128 + qq * 16));
            cpa16(sb + OFF_W2(c2) + sw, W2hi + go);
            cpa16(sb + OFF_W2(c2) + 16384 + sw, W2lo + go);
        }
    };

    if constexpr (KTOT > 16) {
        constexpr int NC = KTOT / 64;
        fill(0); CPA_COMMIT();
        fill(1); CPA_COMMIT();
        for (int ch = 0; ch < NC; ch++) {
            if (ch < NC - 1) CPA_WAIT(1);
            else CPA_WAIT(0);
            __syncthreads();
            const uint32_t bbase = sb + OFF_BUF(ch & 1);
#pragma unroll
            for (int ks = 0; ks < 4; ks++) {
                const uint32_t kcA = (uint32_t)((ks * 2 + a_kx) * 16) ^ xm;
                const uint32_t kcB = (uint32_t)((ks * 2 + b_kx) * 16) ^ xm;
                uint32_t ah[2][4], al[2][4];
#pragma unroll
                for (int mt = 0; mt < 2; mt++) {
                    uint32_t ro = (uint32_t)((a_row0 + mt * 16) * 128);
                    ldsm4(bbase + ro + kcA, ah[mt]);
                    ldsm4(bbase + 16384 + ro + kcA, al[mt]);
                }
#pragma unroll
                for (int g = 0; g < 4; g++) {
                    uint32_t bh[4], bl[4];
                    uint32_t ro = (uint32_t)((b_row0 + g * 16) * 128);
                    ldsm4(bbase + 32768 + ro + kcB, bh);
                    ldsm4(bbase + 49152 + ro + kcB, bl);
#pragma unroll
                    for (int mt = 0; mt < 2; mt++)
#pragma unroll
                        for (int hf = 0; hf < 2; hf++) {
                            float* cc = c[mt][g * 2 + hf];
                            mma_bf16(cc, ah[mt], &bh[hf * 2]);
                            mma_bf16(cc, ah[mt], &bl[hf * 2]);
                            mma_bf16(cc, al[mt], &bh[hf * 2]);
                        }
                }
            }
            __syncthreads();
            if (ch + 2 < NC) { fill(ch + 2); CPA_COMMIT(); }
        }
        // buffers fully drained; H -> buf0, prefetch W2 -> buf1
        fillW2();
        CPA_COMMIT();
#pragma unroll
        for (int mt = 0; mt < 2; mt++)
#pragma unroll
            for (int idx = 0; idx < 8; idx++)
#pragma unroll
                for (int e = 0; e < 2; e++) {
                    int row = mwarp * 32 + mt * 16 + (lane >> 2) + 8 * e;
                    int col = nwarp * 64 + (idx >> 1) * 16 + (idx & 1) * 8 + 2 * (lane & 3);
                    float v0 = fmaxf(c[mt][idx][2 * e] + b1s[col], 0.f);
                    float v1 = fmaxf(c[mt][idx][2 * e + 1] + b1s[col + 1], 0.f);
                    uint32_t hi, lo;
                    split_pair(v0, v1, hi, lo);
                    uint32_t off = (uint32_t)(nwarp * 16384 + row * 128 +
                                              (((col & 63) * 2) ^ ((row & 7) << 4)));
                    *(uint32_t*)(smp + OFF_H_HI + off) = hi;
                    *(uint32_t*)(smp + OFF_H_LO + off) = lo;
                }
#pragma unroll
        for (int mt = 0; mt < 2; mt++)
#pragma unroll
            for (int i = 0; i < 8; i++)
#pragma unroll
                for (int j = 0; j < 4; j++) c[mt][i][j] = 0.f;
        CPA_WAIT(0);
        __syncthreads();
    } else {
        // encoder: prefetch W2, SIMT layer1 into H
        fillW2();
        CPA_COMMIT();
#pragma unroll
        for (int mt = 0; mt < 2; mt++)
#pragma unroll
            for (int e = 0; e < 2; e++) {
                int row = mwarp * 32 + mt * 16 + (lane >> 2) + 8 * e;
                int grc = min(blockRow + row, nRows - 1);
                float xv[4];
#pragma unroll
                for (int k = 0; k < 4; k++)
                    xv[k] = (k < kreal) ? raw[(size_t)grc * kreal + k] : 0.f;
#pragma unroll
                for (int idx = 0; idx < 8; idx++) {
                    int col = nwarp * 64 + (idx >> 1) * 16 + (idx & 1) * 8 + 2 * (lane & 3);
                    float v0 = b1s[col], v1 = b1s[col + 1];
                    for (int k = 0; k < kreal; k++) {
                        v0 = fmaf(xv[k], w1r[k * 128 + col], v0);
                        v1 = fmaf(xv[k], w1r[k * 128 + col + 1], v1);
                    }
                    v0 = fmaxf(v0, 0.f); v1 = fmaxf(v1, 0.f);
                    uint32_t hi, lo;
                    split_pair(v0, v1, hi, lo);
                    uint32_t off = (uint32_t)(nwarp * 16384 + row * 128 +
                                              (((col & 63) * 2) ^ ((row & 7) << 4)));
                    *(uint32_t*)(smp + OFF_H_HI + off) = hi;
                    *(uint32_t*)(smp + OFF_H_LO + off) = lo;
                }
            }
        CPA_WAIT(0);
        __syncthreads();
    }

    // ---- layer 2: both W2 chunks resident; no mid syncs ----
#pragma unroll
    for (int c2 = 0; c2 < 2; c2++) {
        const uint32_t abH = sb + OFF_H_HI + c2 * 16384;
        const uint32_t abL = sb + OFF_H_LO + c2 * 16384;
        const uint32_t wb = sb + OFF_W2(c2);
#pragma unroll
        for (int ks = 0; ks < 4; ks++) {
            const uint32_t kcA = (uint32_t)((ks * 2 + a_kx) * 16) ^ xm;
            const uint32_t kcB = (uint32_t)((ks * 2 + b_kx) * 16) ^ xm;
            uint32_t ah[2][4], al[2][4];
#pragma unroll
            for (int mt = 0; mt < 2; mt++) {
                uint32_t ro = (uint32_t)((a_row0 + mt * 16) * 128);
                ldsm4(abH + ro + kcA, ah[mt]);
                ldsm4(abL + ro + kcA, al[mt]);
            }
#pragma unroll
            for (int g = 0; g < 4; g++) {
                uint32_t bh[4], bl[4];
                uint32_t ro = (uint32_t)((b_row0 + g * 16) * 128);
                ldsm4(wb + ro + kcB, bh);
                ldsm4(wb + 16384 + ro + kcB, bl);
#pragma unroll
                for (int mt = 0; mt < 2; mt++)
#pragma unroll
                    for (int hf = 0; hf < 2; hf++) {
                        float* cc = c[mt][g * 2 + hf];
                        mma_bf16(cc, ah[mt], &bh[hf * 2]);
                        mma_bf16(cc, ah[mt], &bl[hf * 2]);
                        mma_bf16(cc, al[mt], &bh[hf * 2]);
                    }
            }
        }
    }

    // ---- bias2 + ReLU ----
#pragma unroll
    for (int mt = 0; mt < 2; mt++)
#pragma unroll
        for (int idx = 0; idx < 8; idx++) {
            int col = nwarp * 64 + (idx >> 1) * 16 + (idx & 1) * 8 + 2 * (lane & 3);
#pragma unroll
            for (int j = 0; j < 4; j++)
                c[mt][idx][j] = fmaxf(c[mt][idx][j] + b2s[col + (j & 1)], 0.f);
        }

    // ---- LayerNorm ----
#pragma unroll
    for (int mt = 0; mt < 2; mt++)
#pragma unroll
        for (int e = 0; e < 2; e++) {
            float s = 0.f;
#pragma unroll
            for (int idx = 0; idx < 8; idx++)
                s += c[mt][idx][2 * e] + c[mt][idx][2 * e + 1];
            s += __shfl_xor_sync(0xffffffffu, s, 1);
            s += __shfl_xor_sync(0xffffffffu, s, 2);
            if ((lane & 3) == 0) {
                int row = mwarp * 32 + mt * 16 + (lane >> 2) + 8 * e;
                lnb[row * 2 + nwarp] = s;
            }
        }
    __syncthreads();
    float mu[2][2], rs[2][2];
#pragma unroll
    for (int mt = 0; mt < 2; mt++)
#pragma unroll
        for (int e = 0; e < 2; e++) {
            int row = mwarp * 32 + mt * 16 + (lane >> 2) + 8 * e;
            mu[mt][e] = (lnb[row * 2] + lnb[row * 2 + 1]) * (1.0f / 128.0f);
            float sq = 0.f;
#pragma unroll
            for (int idx = 0; idx < 8; idx++) {
                float d0 = c[mt][idx][2 * e] - mu[mt][e];
                float d1 = c[mt][idx][2 * e + 1] - mu[mt][e];
                sq = fmaf(d0, d0, sq);
                sq = fmaf(d1, d1, sq);
            }
            sq += __shfl_xor_sync(0xffffffffu, sq, 1);
            sq += __shfl_xor_sync(0xffffffffu, sq, 2);
            if ((lane & 3) == 0) lnb[256 + row * 2 + nwarp] = sq;
        }
    __syncthreads();
#pragma unroll
    for (int mt = 0; mt < 2; mt++)
#pragma unroll
        for (int e = 0; e < 2; e++) {
            int row = mwarp * 32 + mt * 16 + (lane >> 2) + 8 * e;
            rs[mt][e] = rsqrtf((lnb[256 + row * 2] + lnb[256 + row * 2 + 1]) *
                                   (1.0f / 128.0f) + EPSV);
        }

    // ---- output ----
#pragma unroll
    for (int mt = 0; mt < 2; mt++)
#pragma unroll
        for (int e = 0; e < 2; e++) {
            int row = mwarp * 32 + mt * 16 + (lane >> 2) + 8 * e;
            int gr = blockRow + row;
            if (gr >= nRows) continue;
            float m = mu[mt][e], q = rs[mt][e];
            if constexpr (ATOMIC) {
                const int drow = scatIdx[gr];
                float* op = outF + (size_t)drow * LAT;
#pragma unroll
                for (int idx = 0; idx < 8; idx++) {
                    int col = nwarp * 64 + (idx >> 1) * 16 + (idx & 1) * 8 + 2 * (lane & 3);
                    float v0 = (c[mt][idx][2 * e]     - m) * q * Gs[col]     + BEs[col];
                    float v1 = (c[mt][idx][2 * e + 1] - m) * q * Gs[col + 1] + BEs[col + 1];
                    red2(&op[col], v0, v1);
                }
            } else {
#pragma unroll
                for (int idx = 0; idx < 8; idx++) {
                    int col = nwarp * 64 + (idx >> 1) * 16 + (idx & 1) * 8 + 2 * (lane & 3);
                    float v0 = (c[mt][idx][2 * e]     - m) * q * Gs[col]     + BEs[col];
                    float v1 = (c[mt][idx][2 * e + 1] - m) * q * Gs[col + 1] + BEs[col + 1];
                    if (resHi) {
                        uint32_t rh = *(const uint32_t*)&resHi[(size_t)gr * LAT + col];
                        uint32_t rl = *(const uint32_t*)&resLo[(size_t)gr * LAT + col];
                        v0 += recon(rh, 0) + recon(rl, 0);
                        v1 += recon(rh, 1) + recon(rl, 1);
                    }
                    uint32_t hi, lo;
                    split_pair(v0, v1, hi, lo);
                    *(uint32_t*)&outHi[(size_t)gr * LAT + col] = hi;
                    *(uint32_t*)&outLo[(size_t)gr * LAT + col] = lo;
                }
            }
        }
}

// merged weight prep: 6 matrices, transpose + hi/lo split, single launch
__global__ void prep_all(
    const float* __restrict__ s0, __nv_bfloat16* __restrict__ h0b, __nv_bfloat16* __restrict__ l0b,
    const float* __restrict__ s1, __nv_bfloat16* __restrict__ h1b, __nv_bfloat16* __restrict__ l1b,
    const float* __restrict__ s2, __nv_bfloat16* __restrict__ h2b, __nv_bfloat16* __restrict__ l2b,
    const float* __restrict__ s3, __nv_bfloat16* __restrict__ h3b, __nv_bfloat16* __restrict__ l3b,
    const float* __restrict__ s4, __nv_bfloat16* __restrict__ h4b, __nv_bfloat16* __restrict__ l4b,
    const float* __restrict__ s5, __nv_bfloat16* __restrict__ h5b, __nv_bfloat16* __restrict__ l5b)
{
    int i = blockIdx.x * blockDim.x + threadIdx.x;
    const float* W; __nv_bfloat16 *hi, *lo; int K, j;
    if (i < 49152)       { W = s0; hi = h0b; lo = l0b; K = 384; j = i; }
    else if (i < 65536)  { W = s1; hi = h1b; lo = l1b; K = 128; j = i - 49152; }
    else if (i < 98304)  { W = s2; hi = h2b; lo = l2b; K = 256; j = i - 65536; }
    else if (i < 114688) { W = s3; hi = h3b; lo = l3b; K = 128; j = i - 98304; }
    else if (i < 131072) { W = s4; hi = h4b; lo = l4b; K = 128; j = i - 114688; }
    else if (i < 147456) { W = s5; hi = h5b; lo = l5b; K = 128; j = i - 131072; }
    else return;
    int k = j >> 7, n = j & 127;
    float v = W[j];
    __nv_bfloat16 h = __float2bfloat16(v);
    hi[(size_t)n * K + k] = h;
    lo[(size_t)n * K + k] = __float2bfloat16(v - __bfloat162float(h));
}

__global__ __launch_bounds__(256) void decoder_kernel(
    const __nv_bfloat16* __restrict__ hHi, const __nv_bfloat16* __restrict__ hLo,
    const float* __restrict__ W1, const float* __restrict__ B1,
    const float* __restrict__ W2, const float* __restrict__ B2,
    float* __restrict__ out, int n)
{
    extern __shared__ float s[];
    float* W1s = s;
    float* hs = s + 128 * 128;
    int tid = threadIdx.x;
#pragma unroll
    for (int it = 0; it < 16; it++) {
        int f = tid + 256 * it;
        *(float4*)&W1s[f * 4] = *(const float4*)&W1[f * 4];
    }
    int warp = tid >> 5, lane = tid & 31;
    int row = blockIdx.x * 8 + warp;
    int rc = min(row, n - 1);
#pragma unroll
    for (int q = 0; q < 4; q++) {
        int cc = lane + 32 * q;
        hs[warp * 128 + cc] = __bfloat162float(hHi[(size_t)rc * LAT + cc]) +
                              __bfloat162float(hLo[(size_t)rc * LAT + cc]);
    }
    __syncthreads();

    float acc[4];
#pragma unroll
    for (int q = 0; q < 4; q++) acc[q] = B1[lane + 32 * q];
    for (int k = 0; k < 128; k++) {
        float hv = hs[warp * 128 + k];
#pragma unroll
        for (int q = 0; q < 4; q++)
            acc[q] = fmaf(hv, W1s[k * 128 + lane + 32 * q], acc[q]);
    }
#pragma unroll
    for (int q = 0; q < 4; q++) acc[q] = fmaxf(acc[q], 0.f);

    float o[3];
#pragma unroll
    for (int oo = 0; oo < 3; oo++) {
        float p = 0.f;
#pragma unroll
        for (int q = 0; q < 4; q++)
            p = fmaf(acc[q], W2[(size_t)(lane + 32 * q) * 3 + oo], p);
#pragma unroll
        for (int off = 16; off > 0; off >>= 1)
            p += __shfl_xor_sync(0xffffffffu, p, off);
        o[oo] = p;
    }
    if (lane == 0 && row < n) {
        out[(size_t)row * 3 + 0] = o[0] + B2[0];
        out[(size_t)row * 3 + 1] = o[1] + B2[1];
        out[(size_t)row * 3 + 2] = o[2] + B2[2];
    }
}

__global__ void zero_kernel(float4* __restrict__ p, int n4)
{
    int i = blockIdx.x * blockDim.x + threadIdx.x;
    if (i < n4) p[i] = make_float4(0.f, 0.f, 0.f, 0.f);
}

extern "C" void kernel_launch(void* const* d_in, const int* in_sizes, int n_in,
                              void* d_out, int out_size)
{
    (void)in_sizes; (void)n_in; (void)out_size;
    const float* x  = (const float*)d_in[0];
    const float* ea = (const float*)d_in[1];
    const int*   ei = (const int*)d_in[2];
    const int* src = ei;
    const int* dst = ei + NEDGES;

    const float* ne_w1 = (const float*)d_in[3];
    const float* ne_b1 = (const float*)d_in[4];
    const float* ne_w2 = (const float*)d_in[5];
    const float* ne_b2 = (const float*)d_in[6];
    const float* ne_g  = (const float*)d_in[7];
    const float* ne_be = (const float*)d_in[8];
    const float* ee_w1 = (const float*)d_in[9];
    const float* ee_b1 = (const float*)d_in[10];
    const float* ee_w2 = (const float*)d_in[11];
    const float* ee_b2 = (const float*)d_in[12];
    const float* ee_g  = (const float*)d_in[13];
    const float* ee_be = (const float*)d_in[14];
    const float* em_w1 = (const float*)d_in[15];
    const float* em_b1 = (const float*)d_in[16];
    const float* em_w2 = (const float*)d_in[17];
    const float* em_b2 = (const float*)d_in[18];
    const float* em_g  = (const float*)d_in[19];
    const float* em_be = (const float*)d_in[20];
    const float* nm_w1 = (const float*)d_in[21];
    const float* nm_b1 = (const float*)d_in[22];
    const float* nm_w2 = (const float*)d_in[23];
    const float* nm_b2 = (const float*)d_in[24];
    const float* nm_g  = (const float*)d_in[25];
    const float* nm_be = (const float*)d_in[26];
    const float* dw1   = (const float*)d_in[27];
    const float* db1   = (const float*)d_in[28];
    const float* dw2   = (const float*)d_in[29];
    const float* db2   = (const float*)d_in[30];

    float* agg = nullptr;
    cudaGetSymbolAddress((void**)&agg, g_agg);
    __nv_bfloat16* hp = nullptr;
    cudaGetSymbolAddress((void**)&hp, g_hpl);
    __nv_bfloat16* ep = nullptr;
    cudaGetSymbolAddress((void**)&ep, g_epl);
    const size_t HS = (size_t)NNODES * LAT, ES = (size_t)NEDGES * LAT;
    __nv_bfloat16 *hH0 = hp, *hL0 = hp + HS, *hH1 = hp + 2 * HS, *hL1 = hp + 3 * HS;
    __nv_bfloat16 *eH0 = ep, *eL0 = ep + ES, *eH1 = ep + 2 * ES, *eL1 = ep + 3 * ES;

    __nv_bfloat16* pl = nullptr;
    cudaGetSymbolAddress((void**)&pl, g_planes);
    __nv_bfloat16* emW1h = pl;
    __nv_bfloat16* emW1l = pl + 49152;
    __nv_bfloat16* emW2h = pl + 98304;
    __nv_bfloat16* emW2l = pl + 114688;
    __nv_bfloat16* nmW1h = pl + 131072;
    __nv_bfloat16* nmW1l = pl + 163840;
    __nv_bfloat16* nmW2h = pl + 196608;
    __nv_bfloat16* nmW2l = pl + 212992;
    __nv_bfloat16* neW2h = pl + 229376;
    __nv_bfloat16* neW2l = pl + 245760;
    __nv_bfloat16* eeW2h = pl + 262144;
    __nv_bfloat16* eeW2l = pl + 278528;

    cudaFuncSetAttribute(gnn_mma<16, 0, false>,
                         cudaFuncAttributeMaxDynamicSharedMemorySize, SMEM_DYN);
    cudaFuncSetAttribute(gnn_mma<384, 1, true>,
                         cudaFuncAttributeMaxDynamicSharedMemorySize, SMEM_DYN);
    cudaFuncSetAttribute(gnn_mma<384, 1, false>,
                         cudaFuncAttributeMaxDynamicSharedMemorySize, SMEM_DYN);
    cudaFuncSetAttribute(gnn_mma<256, 2, false>,
                         cudaFuncAttributeMaxDynamicSharedMemorySize, SMEM_DYN);
    const int DSM = (128 * 128 + 8 * 128) * (int)sizeof(float);
    cudaFuncSetAttribute(decoder_kernel,
                         cudaFuncAttributeMaxDynamicSharedMemorySize, DSM);

    prep_all<<<(147456 + 255) / 256, 256>>>(
        em_w1, emW1h, emW1l, em_w2, emW2h, emW2l,
        nm_w1, nmW1h, nmW1l, nm_w2, nmW2h, nmW2l,
        ne_w2, neW2h, neW2l, ee_w2, eeW2h, eeW2l);

    dim3 blk(256);
    const int ntiles = (NNODES + 127) / 128;  // 391
    const int etiles = NEDGES / 128;          // 3125

    gnn_mma<16, 0, false><<<ntiles, blk, SMEM_DYN>>>(
        x, ne_w1, 3, nullptr, nullptr, nullptr, nullptr, nullptr, nullptr, nullptr,
        nullptr, nullptr, ne_b1, neW2h, neW2l, ne_b2, ne_g, ne_be,
        nullptr, nullptr, hH0, hL0, nullptr, nullptr, NNODES);
    gnn_mma<16, 0, false><<<etiles, blk, SMEM_DYN>>>(
        ea, ee_w1, 4, nullptr, nullptr, nullptr, nullptr, nullptr, nullptr, nullptr,
        nullptr, nullptr, ee_b1, eeW2h, eeW2l, ee_b2, ee_g, ee_be,
        nullptr, nullptr, eH0, eL0, nullptr, nullptr, NEDGES);

    __nv_bfloat16 *hcH = hH0, *hcL = hL0, *hnH = hH1, *hnL = hL1;
    __nv_bfloat16 *ecH = eH0, *ecL = eL0, *enH = eH1, *enL = eL1;
    for (int s = 0; s < 5; s++) {
        zero_kernel<<<(NNODES * LAT / 4 + 255) / 256, 256>>>((float4*)agg, NNODES * LAT / 4);
        gnn_mma<384, 1, true><<<etiles, blk, SMEM_DYN>>>(
            nullptr, nullptr, 0, nullptr, hcH, hcL, ecH, ecL, dst, src,
            emW1h, emW1l, em_b1, emW2h, emW2l, em_b2, em_g, em_be,
            nullptr, nullptr, nullptr, nullptr, agg, dst, NEDGES);
        gnn_mma<384, 1, false><<<etiles, blk, SMEM_DYN>>>(
            nullptr, nullptr, 0, nullptr, hcH, hcL, ecH, ecL, src, dst,
            emW1h, emW1l, em_b1, emW2h, emW2l, em_b2, em_g, em_be,
            ecH, ecL, enH, enL, nullptr, nullptr, NEDGES);
        gnn_mma<256, 2, false><<<ntiles, blk, SMEM_DYN>>>(
            nullptr, nullptr, 0, agg, hcH, hcL, nullptr, nullptr, nullptr, nullptr,
            nmW1h, nmW1l, nm_b1, nmW2h, nmW2l, nm_b2, nm_g, nm_be,
            hcH, hcL, hnH, hnL, nullptr, nullptr, NNODES);
        __nv_bfloat16* t;
        t = hcH; hcH = hnH; hnH = t;
        t = hcL; hcL = hnL; hnL = t;
        t = ecH; ecH = enH; enH = t;
        t = ecL; ecL = enL; enL = t;
    }

    decoder_kernel<<<(NNODES + 7) / 8, blk, DSM>>>(
        hcH, hcL, dw1, db1, dw2, db2, (float*)d_out, NNODES);
}

// round 8
// speedup vs baseline: 3.1284x; 1.3053x over previous
#include <cuda_runtime.h>
#include <cuda_bf16.h>
#include <cstdint>
#include <cstddef>

#define LAT 128
#define NNODES 50000
#define NEDGES 400000
#define EPSV 1e-5f

// fp32: agg | Y1 | Y2 | Ye
__device__ float g_fbuf[(size_t)(3 * NNODES + NEDGES) * LAT];
__device__ __align__(16) __nv_bfloat16 g_hpl[(size_t)4 * NNODES * LAT];
__device__ __align__(16) __nv_bfloat16 g_epl[(size_t)4 * NEDGES * LAT];
__device__ __align__(16) __nv_bfloat16 g_planes[294912];

__device__ __forceinline__ uint32_t smem_u32(const void* p) {
    uint32_t a;
    asm("{ .reg .u64 t; cvta.to.shared.u64 t, %1; cvt.u32.u64 %0, t; }" : "=r"(a) : "l"(p));
    return a;
}
__device__ __forceinline__ void ldsm4(uint32_t addr, uint32_t* r) {
    asm volatile("ldmatrix.sync.aligned.m8n8.x4.shared.b16 {%0,%1,%2,%3}, [%4];"
                 : "=r"(r[0]), "=r"(r[1]), "=r"(r[2]), "=r"(r[3]) : "r"(addr));
}
__device__ __forceinline__ void mma_bf16(float* d, const uint32_t* a, const uint32_t* b) {
    asm volatile("mma.sync.aligned.m16n8k16.row.col.f32.bf16.bf16.f32 "
                 "{%0,%1,%2,%3}, {%4,%5,%6,%7}, {%8,%9}, {%0,%1,%2,%3};"
                 : "+f"(d[0]), "+f"(d[1]), "+f"(d[2]), "+f"(d[3])
                 : "r"(a[0]), "r"(a[1]), "r"(a[2]), "r"(a[3]), "r"(b[0]), "r"(b[1]));
}
__device__ __forceinline__ void cpa16(uint32_t saddr, const void* g) {
    asm volatile("cp.async.cg.shared.global [%0], [%1], 16;"
                 :: "r"(saddr), "l"(g) : "memory");
}
#define CPA_COMMIT() asm volatile("cp.async.commit_group;" ::: "memory")
#define CPA_WAIT(N)  asm volatile("cp.async.wait_group %0;" :: "n"(N) : "memory")
__device__ __forceinline__ void red2(float* addr, float v0, float v1) {
    asm volatile("red.global.add.v2.f32 [%0], {%1, %2};"
                 :: "l"(addr), "f"(v0), "f"(v1) : "memory");
}
__device__ __forceinline__ uint32_t swz(uint32_t bo) { return bo ^ ((bo >> 3) & 0x70); }
__device__ __forceinline__ void split_pair(float a, float b, uint32_t& hi, uint32_t& lo) {
    __nv_bfloat16 ah = __float2bfloat16(a), bh = __float2bfloat16(b);
    __nv_bfloat162 hp; hp.x = ah; hp.y = bh;
    __nv_bfloat162 lp;
    lp.x = __float2bfloat16(a - __bfloat162float(ah));
    lp.y = __float2bfloat16(b - __bfloat162float(bh));
    hi = *reinterpret_cast<uint32_t*>(&hp);
    lo = *reinterpret_cast<uint32_t*>(&lp);
}
__device__ __forceinline__ float recon(uint32_t packed, int half) {
    __nv_bfloat162 v = *reinterpret_cast<__nv_bfloat162*>(&packed);
    return half ? __bfloat162float(v.y) : __bfloat162float(v.x);
}

// ============================================================================
// gemm_k128: out[r,128] = Aplanes[r,128] @ Bplanes(k0, stride)  (+bias), fp32
// 3-pass bf16 split. 1 CTA/SM, all operands prefetched via cp.async.
// ============================================================================
#define GA_HI 0
#define GA_LO 32768
#define GB_HI 65536
#define GB_LO 98304
#define GBIAS 131072
#define SMEM_G 131584

__global__ __launch_bounds__(256, 1) void gemm_k128(
    const __nv_bfloat16* __restrict__ aHi, const __nv_bfloat16* __restrict__ aLo,
    const __nv_bfloat16* __restrict__ bHi, const __nv_bfloat16* __restrict__ bLo,
    int bStride, int bK0,
    const float* __restrict__ bias, float* __restrict__ out, int nRows)
{
    extern __shared__ char smp[];
    const uint32_t sb = smem_u32(smp);
    const int tid = threadIdx.x;
    const int wid = tid >> 5, lane = tid & 31;
    const int mwarp = wid & 3, nwarp = wid >> 2;
    const int blockRow = blockIdx.x * 128;

    float* bs = (float*)(smp + GBIAS);
    if (tid < 128) bs[tid] = bias ? bias[tid] : 0.f;

#pragma unroll
    for (int p = 0; p < 8; p++) {
        int idx = tid + 256 * p;
        int row = idx >> 4, q = idx & 15;
        int c2 = q >> 3, qq = q & 7;
        int rc = min(blockRow + row, nRows - 1);
        size_t ga = (size_t)rc * 128 + q * 8;
        size_t gb = (size_t)row * bStride + bK0 + q * 8;
        uint32_t sw = (uint32_t)(c2 * 16384) + swz((uint32_t)(row * 128 + qq * 16));
        cpa16(sb + GA_HI + sw, aHi + ga);
        cpa16(sb + GA_LO + sw, aLo + ga);
        cpa16(sb + GB_HI + sw, bHi + gb);
        cpa16(sb + GB_LO + sw, bLo + gb);
    }
    CPA_COMMIT();

    const int lrow = lane & 7, lg = lane >> 3;
    const uint32_t xm = (uint32_t)lrow << 4;
    const int a_row0 = mwarp * 32 + lrow + 8 * (lg & 1);
    const int a_kx = lg >> 1;
    const int b_row0 = nwarp * 64 + lrow + 8 * (lg >> 1);
    const int b_kx = lg & 1;

    float c[2][8][4];
#pragma unroll
    for (int mt = 0; mt < 2; mt++)
#pragma unroll
        for (int i = 0; i < 8; i++)
#pragma unroll
            for (int j = 0; j < 4; j++) c[mt][i][j] = 0.f;

    CPA_WAIT(0);
    __syncthreads();

#pragma unroll
    for (int c2 = 0; c2 < 2; c2++) {
        const uint32_t abH = sb + GA_HI + c2 * 16384;
        const uint32_t abL = sb + GA_LO + c2 * 16384;
        const uint32_t wbH = sb + GB_HI + c2 * 16384;
        const uint32_t wbL = sb + GB_LO + c2 * 16384;
#pragma unroll
        for (int ks = 0; ks < 4; ks++) {
            const uint32_t kcA = (uint32_t)((ks * 2 + a_kx) * 16) ^ xm;
            const uint32_t kcB = (uint32_t)((ks * 2 + b_kx) * 16) ^ xm;
            uint32_t ah[2][4], al[2][4];
#pragma unroll
            for (int mt = 0; mt < 2; mt++) {
                uint32_t ro = (uint32_t)((a_row0 + mt * 16) * 128);
                ldsm4(abH + ro + kcA, ah[mt]);
                ldsm4(abL + ro + kcA, al[mt]);
            }
#pragma unroll
            for (int g = 0; g < 4; g++) {
                uint32_t bh[4], bl[4];
                uint32_t ro = (uint32_t)((b_row0 + g * 16) * 128);
                ldsm4(wbH + ro + kcB, bh);
                ldsm4(wbL + ro + kcB, bl);
#pragma unroll
                for (int mt = 0; mt < 2; mt++)
#pragma unroll
                    for (int hf = 0; hf < 2; hf++) {
                        float* cc = c[mt][g * 2 + hf];
                        mma_bf16(cc, ah[mt], &bh[hf * 2]);
                        mma_bf16(cc, ah[mt], &bl[hf * 2]);
                        mma_bf16(cc, al[mt], &bh[hf * 2]);
                    }
            }
        }
    }

#pragma unroll
    for (int mt = 0; mt < 2; mt++)
#pragma unroll
        for (int e = 0; e < 2; e++) {
            int row = mwarp * 32 + mt * 16 + (lane >> 2) + 8 * e;
            int gr = blockRow + row;
            if (gr >= nRows) continue;
#pragma unroll
            for (int idx = 0; idx < 8; idx++) {
                int col = nwarp * 64 + (idx >> 1) * 16 + (idx & 1) * 8 + 2 * (lane & 3);
                float2 o;
                o.x = c[mt][idx][2 * e] + bs[col];
                o.y = c[mt][idx][2 * e + 1] + bs[col + 1];
                *(float2*)&out[(size_t)gr * 128 + col] = o;
            }
        }
}

// ============================================================================
// edge_mlp: hid = relu(Y1[iA] + Y2[iB] + Ye[r]); out = LN(relu(hid@W2+b2))
//           [+res] -> planes | red2-scatter into outF[iA[r]]
// 2 CTAs/SM; W2 chunk-streamed through one 32KB buffer.
// ============================================================================
#define E_H_HI 0
#define E_H_LO 32768
#define E_W2   65536
#define E_IDX  98304
#define E_B2   99328
#define E_G    99840
#define E_BE   100352
#define E_LN   100864
#define SMEM_E 103424

template <bool ATOMIC>
__global__ __launch_bounds__(256, 2) void edge_mlp(
    const float* __restrict__ Y1, const float* __restrict__ Y2,
    const float* __restrict__ Ye,
    const int* __restrict__ idxA, const int* __restrict__ idxB,
    const __nv_bfloat16* __restrict__ W2hi, const __nv_bfloat16* __restrict__ W2lo,
    const float* __restrict__ B2, const float* __restrict__ G,
    const float* __restrict__ BE,
    const __nv_bfloat16* __restrict__ resHi, const __nv_bfloat16* __restrict__ resLo,
    __nv_bfloat16* __restrict__ outHi, __nv_bfloat16* __restrict__ outLo,
    float* __restrict__ outF, int nRows)
{
    extern __shared__ char smp[];
    const uint32_t sb = smem_u32(smp);
    const int tid = threadIdx.x;
    const int wid = tid >> 5, lane = tid & 31;
    const int mwarp = wid & 3, nwarp = wid >> 2;
    const int blockRow = blockIdx.x * 128;

    int* idxs = (int*)(smp + E_IDX);
    float* b2s = (float*)(smp + E_B2);
    float* Gs  = (float*)(smp + E_G);
    float* BEs = (float*)(smp + E_BE);
    float* lnb = (float*)(smp + E_LN);

    if (tid < 128) {
        idxs[tid] = idxA[min(blockRow + tid, nRows - 1)];
        b2s[tid] = B2[tid]; Gs[tid] = G[tid]; BEs[tid] = BE[tid];
    } else {
        idxs[tid] = idxB[min(blockRow + tid - 128, nRows - 1)];
    }
    __syncthreads();

    // prefetch W2 chunk 0
#pragma unroll
    for (int p = 0; p < 4; p++) {
        int idx = tid + 256 * p;
        int row = idx >> 3, qq = idx & 7;
        size_t go = (size_t)row * 128 + qq * 8;
        uint32_t sw = swz((uint32_t)(row * 128 + qq * 16));
        cpa16(sb + E_W2 + sw, W2hi + go);
        cpa16(sb + E_W2 + 16384 + sw, W2lo + go);
    }
    CPA_COMMIT();

    // fill hidden: relu(Y1[iA] + Y2[iB] + Ye[row]) -> split -> H planes
#pragma unroll 4
    for (int p = 0; p < 16; p++) {
        int idx = tid + 256 * p;
        int row = idx >> 5, qf = idx & 31;
        int col = qf * 4;
        int gr = min(blockRow + row, nRows - 1);
        int riA = idxs[row], riB = idxs[128 + row];
        float4 a = *(const float4*)&Y1[(size_t)riA * 128 + col];
        float4 b = *(const float4*)&Y2[(size_t)riB * 128 + col];
        float4 e4 = *(const float4*)&Ye[(size_t)gr * 128 + col];
        float v0 = fmaxf(a.x + b.x + e4.x, 0.f);
        float v1 = fmaxf(a.y + b.y + e4.y, 0.f);
        float v2 = fmaxf(a.z + b.z + e4.z, 0.f);
        float v3 = fmaxf(a.w + b.w + e4.w, 0.f);
        uint32_t h0, h1, l0, l1;
        split_pair(v0, v1, h0, l0);
        split_pair(v2, v3, h1, l1);
        uint32_t off = (uint32_t)((col >> 6) * 16384) +
                       swz((uint32_t)(row * 128 + (col & 63) * 2));
        *(uint2*)(smp + E_H_HI + off) = make_uint2(h0, h1);
        *(uint2*)(smp + E_H_LO + off) = make_uint2(l0, l1);
    }

    const int lrow = lane & 7, lg = lane >> 3;
    const uint32_t xm = (uint32_t)lrow << 4;
    const int a_row0 = mwarp * 32 + lrow + 8 * (lg & 1);
    const int a_kx = lg >> 1;
    const int b_row0 = nwarp * 64 + lrow + 8 * (lg >> 1);
    const int b_kx = lg & 1;

    float c[2][8][4];
#pragma unroll
    for (int mt = 0; mt < 2; mt++)
#pragma unroll
        for (int i = 0; i < 8; i++)
#pragma unroll
            for (int j = 0; j < 4; j++) c[mt][i][j] = 0.f;

    for (int c2 = 0; c2 < 2; c2++) {
        CPA_WAIT(0);
        __syncthreads();
        const uint32_t abH = sb + E_H_HI + c2 * 16384;
        const uint32_t abL = sb + E_H_LO + c2 * 16384;
#pragma unroll
        for (int ks = 0; ks < 4; ks++) {
            const uint32_t kcA = (uint32_t)((ks * 2 + a_kx) * 16) ^ xm;
            const uint32_t kcB = (uint32_t)((ks * 2 + b_kx) * 16) ^ xm;
            uint32_t ah[2][4], al[2][4];
#pragma unroll
            for (int mt = 0; mt < 2; mt++) {
                uint32_t ro = (uint32_t)((a_row0 + mt * 16) * 128);
                ldsm4(abH + ro + kcA, ah[mt]);
                ldsm4(abL + ro + kcA, al[mt]);
            }
#pragma unroll
            for (int g = 0; g < 4; g++) {
                uint32_t bh[4], bl[4];
                uint32_t ro = (uint32_t)((b_row0 + g * 16) * 128);
                ldsm4(sb + E_W2 + ro + kcB, bh);
                ldsm4(sb + E_W2 + 16384 + ro + kcB, bl);
#pragma unroll
                for (int mt = 0; mt < 2; mt++)
#pragma unroll
                    for (int hf = 0; hf < 2; hf++) {
                        float* cc = c[mt][g * 2 + hf];
                        mma_bf16(cc, ah[mt], &bh[hf * 2]);
                        mma_bf16(cc, ah[mt], &bl[hf * 2]);
                        mma_bf16(cc, al[mt], &bh[hf * 2]);
                    }
            }
        }
        if (c2 == 0) {
            __syncthreads();  // all reads of W2 buf done before refill
#pragma unroll
            for (int p = 0; p < 4; p++) {
                int idx = tid + 256 * p;
                int row = idx >> 3, qq = idx & 7;
                size_t go = (size_t)row * 128 + 64 + qq * 8;
                uint32_t sw = swz((uint32_t)(row * 128 + qq * 16));
                cpa16(sb + E_W2 + sw, W2hi + go);
                cpa16(sb + E_W2 + 16384 + sw, W2lo + go);
            }
            CPA_COMMIT();
        }
    }

    // bias2 + ReLU
#pragma unroll
    for (int mt = 0; mt < 2; mt++)
#pragma unroll
        for (int idx = 0; idx < 8; idx++) {
            int col = nwarp * 64 + (idx >> 1) * 16 + (idx & 1) * 8 + 2 * (lane & 3);
#pragma unroll
            for (int j = 0; j < 4; j++)
                c[mt][idx][j] = fmaxf(c[mt][idx][j] + b2s[col + (j & 1)], 0.f);
        }

    // LayerNorm
#pragma unroll
    for (int mt = 0; mt < 2; mt++)
#pragma unroll
        for (int e = 0; e < 2; e++) {
            float s = 0.f;
#pragma unroll
            for (int idx = 0; idx < 8; idx++)
                s += c[mt][idx][2 * e] + c[mt][idx][2 * e + 1];
            s += __shfl_xor_sync(0xffffffffu, s, 1);
            s += __shfl_xor_sync(0xffffffffu, s, 2);
            if ((lane & 3) == 0) {
                int row = mwarp * 32 + mt * 16 + (lane >> 2) + 8 * e;
                lnb[row * 2 + nwarp] = s;
            }
        }
    __syncthreads();
    float mu[2][2], rs[2][2];
#pragma unroll
    for (int mt = 0; mt < 2; mt++)
#pragma unroll
        for (int e = 0; e < 2; e++) {
            int row = mwarp * 32 + mt * 16 + (lane >> 2) + 8 * e;
            mu[mt][e] = (lnb[row * 2] + lnb[row * 2 + 1]) * (1.0f / 128.0f);
            float sq = 0.f;
#pragma unroll
            for (int idx = 0; idx < 8; idx++) {
                float d0 = c[mt][idx][2 * e] - mu[mt][e];
                float d1 = c[mt][idx][2 * e + 1] - mu[mt][e];
                sq = fmaf(d0, d0, sq);
                sq = fmaf(d1, d1, sq);
            }
            sq += __shfl_xor_sync(0xffffffffu, sq, 1);
            sq += __shfl_xor_sync(0xffffffffu, sq, 2);
            if ((lane & 3) == 0) lnb[256 + row * 2 + nwarp] = sq;
        }
    __syncthreads();
#pragma unroll
    for (int mt = 0; mt < 2; mt++)
#pragma unroll
        for (int e = 0; e < 2; e++) {
            int row = mwarp * 32 + mt * 16 + (lane >> 2) + 8 * e;
            rs[mt][e] = rsqrtf((lnb[256 + row * 2] + lnb[256 + row * 2 + 1]) *
                                   (1.0f / 128.0f) + EPSV);
        }

    // output
#pragma unroll
    for (int mt = 0; mt < 2; mt++)
#pragma unroll
        for (int e = 0; e < 2; e++) {
            int row = mwarp * 32 + mt * 16 + (lane >> 2) + 8 * e;
            int gr = blockRow + row;
            if (gr >= nRows) continue;
            float m = mu[mt][e], q = rs[mt][e];
            if constexpr (ATOMIC) {
                const int drow = idxs[row];
                float* op = outF + (size_t)drow * LAT;
#pragma unroll
                for (int idx = 0; idx < 8; idx++) {
                    int col = nwarp * 64 + (idx >> 1) * 16 + (idx & 1) * 8 + 2 * (lane & 3);
                    float v0 = (c[mt][idx][2 * e]     - m) * q * Gs[col]     + BEs[col];
                    float v1 = (c[mt][idx][2 * e + 1] - m) * q * Gs[col + 1] + BEs[col + 1];
                    red2(&op[col], v0, v1);
                }
            } else {
#pragma unroll
                for (int idx = 0; idx < 8; idx++) {
                    int col = nwarp * 64 + (idx >> 1) * 16 + (idx & 1) * 8 + 2 * (lane & 3);
                    float v0 = (c[mt][idx][2 * e]     - m) * q * Gs[col]     + BEs[col];
                    float v1 = (c[mt][idx][2 * e + 1] - m) * q * Gs[col + 1] + BEs[col + 1];
                    uint32_t rh = *(const uint32_t*)&resHi[(size_t)gr * LAT + col];
                    uint32_t rl = *(const uint32_t*)&resLo[(size_t)gr * LAT + col];
                    v0 += recon(rh, 0) + recon(rl, 0);
                    v1 += recon(rh, 1) + recon(rl, 1);
                    uint32_t hi, lo;
                    split_pair(v0, v1, hi, lo);
                    *(uint32_t*)&outHi[(size_t)gr * LAT + col] = hi;
                    *(uint32_t*)&outLo[(size_t)gr * LAT + col] = lo;
                }
            }
        }
}

// ============================================================================
// gnn_mma (kept for encoders GMODE 0 and node update GMODE 2) — round-7 code
// ============================================================================
#define OFF_BUF(b) ((b) * 65536)
#define OFF_H_HI   0
#define OFF_H_LO   32768
#define OFF_W2(c)  (65536 + (c) * 32768)
#define OFF_IDX    131072
#define OFF_B1     132096
#define OFF_B2     132608
#define OFF_G      133120
#define OFF_BE     133632
#define OFF_LN     134144
#define OFF_W1RAW  136192
#define SMEM_DYN   138240

template <int KTOT, int GMODE, bool ATOMIC>
__global__ __launch_bounds__(256, 1) void gnn_mma(
    const float* __restrict__ raw, const float* __restrict__ W1raw, int kreal,
    const float* __restrict__ aggF,
    const __nv_bfloat16* __restrict__ hHi, const __nv_bfloat16* __restrict__ hLo,
    const __nv_bfloat16* __restrict__ eHi, const __nv_bfloat16* __restrict__ eLo,
    const int* __restrict__ idxA, const int* __restrict__ idxB,
    const __nv_bfloat16* __restrict__ W1hi, const __nv_bfloat16* __restrict__ W1lo,
    const float* __restrict__ B1,
    const __nv_bfloat16* __restrict__ W2hi, const __nv_bfloat16* __restrict__ W2lo,
    const float* __restrict__ B2,
    const float* __restrict__ G, const float* __restrict__ BE,
    const __nv_bfloat16* __restrict__ resHi, const __nv_bfloat16* __restrict__ resLo,
    __nv_bfloat16* __restrict__ outHi, __nv_bfloat16* __restrict__ outLo,
    float* __restrict__ outF, const int* __restrict__ scatIdx, int nRows)
{
    extern __shared__ char smp[];
    const uint32_t sb = smem_u32(smp);

    const int tid = threadIdx.x;
    const int wid = tid >> 5, lane = tid & 31;
    const int mwarp = wid & 3, nwarp = wid >> 2;
    const int blockRow = blockIdx.x * 128;

    int* idxs = (int*)(smp + OFF_IDX);
    float* b1s = (float*)(smp + OFF_B1);
    float* b2s = (float*)(smp + OFF_B2);
    float* Gs  = (float*)(smp + OFF_G);
    float* BEs = (float*)(smp + OFF_BE);
    float* lnb = (float*)(smp + OFF_LN);
    float* w1r = (float*)(smp + OFF_W1RAW);

    if constexpr (GMODE == 1) {
        if (tid < 128) idxs[tid] = idxA[min(blockRow + tid, nRows - 1)];
        else idxs[tid] = idxB[min(blockRow + tid - 128, nRows - 1)];
    }
    if (tid < 128) {
        b1s[tid] = B1[tid]; b2s[tid] = B2[tid];
        Gs[tid] = G[tid];   BEs[tid] = BE[tid];
    }
    if constexpr (GMODE == 0) {
        for (int i = tid; i < kreal * 128; i += 256) w1r[i] = W1raw[i];
    }
    __syncthreads();

    const int lrow = lane & 7, lg = lane >> 3;
    const uint32_t xm = (uint32_t)lrow << 4;
    const int a_row0 = mwarp * 32 + lrow + 8 * (lg & 1);
    const int a_kx = lg >> 1;
    const int b_row0 = nwarp * 64 + lrow + 8 * (lg >> 1);
    const int b_kx = lg & 1;

    float c[2][8][4];
#pragma unroll
    for (int mt = 0; mt < 2; mt++)
#pragma unroll
        for (int i = 0; i < 8; i++)
#pragma unroll
            for (int j = 0; j < 4; j++) c[mt][i][j] = 0.f;

    auto fill = [&](int ch) {
        const uint32_t bbase = sb + OFF_BUF(ch & 1);
        char* bptr = smp + OFF_BUF(ch & 1);
        if ((GMODE == 2) && (ch < 2)) {
            const int koff = ch * 64;
#pragma unroll
            for (int p = 0; p < 8; p++) {
                int idx = tid + 256 * p;
                int row = idx >> 4, f4 = idx & 15;
                int ri = min(blockRow + row, nRows - 1);
                float4 v = *(const float4*)&aggF[(size_t)ri * LAT + koff + f4 * 4];
                uint32_t h0, h1, l0, l1;
                split_pair(v.x, v.y, h0, l0);
                split_pair(v.z, v.w, h1, l1);
                uint32_t sw = swz((uint32_t)(row * 128 + f4 * 8));
                *(uint2*)(bptr + sw) = make_uint2(h0, h1);
                *(uint2*)(bptr + 16384 + sw) = make_uint2(l0, l1);
            }
        } else {
            const __nv_bfloat16 *pHi, *pLo;
            int koff, ibase = 0;
            bool useIdx = false;
            if constexpr (GMODE == 1) {
                int sel = ch >> 1;
                koff = (ch & 1) * 64;
                if (sel == 2) { pHi = eHi; pLo = eLo; }
                else { pHi = hHi; pLo = hLo; useIdx = true; ibase = sel * 128; }
            } else {
                pHi = hHi; pLo = hLo; koff = (ch - 2) * 64;
            }
#pragma unroll
            for (int p = 0; p < 4; p++) {
                int idx = tid + 256 * p;
                int row = idx >> 3, q = idx & 7;
                int ri = useIdx ? idxs[ibase + row] : min(blockRow + row, nRows - 1);
                size_t go = (size_t)ri * LAT + koff + q * 8;
                uint32_t sw = swz((uint32_t)(row * 128 + q * 16));
                cpa16(bbase + sw, pHi + go);
                cpa16(bbase + 16384 + sw, pLo + go);
            }
        }
#pragma unroll
        for (int p = 0; p < 4; p++) {
            int idx = tid + 256 * p;
            int row = idx >> 3, q = idx & 7;
            const size_t go = (size_t)row * KTOT + ch * 64 + q * 8;
            uint32_t sw = swz((uint32_t)(row * 128 + q * 16));
            cpa16(bbase + 32768 + sw, W1hi + go);
            cpa16(bbase + 49152 + sw, W1lo + go);
        }
    };
    auto fillW2 = [&]() {
#pragma unroll
        for (int p = 0; p < 8; p++) {
            int idx = tid + 256 * p;
            int row = idx >> 4, q = idx & 15;
            int c2 = q >> 3, qq = q & 7;
            size_t go = (size_t)row * 128 + c2 * 64 + qq * 8;
            uint32_t sw = swz((uint32_t)(row * 128 + qq * 16));
            cpa16(sb + OFF_W2(c2) + sw, W2hi + go);
            cpa16(sb + OFF_W2(c2) + 16384 + sw, W2lo + go);
        }
    };

    if constexpr (KTOT > 16) {
        constexpr int NC = KTOT / 64;
        fill(0); CPA_COMMIT();
        fill(1); CPA_COMMIT();
        for (int ch = 0; ch < NC; ch++) {
            if (ch < NC - 1) CPA_WAIT(1);
            else CPA_WAIT(0);
            __syncthreads();
            const uint32_t bbase = sb + OFF_BUF(ch & 1);
#pragma unroll
            for (int ks = 0; ks < 4; ks++) {
                const uint32_t kcA = (uint32_t)((ks * 2 + a_kx) * 16) ^ xm;
                const uint32_t kcB = (uint32_t)((ks * 2 + b_kx) * 16) ^ xm;
                uint32_t ah[2][4], al[2][4];
#pragma unroll
                for (int mt = 0; mt < 2; mt++) {
                    uint32_t ro = (uint32_t)((a_row0 + mt * 16) * 128);
                    ldsm4(bbase + ro + kcA, ah[mt]);
                    ldsm4(bbase + 16384 + ro + kcA, al[mt]);
                }
#pragma unroll
                for (int g = 0; g < 4; g++) {
                    uint32_t bh[4], bl[4];
                    uint32_t ro = (uint32_t)((b_row0 + g * 16) * 128);
                    ldsm4(bbase + 32768 + ro + kcB, bh);
                    ldsm4(bbase + 49152 + ro + kcB, bl);
#pragma unroll
                    for (int mt = 0; mt < 2; mt++)
#pragma unroll
                        for (int hf = 0; hf < 2; hf++) {
                            float* cc = c[mt][g * 2 + hf];
                            mma_bf16(cc, ah[mt], &bh[hf * 2]);
                            mma_bf16(cc, ah[mt], &bl[hf * 2]);
                            mma_bf16(cc, al[mt], &bh[hf * 2]);
                        }
                }
            }
            __syncthreads();
            if (ch + 2 < NC) { fill(ch + 2); CPA_COMMIT(); }
        }
        fillW2();
        CPA_COMMIT();
#pragma unroll
        for (int mt = 0; mt < 2; mt++)
#pragma unroll
            for (int idx = 0; idx < 8; idx++)
#pragma unroll
                for (int e = 0; e < 2; e++) {
                    int row = mwarp * 32 + mt * 16 + (lane >> 2) + 8 * e;
                    int col = nwarp * 64 + (idx >> 1) * 16 + (idx & 1) * 8 + 2 * (lane & 3);
                    float v0 = fmaxf(c[mt][idx][2 * e] + b1s[col], 0.f);
                    float v1 = fmaxf(c[mt][idx][2 * e + 1] + b1s[col + 1], 0.f);
                    uint32_t hi, lo;
                    split_pair(v0, v1, hi, lo);
                    uint32_t off = (uint32_t)(nwarp * 16384 + row * 128 +
                                              (((col & 63) * 2) ^ ((row & 7) << 4)));
                    *(uint32_t*)(smp + OFF_H_HI + off) = hi;
                    *(uint32_t*)(smp + OFF_H_LO + off) = lo;
                }
#pragma unroll
        for (int mt = 0; mt < 2; mt++)
#pragma unroll
            for (int i = 0; i < 8; i++)
#pragma unroll
                for (int j = 0; j < 4; j++) c[mt][i][j] = 0.f;
        CPA_WAIT(0);
        __syncthreads();
    } else {
        fillW2();
        CPA_COMMIT();
#pragma unroll
        for (int mt = 0; mt < 2; mt++)
#pragma unroll
            for (int e = 0; e < 2; e++) {
                int row = mwarp * 32 + mt * 16 + (lane >> 2) + 8 * e;
                int grc = min(blockRow + row, nRows - 1);
                float xv[4];
#pragma unroll
                for (int k = 0; k < 4; k++)
                    xv[k] = (k < kreal) ? raw[(size_t)grc * kreal + k] : 0.f;
#pragma unroll
                for (int idx = 0; idx < 8; idx++) {
                    int col = nwarp * 64 + (idx >> 1) * 16 + (idx & 1) * 8 + 2 * (lane & 3);
                    float v0 = b1s[col], v1 = b1s[col + 1];
                    for (int k = 0; k < kreal; k++) {
                        v0 = fmaf(xv[k], w1r[k * 128 + col], v0);
                        v1 = fmaf(xv[k], w1r[k * 128 + col + 1], v1);
                    }
                    v0 = fmaxf(v0, 0.f); v1 = fmaxf(v1, 0.f);
                    uint32_t hi, lo;
                    split_pair(v0, v1, hi, lo);
                    uint32_t off = (uint32_t)(nwarp * 16384 + row * 128 +
                                              (((col & 63) * 2) ^ ((row & 7) << 4)));
                    *(uint32_t*)(smp + OFF_H_HI + off) = hi;
                    *(uint32_t*)(smp + OFF_H_LO + off) = lo;
                }
            }
        CPA_WAIT(0);
        __syncthreads();
    }

#pragma unroll
    for (int c2 = 0; c2 < 2; c2++) {
        const uint32_t abH = sb + OFF_H_HI + c2 * 16384;
        const uint32_t abL = sb + OFF_H_LO + c2 * 16384;
        const uint32_t wb = sb + OFF_W2(c2);
#pragma unroll
        for (int ks = 0; ks < 4; ks++) {
            const uint32_t kcA = (uint32_t)((ks * 2 + a_kx) * 16) ^ xm;
            const uint32_t kcB = (uint32_t)((ks * 2 + b_kx) * 16) ^ xm;
            uint32_t ah[2][4], al[2][4];
#pragma unroll
            for (int mt = 0; mt < 2; mt++) {
                uint32_t ro = (uint32_t)((a_row0 + mt * 16) * 128);
                ldsm4(abH + ro + kcA, ah[mt]);
                ldsm4(abL + ro + kcA, al[mt]);
            }
#pragma unroll
            for (int g = 0; g < 4; g++) {
                uint32_t bh[4], bl[4];
                uint32_t ro = (uint32_t)((b_row0 + g * 16) * 128);
                ldsm4(wb + ro + kcB, bh);
                ldsm4(wb + 16384 + ro + kcB, bl);
#pragma unroll
                for (int mt = 0; mt < 2; mt++)
#pragma unroll
                    for (int hf = 0; hf < 2; hf++) {
                        float* cc = c[mt][g * 2 + hf];
                        mma_bf16(cc, ah[mt], &bh[hf * 2]);
                        mma_bf16(cc, ah[mt], &bl[hf * 2]);
                        mma_bf16(cc, al[mt], &bh[hf * 2]);
                    }
            }
        }
    }

#pragma unroll
    for (int mt = 0; mt < 2; mt++)
#pragma unroll
        for (int idx = 0; idx < 8; idx++) {
            int col = nwarp * 64 + (idx >> 1) * 16 + (idx & 1) * 8 + 2 * (lane & 3);
#pragma unroll
            for (int j = 0; j < 4; j++)
                c[mt][idx][j] = fmaxf(c[mt][idx][j] + b2s[col + (j & 1)], 0.f);
        }

#pragma unroll
    for (int mt = 0; mt < 2; mt++)
#pragma unroll
        for (int e = 0; e < 2; e++) {
            float s = 0.f;
#pragma unroll
            for (int idx = 0; idx < 8; idx++)
                s += c[mt][idx][2 * e] + c[mt][idx][2 * e + 1];
            s += __shfl_xor_sync(0xffffffffu, s, 1);
            s += __shfl_xor_sync(0xffffffffu, s, 2);
            if ((lane & 3) == 0) {
                int row = mwarp * 32 + mt * 16 + (lane >> 2) + 8 * e;
                lnb[row * 2 + nwarp] = s;
            }
        }
    __syncthreads();
    float mu[2][2], rs[2][2];
#pragma unroll
    for (int mt = 0; mt < 2; mt++)
#pragma unroll
        for (int e = 0; e < 2; e++) {
            int row = mwarp * 32 + mt * 16 + (lane >> 2) + 8 * e;
            mu[mt][e] = (lnb[row * 2] + lnb[row * 2 + 1]) * (1.0f / 128.0f);
            float sq = 0.f;
#pragma unroll
            for (int idx = 0; idx < 8; idx++) {
                float d0 = c[mt][idx][2 * e] - mu[mt][e];
                float d1 = c[mt][idx][2 * e + 1] - mu[mt][e];
                sq = fmaf(d0, d0, sq);
                sq = fmaf(d1, d1, sq);
            }
            sq += __shfl_xor_sync(0xffffffffu, sq, 1);
            sq += __shfl_xor_sync(0xffffffffu, sq, 2);
            if ((lane & 3) == 0) lnb[256 + row * 2 + nwarp] = sq;
        }
    __syncthreads();
#pragma unroll
    for (int mt = 0; mt < 2; mt++)
#pragma unroll
        for (int e = 0; e < 2; e++) {
            int row = mwarp * 32 + mt * 16 + (lane >> 2) + 8 * e;
            rs[mt][e] = rsqrtf((lnb[256 + row * 2] + lnb[256 + row * 2 + 1]) *
                                   (1.0f / 128.0f) + EPSV);
        }

#pragma unroll
    for (int mt = 0; mt < 2; mt++)
#pragma unroll
        for (int e = 0; e < 2; e++) {
            int row = mwarp * 32 + mt * 16 + (lane >> 2) + 8 * e;
            int gr = blockRow + row;
            if (gr >= nRows) continue;
            float m = mu[mt][e], q = rs[mt][e];
            if constexpr (ATOMIC) {
                const int drow = scatIdx[gr];
                float* op = outF + (size_t)drow * LAT;
#pragma unroll
                for (int idx = 0; idx < 8; idx++) {
                    int col = nwarp * 64 + (idx >> 1) * 16 + (idx & 1) * 8 + 2 * (lane & 3);
                    float v0 = (c[mt][idx][2 * e]     - m) * q * Gs[col]     + BEs[col];
                    float v1 = (c[mt][idx][2 * e + 1] - m) * q * Gs[col + 1] + BEs[col + 1];
                    red2(&op[col], v0, v1);
                }
            } else {
#pragma unroll
                for (int idx = 0; idx < 8; idx++) {
                    int col = nwarp * 64 + (idx >> 1) * 16 + (idx & 1) * 8 + 2 * (lane & 3);
                    float v0 = (c[mt][idx][2 * e]     - m) * q * Gs[col]     + BEs[col];
                    float v1 = (c[mt][idx][2 * e + 1] - m) * q * Gs[col + 1] + BEs[col + 1];
                    if (resHi) {
                        uint32_t rh = *(const uint32_t*)&resHi[(size_t)gr * LAT + col];
                        uint32_t rl = *(const uint32_t*)&resLo[(size_t)gr * LAT + col];
                        v0 += recon(rh, 0) + recon(rl, 0);
                        v1 += recon(rh, 1) + recon(rl, 1);
                    }
                    uint32_t hi, lo;
                    split_pair(v0, v1, hi, lo);
                    *(uint32_t*)&outHi[(size_t)gr * LAT + col] = hi;
                    *(uint32_t*)&outLo[(size_t)gr * LAT + col] = lo;
                }
            }
        }
}

__global__ void prep_all(
    const float* __restrict__ s0, __nv_bfloat16* __restrict__ h0b, __nv_bfloat16* __restrict__ l0b,
    const float* __restrict__ s1, __nv_bfloat16* __restrict__ h1b, __nv_bfloat16* __restrict__ l1b,
    const float* __restrict__ s2, __nv_bfloat16* __restrict__ h2b, __nv_bfloat16* __restrict__ l2b,
    const float* __restrict__ s3, __nv_bfloat16* __restrict__ h3b, __nv_bfloat16* __restrict__ l3b,
    const float* __restrict__ s4, __nv_bfloat16* __restrict__ h4b, __nv_bfloat16* __restrict__ l4b,
    const float* __restrict__ s5, __nv_bfloat16* __restrict__ h5b, __nv_bfloat16* __restrict__ l5b)
{
    int i = blockIdx.x * blockDim.x + threadIdx.x;
    const float* W; __nv_bfloat16 *hi, *lo; int K, j;
    if (i < 49152)       { W = s0; hi = h0b; lo = l0b; K = 384; j = i; }
    else if (i < 65536)  { W = s1; hi = h1b; lo = l1b; K = 128; j = i - 49152; }
    else if (i < 98304)  { W = s2; hi = h2b; lo = l2b; K = 256; j = i - 65536; }
    else if (i < 114688) { W = s3; hi = h3b; lo = l3b; K = 128; j = i - 98304; }
    else if (i < 131072) { W = s4; hi = h4b; lo = l4b; K = 128; j = i - 114688; }
    else if (i < 147456) { W = s5; hi = h5b; lo = l5b; K = 128; j = i - 131072; }
    else return;
    int k = j >> 7, n = j & 127;
    float v = W[j];
    __nv_bfloat16 h = __float2bfloat16(v);
    hi[(size_t)n * K + k] = h;
    lo[(size_t)n * K + k] = __float2bfloat16(v - __bfloat162float(h));
}

__global__ __launch_bounds__(256) void decoder_kernel(
    const __nv_bfloat16* __restrict__ hHi, const __nv_bfloat16* __restrict__ hLo,
    const float* __restrict__ W1, const float* __restrict__ B1,
    const float* __restrict__ W2, const float* __restrict__ B2,
    float* __restrict__ out, int n)
{
    extern __shared__ float s[];
    float* W1s = s;
    float* hs = s + 128 * 128;
    int tid = threadIdx.x;
#pragma unroll
    for (int it = 0; it < 16; it++) {
        int f = tid + 256 * it;
        *(float4*)&W1s[f * 4] = *(const float4*)&W1[f * 4];
    }
    int warp = tid >> 5, lane = tid & 31;
    int row = blockIdx.x * 8 + warp;
    int rc = min(row, n - 1);
#pragma unroll
    for (int q = 0; q < 4; q++) {
        int cc = lane + 32 * q;
        hs[warp * 128 + cc] = __bfloat162float(hHi[(size_t)rc * LAT + cc]) +
                              __bfloat162float(hLo[(size_t)rc * LAT + cc]);
    }
    __syncthreads();

    float acc[4];
#pragma unroll
    for (int q = 0; q < 4; q++) acc[q] = B1[lane + 32 * q];
    for (int k = 0; k < 128; k++) {
        float hv = hs[warp * 128 + k];
#pragma unroll
        for (int q = 0; q < 4; q++)
            acc[q] = fmaf(hv, W1s[k * 128 + lane + 32 * q], acc[q]);
    }
#pragma unroll
    for (int q = 0; q < 4; q++) acc[q] = fmaxf(acc[q], 0.f);

    float o[3];
#pragma unroll
    for (int oo = 0; oo < 3; oo++) {
        float p = 0.f;
#pragma unroll
        for (int q = 0; q < 4; q++)
            p = fmaf(acc[q], W2[(size_t)(lane + 32 * q) * 3 + oo], p);
#pragma unroll
        for (int off = 16; off > 0; off >>= 1)
            p += __shfl_xor_sync(0xffffffffu, p, off);
        o[oo] = p;
    }
    if (lane == 0 && row < n) {
        out[(size_t)row * 3 + 0] = o[0] + B2[0];
        out[(size_t)row * 3 + 1] = o[1] + B2[1];
        out[(size_t)row * 3 + 2] = o[2] + B2[2];
    }
}

__global__ void zero_kernel(float4* __restrict__ p, int n4)
{
    int i = blockIdx.x * blockDim.x + threadIdx.x;
    if (i < n4) p[i] = make_float4(0.f, 0.f, 0.f, 0.f);
}

extern "C" void kernel_launch(void* const* d_in, const int* in_sizes, int n_in,
                              void* d_out, int out_size)
{
    (void)in_sizes; (void)n_in; (void)out_size;
    const float* x  = (const float*)d_in[0];
    const float* ea = (const float*)d_in[1];
    const int*   ei = (const int*)d_in[2];
    const int* src = ei;
    const int* dst = ei + NEDGES;

    const float* ne_w1 = (const float*)d_in[3];
    const float* ne_b1 = (const float*)d_in[4];
    const float* ne_w2 = (const float*)d_in[5];
    const float* ne_b2 = (const float*)d_in[6];
    const float* ne_g  = (const float*)d_in[7];
    const float* ne_be = (const float*)d_in[8];
    const float* ee_w1 = (const float*)d_in[9];
    const float* ee_b1 = (const float*)d_in[10];
    const float* ee_w2 = (const float*)d_in[11];
    const float* ee_b2 = (const float*)d_in[12];
    const float* ee_g  = (const float*)d_in[13];
    const float* ee_be = (const float*)d_in[14];
    const float* em_w1 = (const float*)d_in[15];
    const float* em_b1 = (const float*)d_in[16];
    const float* em_w2 = (const float*)d_in[17];
    const float* em_b2 = (const float*)d_in[18];
    const float* em_g  = (const float*)d_in[19];
    const float* em_be = (const float*)d_in[20];
    const float* nm_w1 = (const float*)d_in[21];
    const float* nm_b1 = (const float*)d_in[22];
    const float* nm_w2 = (const float*)d_in[23];
    const float* nm_b2 = (const float*)d_in[24];
    const float* nm_g  = (const float*)d_in[25];
    const float* nm_be = (const float*)d_in[26];
    const float* dw1   = (const float*)d_in[27];
    const float* db1   = (const float*)d_in[28];
    const float* dw2   = (const float*)d_in[29];
    const float* db2   = (const float*)d_in[30];

    float* fb = nullptr;
    cudaGetSymbolAddress((void**)&fb, g_fbuf);
    float* agg = fb;
    float* Y1 = fb + (size_t)NNODES * LAT;
    float* Y2 = fb + (size_t)2 * NNODES * LAT;
    float* Ye = fb + (size_t)3 * NNODES * LAT;

    __nv_bfloat16* hp = nullptr;
    cudaGetSymbolAddress((void**)&hp, g_hpl);
    __nv_bfloat16* ep = nullptr;
    cudaGetSymbolAddress((void**)&ep, g_epl);
    const size_t HS = (size_t)NNODES * LAT, ES = (size_t)NEDGES * LAT;
    __nv_bfloat16 *hH0 = hp, *hL0 = hp + HS, *hH1 = hp + 2 * HS, *hL1 = hp + 3 * HS;
    __nv_bfloat16 *eH0 = ep, *eL0 = ep + ES, *eH1 = ep + 2 * ES, *eL1 = ep + 3 * ES;

    __nv_bfloat16* pl = nullptr;
    cudaGetSymbolAddress((void**)&pl, g_planes);
    __nv_bfloat16* emW1h = pl;
    __nv_bfloat16* emW1l = pl + 49152;
    __nv_bfloat16* emW2h = pl + 98304;
    __nv_bfloat16* emW2l = pl + 114688;
    __nv_bfloat16* nmW1h = pl + 131072;
    __nv_bfloat16* nmW1l = pl + 163840;
    __nv_bfloat16* nmW2h = pl + 196608;
    __nv_bfloat16* nmW2l = pl + 212992;
    __nv_bfloat16* neW2h = pl + 229376;
    __nv_bfloat16* neW2l = pl + 245760;
    __nv_bfloat16* eeW2h = pl + 262144;
    __nv_bfloat16* eeW2l = pl + 278528;

    cudaFuncSetAttribute(gnn_mma<16, 0, false>,
                         cudaFuncAttributeMaxDynamicSharedMemorySize, SMEM_DYN);
    cudaFuncSetAttribute(gnn_mma<256, 2, false>,
                         cudaFuncAttributeMaxDynamicSharedMemorySize, SMEM_DYN);
    cudaFuncSetAttribute(edge_mlp<true>,
                         cudaFuncAttributeMaxDynamicSharedMemorySize, SMEM_E);
    cudaFuncSetAttribute(edge_mlp<false>,
                         cudaFuncAttributeMaxDynamicSharedMemorySize, SMEM_E);
    cudaFuncSetAttribute(gemm_k128,
                         cudaFuncAttributeMaxDynamicSharedMemorySize, SMEM_G);
    const int DSM = (128 * 128 + 8 * 128) * (int)sizeof(float);
    cudaFuncSetAttribute(decoder_kernel,
                         cudaFuncAttributeMaxDynamicSharedMemorySize, DSM);

    prep_all<<<(147456 + 255) / 256, 256>>>(
        em_w1, emW1h, emW1l, em_w2, emW2h, emW2l,
        nm_w1, nmW1h, nmW1l, nm_w2, nmW2h, nmW2l,
        ne_w2, neW2h, neW2l, ee_w2, eeW2h, eeW2l);

    dim3 blk(256);
    const int ntiles = (NNODES + 127) / 128;  // 391
    const int etiles = NEDGES / 128;          // 3125

    gnn_mma<16, 0, false><<<ntiles, blk, SMEM_DYN>>>(
        x, ne_w1, 3, nullptr, nullptr, nullptr, nullptr, nullptr, nullptr, nullptr,
        nullptr, nullptr, ne_b1, neW2h, neW2l, ne_b2, ne_g, ne_be,
        nullptr, nullptr, hH0, hL0, nullptr, nullptr, NNODES);
    gnn_mma<16, 0, false><<<etiles, blk, SMEM_DYN>>>(
        ea, ee_w1, 4, nullptr, nullptr, nullptr, nullptr, nullptr, nullptr, nullptr,
        nullptr, nullptr, ee_b1, eeW2h, eeW2l, ee_b2, ee_g, ee_be,
        nullptr, nullptr, eH0, eL0, nullptr, nullptr, NEDGES);

    __nv_bfloat16 *hcH = hH0, *hcL = hL0, *hnH = hH1, *hnL = hL1;
    __nv_bfloat16 *ecH = eH0, *ecL = eL0, *enH = eH1, *enL = eL1;
    for (int s = 0; s < 5; s++) {
        // shared layer-1 partial products
        gemm_k128<<<ntiles, blk, SMEM_G>>>(hcH, hcL, emW1h, emW1l, 384, 0,
                                           nullptr, Y1, NNODES);
        gemm_k128<<<ntiles, blk, SMEM_G>>>(hcH, hcL, emW1h, emW1l, 384, 128,
                                           nullptr, Y2, NNODES);
        gemm_k128<<<etiles, blk, SMEM_G>>>(ecH, ecL, emW1h, emW1l, 384, 256,
                                           em_b1, Ye, NEDGES);
        zero_kernel<<<(NNODES * LAT / 4 + 255) / 256, 256>>>((float4*)agg,
                                                             NNODES * LAT / 4);
        // messages -> scatter agg[dst]
        edge_mlp<true><<<etiles, blk, SMEM_E>>>(
            Y1, Y2, Ye, dst, src, emW2h, emW2l, em_b2, em_g, em_be,
            nullptr, nullptr, nullptr, nullptr, agg, NEDGES);
        // edge update (+res)
        edge_mlp<false><<<etiles, blk, SMEM_E>>>(
            Y1, Y2, Ye, src, dst, emW2h, emW2l, em_b2, em_g, em_be,
            ecH, ecL, enH, enL, nullptr, NEDGES);
        // node update
        gnn_mma<256, 2, false><<<ntiles, blk, SMEM_DYN>>>(
            nullptr, nullptr, 0, agg, hcH, hcL, nullptr, nullptr, nullptr, nullptr,
            nmW1h, nmW1l, nm_b1, nmW2h, nmW2l, nm_b2, nm_g, nm_be,
            hcH, hcL, hnH, hnL, nullptr, nullptr, NNODES);
        __nv_bfloat16* t;
        t = hcH; hcH = hnH; hnH = t;
        t = hcL; hcL = hnL; hnL = t;
        t = ecH; ecH = enH; enH = t;
        t = ecL; ecL = enL; enL = t;
    }

    decoder_kernel<<<(NNODES + 7) / 8, blk, DSM>>>(
        hcH, hcL, dw1, db1, dw2, db2, (float*)d_out, NNODES);
}

// round 9
// speedup vs baseline: 3.2167x; 1.0282x over previous
#include <cuda_runtime.h>
#include <cuda_bf16.h>
#include <cstdint>
#include <cstddef>

#define LAT 128
#define NNODES 50000
#define NEDGES 400000
#define EPSV 1e-5f

// fp32: agg | Y1 | Y2 | Ye
__device__ float g_fbuf[(size_t)(3 * NNODES + NEDGES) * LAT];
__device__ __align__(16) __nv_bfloat16 g_hpl[(size_t)4 * NNODES * LAT];
__device__ __align__(16) __nv_bfloat16 g_epl[(size_t)4 * NEDGES * LAT];
__device__ __align__(16) __nv_bfloat16 g_planes[294912];

__device__ __forceinline__ uint32_t smem_u32(const void* p) {
    uint32_t a;
    asm("{ .reg .u64 t; cvta.to.shared.u64 t, %1; cvt.u32.u64 %0, t; }" : "=r"(a) : "l"(p));
    return a;
}
__device__ __forceinline__ void ldsm4(uint32_t addr, uint32_t* r) {
    asm volatile("ldmatrix.sync.aligned.m8n8.x4.shared.b16 {%0,%1,%2,%3}, [%4];"
                 : "=r"(r[0]), "=r"(r[1]), "=r"(r[2]), "=r"(r[3]) : "r"(addr));
}
__device__ __forceinline__ void mma_bf16(float* d, const uint32_t* a, const uint32_t* b) {
    asm volatile("mma.sync.aligned.m16n8k16.row.col.f32.bf16.bf16.f32 "
                 "{%0,%1,%2,%3}, {%4,%5,%6,%7}, {%8,%9}, {%0,%1,%2,%3};"
                 : "+f"(d[0]), "+f"(d[1]), "+f"(d[2]), "+f"(d[3])
                 : "r"(a[0]), "r"(a[1]), "r"(a[2]), "r"(a[3]), "r"(b[0]), "r"(b[1]));
}
__device__ __forceinline__ void cpa16(uint32_t saddr, const void* g) {
    asm volatile("cp.async.cg.shared.global [%0], [%1], 16;"
                 :: "r"(saddr), "l"(g) : "memory");
}
#define CPA_COMMIT() asm volatile("cp.async.commit_group;" ::: "memory")
#define CPA_WAIT(N)  asm volatile("cp.async.wait_group %0;" :: "n"(N) : "memory")
__device__ __forceinline__ void red2(float* addr, float v0, float v1) {
    asm volatile("red.global.add.v2.f32 [%0], {%1, %2};"
                 :: "l"(addr), "f"(v0), "f"(v1) : "memory");
}
__device__ __forceinline__ uint32_t swz(uint32_t bo) { return bo ^ ((bo >> 3) & 0x70); }
__device__ __forceinline__ void split_pair(float a, float b, uint32_t& hi, uint32_t& lo) {
    __nv_bfloat16 ah = __float2bfloat16(a), bh = __float2bfloat16(b);
    __nv_bfloat162 hp; hp.x = ah; hp.y = bh;
    __nv_bfloat162 lp;
    lp.x = __float2bfloat16(a - __bfloat162float(ah));
    lp.y = __float2bfloat16(b - __bfloat162float(bh));
    hi = *reinterpret_cast<uint32_t*>(&hp);
    lo = *reinterpret_cast<uint32_t*>(&lp);
}
__device__ __forceinline__ float recon(uint32_t packed, int half) {
    __nv_bfloat162 v = *reinterpret_cast<__nv_bfloat162*>(&packed);
    return half ? __bfloat162float(v.y) : __bfloat162float(v.x);
}

// ============================================================================
// gemm_k128<TILES>: out[r,128] = A[r,128] @ B(k0,stride) (+bias), fp32.
// B loaded ONCE per CTA; A double-buffered across TILES row-tiles.
// ============================================================================
#define GB_HI  0
#define GB_LO  32768
#define GA(b)  (65536 + (b) * 65536)   /* hi at +0 (32KB: 2 k-chunks), lo at +32768 */
#define GBIAS  196608
#define SMEM_G 197120

template <int TILES>
__global__ __launch_bounds__(256, 1) void gemm_k128(
    const __nv_bfloat16* __restrict__ aHi, const __nv_bfloat16* __restrict__ aLo,
    const __nv_bfloat16* __restrict__ bHi, const __nv_bfloat16* __restrict__ bLo,
    int bStride, int bK0,
    const float* __restrict__ bias, float* __restrict__ out, int nRows)
{
    extern __shared__ char smp[];
    const uint32_t sb = smem_u32(smp);
    const int tid = threadIdx.x;
    const int wid = tid >> 5, lane = tid & 31;
    const int mwarp = wid & 3, nwarp = wid >> 2;
    const int base0 = blockIdx.x * (TILES * 128);

    float* bs = (float*)(smp + GBIAS);
    if (tid < 128) bs[tid] = bias ? bias[tid] : 0.f;

    // B fill (both k-chunks, hi+lo) — once per CTA
#pragma unroll
    for (int p = 0; p < 8; p++) {
        int idx = tid + 256 * p;
        int row = idx >> 4, q = idx & 15;
        int c2 = q >> 3, qq = q & 7;
        size_t gb = (size_t)row * bStride + bK0 + q * 8;
        uint32_t sw = (uint32_t)(c2 * 16384) + swz((uint32_t)(row * 128 + qq * 16));
        cpa16(sb + GB_HI + sw, bHi + gb);
        cpa16(sb + GB_LO + sw, bLo + gb);
    }
    auto fillA = [&](int t) {
        const uint32_t ab = sb + GA(t & 1);
#pragma unroll
        for (int p = 0; p < 8; p++) {
            int idx = tid + 256 * p;
            int row = idx >> 4, q = idx & 15;
            int c2 = q >> 3, qq = q & 7;
            int rc = min(base0 + t * 128 + row, nRows - 1);
            size_t ga = (size_t)rc * 128 + q * 8;
            uint32_t sw = (uint32_t)(c2 * 16384) + swz((uint32_t)(row * 128 + qq * 16));
            cpa16(ab + sw, aHi + ga);
            cpa16(ab + 32768 + sw, aLo + ga);
        }
    };
    fillA(0); CPA_COMMIT();     // group: B + A0
    fillA(1); CPA_COMMIT();     // group: A1

    const int lrow = lane & 7, lg = lane >> 3;
    const uint32_t xm = (uint32_t)lrow << 4;
    const int a_row0 = mwarp * 32 + lrow + 8 * (lg & 1);
    const int a_kx = lg >> 1;
    const int b_row0 = nwarp * 64 + lrow + 8 * (lg >> 1);
    const int b_kx = lg & 1;

    for (int t = 0; t < TILES; t++) {
        if (t < TILES - 1) CPA_WAIT(1);
        else CPA_WAIT(0);
        __syncthreads();

        float c[2][8][4];
#pragma unroll
        for (int mt = 0; mt < 2; mt++)
#pragma unroll
            for (int i = 0; i < 8; i++)
#pragma unroll
                for (int j = 0; j < 4; j++) c[mt][i][j] = 0.f;

        const uint32_t ab = sb + GA(t & 1);
#pragma unroll
        for (int c2 = 0; c2 < 2; c2++) {
            const uint32_t abH = ab + c2 * 16384;
            const uint32_t abL = ab + 32768 + c2 * 16384;
            const uint32_t wbH = sb + GB_HI + c2 * 16384;
            const uint32_t wbL = sb + GB_LO + c2 * 16384;
#pragma unroll
            for (int ks = 0; ks < 4; ks++) {
                const uint32_t kcA = (uint32_t)((ks * 2 + a_kx) * 16) ^ xm;
                const uint32_t kcB = (uint32_t)((ks * 2 + b_kx) * 16) ^ xm;
                uint32_t ah[2][4], al[2][4];
#pragma unroll
                for (int mt = 0; mt < 2; mt++) {
                    uint32_t ro = (uint32_t)((a_row0 + mt * 16) * 128);
                    ldsm4(abH + ro + kcA, ah[mt]);
                    ldsm4(abL + ro + kcA, al[mt]);
                }
#pragma unroll
                for (int g = 0; g < 4; g++) {
                    uint32_t bh[4], bl[4];
                    uint32_t ro = (uint32_t)((b_row0 + g * 16) * 128);
                    ldsm4(wbH + ro + kcB, bh);
                    ldsm4(wbL + ro + kcB, bl);
#pragma unroll
                    for (int mt = 0; mt < 2; mt++)
#pragma unroll
                        for (int hf = 0; hf < 2; hf++) {
                            float* cc = c[mt][g * 2 + hf];
                            mma_bf16(cc, ah[mt], &bh[hf * 2]);
                            mma_bf16(cc, ah[mt], &bl[hf * 2]);
                            mma_bf16(cc, al[mt], &bh[hf * 2]);
                        }
                }
            }
        }

#pragma unroll
        for (int mt = 0; mt < 2; mt++)
#pragma unroll
            for (int e = 0; e < 2; e++) {
                int row = mwarp * 32 + mt * 16 + (lane >> 2) + 8 * e;
                int gr = base0 + t * 128 + row;
                if (gr >= nRows) continue;
#pragma unroll
                for (int idx = 0; idx < 8; idx++) {
                    int col = nwarp * 64 + (idx >> 1) * 16 + (idx & 1) * 8 + 2 * (lane & 3);
                    float2 o;
                    o.x = c[mt][idx][2 * e] + bs[col];
                    o.y = c[mt][idx][2 * e + 1] + bs[col + 1];
                    *(float2*)&out[(size_t)gr * 128 + col] = o;
                }
            }

        __syncthreads();
        if (t + 2 < TILES) { fillA(t + 2); CPA_COMMIT(); }
    }
}

// ============================================================================
// edge_fused: per 128-edge tile, BOTH edge MLPs:
//  phase M: hid=relu(Y1[dst]+Y2[src]+Ye) -> LN(relu(hid@W2+b2)) -> red2 agg[dst]
//  phase E: hid=relu(Y1[src]+Y2[dst]+Ye) -> LN(...) + e  -> planes
// 2 CTAs/SM; W2 streamed through one 32KB buffer; Ye phase-E read hits L2.
// ============================================================================
#define E_H_HI 0
#define E_H_LO 32768
#define E_W2   65536
#define E_IDX  98304
#define E_B2   99328
#define E_G    99840
#define E_BE   100352
#define E_LN   100864
#define SMEM_E 103424

__global__ __launch_bounds__(256, 2) void edge_fused(
    const float* __restrict__ Y1, const float* __restrict__ Y2,
    const float* __restrict__ Ye,
    const int* __restrict__ dst, const int* __restrict__ src,
    const __nv_bfloat16* __restrict__ W2hi, const __nv_bfloat16* __restrict__ W2lo,
    const float* __restrict__ B2, const float* __restrict__ G,
    const float* __restrict__ BE,
    const __nv_bfloat16* __restrict__ resHi, const __nv_bfloat16* __restrict__ resLo,
    __nv_bfloat16* __restrict__ outHi, __nv_bfloat16* __restrict__ outLo,
    float* __restrict__ aggF, int nRows)
{
    extern __shared__ char smp[];
    const uint32_t sb = smem_u32(smp);
    const int tid = threadIdx.x;
    const int wid = tid >> 5, lane = tid & 31;
    const int mwarp = wid & 3, nwarp = wid >> 2;
    const int blockRow = blockIdx.x * 128;

    int* idxs = (int*)(smp + E_IDX);    // [0..127]=dst, [128..255]=src
    float* b2s = (float*)(smp + E_B2);
    float* Gs  = (float*)(smp + E_G);
    float* BEs = (float*)(smp + E_BE);
    float* lnb = (float*)(smp + E_LN);

    if (tid < 128) {
        idxs[tid] = dst[min(blockRow + tid, nRows - 1)];
        b2s[tid] = B2[tid]; Gs[tid] = G[tid]; BEs[tid] = BE[tid];
    } else {
        idxs[tid] = src[min(blockRow + tid - 128, nRows - 1)];
    }
    __syncthreads();

    auto fillW2 = [&](int chunk) {
#pragma unroll
        for (int p = 0; p < 4; p++) {
            int idx = tid + 256 * p;
            int row = idx >> 3, qq = idx & 7;
            size_t go = (size_t)row * 128 + chunk * 64 + qq * 8;
            uint32_t sw = swz((uint32_t)(row * 128 + qq * 16));
            cpa16(sb + E_W2 + sw, W2hi + go);
            cpa16(sb + E_W2 + 16384 + sw, W2lo + go);
        }
    };
    fillW2(0); CPA_COMMIT();

    const int lrow = lane & 7, lg = lane >> 3;
    const uint32_t xm = (uint32_t)lrow << 4;
    const int a_row0 = mwarp * 32 + lrow + 8 * (lg & 1);
    const int a_kx = lg >> 1;
    const int b_row0 = nwarp * 64 + lrow + 8 * (lg >> 1);
    const int b_kx = lg & 1;

    for (int ph = 0; ph < 2; ph++) {
        const bool MSG = (ph == 0);
        // ---- H fill: relu(Y1[riA] + Y2[riB] + Ye[r]) -> hi/lo planes ----
#pragma unroll 4
        for (int p = 0; p < 16; p++) {
            int idx = tid + 256 * p;
            int row = idx >> 5, qf = idx & 31;
            int col = qf * 4;
            int gr = min(blockRow + row, nRows - 1);
            int riA = MSG ? idxs[row] : idxs[128 + row];
            int riB = MSG ? idxs[128 + row] : idxs[row];
            float4 a = *(const float4*)&Y1[(size_t)riA * 128 + col];
            float4 b = *(const float4*)&Y2[(size_t)riB * 128 + col];
            float4 e4 = *(const float4*)&Ye[(size_t)gr * 128 + col];
            float v0 = fmaxf(a.x + b.x + e4.x, 0.f);
            float v1 = fmaxf(a.y + b.y + e4.y, 0.f);
            float v2 = fmaxf(a.z + b.z + e4.z, 0.f);
            float v3 = fmaxf(a.w + b.w + e4.w, 0.f);
            uint32_t h0, h1, l0, l1;
            split_pair(v0, v1, h0, l0);
            split_pair(v2, v3, h1, l1);
            uint32_t off = (uint32_t)((col >> 6) * 16384) +
                           swz((uint32_t)(row * 128 + (col & 63) * 2));
            *(uint2*)(smp + E_H_HI + off) = make_uint2(h0, h1);
            *(uint2*)(smp + E_H_LO + off) = make_uint2(l0, l1);
        }

        float c[2][8][4];
#pragma unroll
        for (int mt = 0; mt < 2; mt++)
#pragma unroll
            for (int i = 0; i < 8; i++)
#pragma unroll
                for (int j = 0; j < 4; j++) c[mt][i][j] = 0.f;

        for (int c2 = 0; c2 < 2; c2++) {
            CPA_WAIT(0);
            __syncthreads();
            const uint32_t abH = sb + E_H_HI + c2 * 16384;
            const uint32_t abL = sb + E_H_LO + c2 * 16384;
#pragma unroll
            for (int ks = 0; ks < 4; ks++) {
                const uint32_t kcA = (uint32_t)((ks * 2 + a_kx) * 16) ^ xm;
                const uint32_t kcB = (uint32_t)((ks * 2 + b_kx) * 16) ^ xm;
                uint32_t ah[2][4], al[2][4];
#pragma unroll
                for (int mt = 0; mt < 2; mt++) {
                    uint32_t ro = (uint32_t)((a_row0 + mt * 16) * 128);
                    ldsm4(abH + ro + kcA, ah[mt]);
                    ldsm4(abL + ro + kcA, al[mt]);
                }
#pragma unroll
                for (int g = 0; g < 4; g++) {
                    uint32_t bh[4], bl[4];
                    uint32_t ro = (uint32_t)((b_row0 + g * 16) * 128);
                    ldsm4(sb + E_W2 + ro + kcB, bh);
                    ldsm4(sb + E_W2 + 16384 + ro + kcB, bl);
#pragma unroll
                    for (int mt = 0; mt < 2; mt++)
#pragma unroll
                        for (int hf = 0; hf < 2; hf++) {
                            float* cc = c[mt][g * 2 + hf];
                            mma_bf16(cc, ah[mt], &bh[hf * 2]);
                            mma_bf16(cc, ah[mt], &bl[hf * 2]);
                            mma_bf16(cc, al[mt], &bh[hf * 2]);
                        }
                }
            }
            __syncthreads();   // all reads of W2 buf (and H for refill safety) done
            int nxt = (c2 == 0) ? 1 : (MSG ? 0 : -1);
            if (nxt >= 0) { fillW2(nxt); CPA_COMMIT(); }
        }

        // bias2 + ReLU
#pragma unroll
        for (int mt = 0; mt < 2; mt++)
#pragma unroll
            for (int idx = 0; idx < 8; idx++) {
                int col = nwarp * 64 + (idx >> 1) * 16 + (idx & 1) * 8 + 2 * (lane & 3);
#pragma unroll
                for (int j = 0; j < 4; j++)
                    c[mt][idx][j] = fmaxf(c[mt][idx][j] + b2s[col + (j & 1)], 0.f);
            }

        // LayerNorm
#pragma unroll
        for (int mt = 0; mt < 2; mt++)
#pragma unroll
            for (int e = 0; e < 2; e++) {
                float s = 0.f;
#pragma unroll
                for (int idx = 0; idx < 8; idx++)
                    s += c[mt][idx][2 * e] + c[mt][idx][2 * e + 1];
                s += __shfl_xor_sync(0xffffffffu, s, 1);
                s += __shfl_xor_sync(0xffffffffu, s, 2);
                if ((lane & 3) == 0) {
                    int row = mwarp * 32 + mt * 16 + (lane >> 2) + 8 * e;
                    lnb[row * 2 + nwarp] = s;
                }
            }
        __syncthreads();
        float mu[2][2], rs[2][2];
#pragma unroll
        for (int mt = 0; mt < 2; mt++)
#pragma unroll
            for (int e = 0; e < 2; e++) {
                int row = mwarp * 32 + mt * 16 + (lane >> 2) + 8 * e;
                mu[mt][e] = (lnb[row * 2] + lnb[row * 2 + 1]) * (1.0f / 128.0f);
                float sq = 0.f;
#pragma unroll
                for (int idx = 0; idx < 8; idx++) {
                    float d0 = c[mt][idx][2 * e] - mu[mt][e];
                    float d1 = c[mt][idx][2 * e + 1] - mu[mt][e];
                    sq = fmaf(d0, d0, sq);
                    sq = fmaf(d1, d1, sq);
                }
                sq += __shfl_xor_sync(0xffffffffu, sq, 1);
                sq += __shfl_xor_sync(0xffffffffu, sq, 2);
                if ((lane & 3) == 0) lnb[256 + row * 2 + nwarp] = sq;
            }
        __syncthreads();
#pragma unroll
        for (int mt = 0; mt < 2; mt++)
#pragma unroll
            for (int e = 0; e < 2; e++) {
                int row = mwarp * 32 + mt * 16 + (lane >> 2) + 8 * e;
                rs[mt][e] = rsqrtf((lnb[256 + row * 2] + lnb[256 + row * 2 + 1]) *
                                       (1.0f / 128.0f) + EPSV);
            }

        // output
#pragma unroll
        for (int mt = 0; mt < 2; mt++)
#pragma unroll
            for (int e = 0; e < 2; e++) {
                int row = mwarp * 32 + mt * 16 + (lane >> 2) + 8 * e;
                int gr = blockRow + row;
                if (gr >= nRows) continue;
                float m = mu[mt][e], q = rs[mt][e];
                if (MSG) {
                    const int drow = idxs[row];
                    float* op = aggF + (size_t)drow * LAT;
#pragma unroll
                    for (int idx = 0; idx < 8; idx++) {
                        int col = nwarp * 64 + (idx >> 1) * 16 + (idx & 1) * 8 + 2 * (lane & 3);
                        float v0 = (c[mt][idx][2 * e]     - m) * q * Gs[col]     + BEs[col];
                        float v1 = (c[mt][idx][2 * e + 1] - m) * q * Gs[col + 1] + BEs[col + 1];
                        red2(&op[col], v0, v1);
                    }
                } else {
#pragma unroll
                    for (int idx = 0; idx < 8; idx++) {
                        int col = nwarp * 64 + (idx >> 1) * 16 + (idx & 1) * 8 + 2 * (lane & 3);
                        float v0 = (c[mt][idx][2 * e]     - m) * q * Gs[col]     + BEs[col];
                        float v1 = (c[mt][idx][2 * e + 1] - m) * q * Gs[col + 1] + BEs[col + 1];
                        uint32_t rh = *(const uint32_t*)&resHi[(size_t)gr * LAT + col];
                        uint32_t rl = *(const uint32_t*)&resLo[(size_t)gr * LAT + col];
                        v0 += recon(rh, 0) + recon(rl, 0);
                        v1 += recon(rh, 1) + recon(rl, 1);
                        uint32_t hi, lo;
                        split_pair(v0, v1, hi, lo);
                        *(uint32_t*)&outHi[(size_t)gr * LAT + col] = hi;
                        *(uint32_t*)&outLo[(size_t)gr * LAT + col] = lo;
                    }
                }
            }
        __syncthreads();   // H/lnb safe to overwrite in next phase
    }
}

// ============================================================================
// gnn_mma (encoders GMODE 0, node update GMODE 2) — unchanged from round 7/8
// ============================================================================
#define OFF_BUF(b) ((b) * 65536)
#define OFF_H_HI   0
#define OFF_H_LO   32768
#define OFF_W2(c)  (65536 + (c) * 32768)
#define OFF_IDX    131072
#define OFF_B1     132096
#define OFF_B2     132608
#define OFF_G      133120
#define OFF_BE     133632
#define OFF_LN     134144
#define OFF_W1RAW  136192
#define SMEM_DYN   138240

template <int KTOT, int GMODE, bool ATOMIC>
__global__ __launch_bounds__(256, 1) void gnn_mma(
    const float* __restrict__ raw, const float* __restrict__ W1raw, int kreal,
    const float* __restrict__ aggF,
    const __nv_bfloat16* __restrict__ hHi, const __nv_bfloat16* __restrict__ hLo,
    const __nv_bfloat16* __restrict__ eHi, const __nv_bfloat16* __restrict__ eLo,
    const int* __restrict__ idxA, const int* __restrict__ idxB,
    const __nv_bfloat16* __restrict__ W1hi, const __nv_bfloat16* __restrict__ W1lo,
    const float* __restrict__ B1,
    const __nv_bfloat16* __restrict__ W2hi, const __nv_bfloat16* __restrict__ W2lo,
    const float* __restrict__ B2,
    const float* __restrict__ G, const float* __restrict__ BE,
    const __nv_bfloat16* __restrict__ resHi, const __nv_bfloat16* __restrict__ resLo,
    __nv_bfloat16* __restrict__ outHi, __nv_bfloat16* __restrict__ outLo,
    float* __restrict__ outF, const int* __restrict__ scatIdx, int nRows)
{
    extern __shared__ char smp[];
    const uint32_t sb = smem_u32(smp);

    const int tid = threadIdx.x;
    const int wid = tid >> 5, lane = tid & 31;
    const int mwarp = wid & 3, nwarp = wid >> 2;
    const int blockRow = blockIdx.x * 128;

    int* idxs = (int*)(smp + OFF_IDX);
    float* b1s = (float*)(smp + OFF_B1);
    float* b2s = (float*)(smp + OFF_B2);
    float* Gs  = (float*)(smp + OFF_G);
    float* BEs = (float*)(smp + OFF_BE);
    float* lnb = (float*)(smp + OFF_LN);
    float* w1r = (float*)(smp + OFF_W1RAW);

    if constexpr (GMODE == 1) {
        if (tid < 128) idxs[tid] = idxA[min(blockRow + tid, nRows - 1)];
        else idxs[tid] = idxB[min(blockRow + tid - 128, nRows - 1)];
    }
    if (tid < 128) {
        b1s[tid] = B1[tid]; b2s[tid] = B2[tid];
        Gs[tid] = G[tid];   BEs[tid] = BE[tid];
    }
    if constexpr (GMODE == 0) {
        for (int i = tid; i < kreal * 128; i += 256) w1r[i] = W1raw[i];
    }
    __syncthreads();

    const int lrow = lane & 7, lg = lane >> 3;
    const uint32_t xm = (uint32_t)lrow << 4;
    const int a_row0 = mwarp * 32 + lrow + 8 * (lg & 1);
    const int a_kx = lg >> 1;
    const int b_row0 = nwarp * 64 + lrow + 8 * (lg >> 1);
    const int b_kx = lg & 1;

    float c[2][8][4];
#pragma unroll
    for (int mt = 0; mt < 2; mt++)
#pragma unroll
        for (int i = 0; i < 8; i++)
#pragma unroll
            for (int j = 0; j < 4; j++) c[mt][i][j] = 0.f;

    auto fill = [&](int ch) {
        const uint32_t bbase = sb + OFF_BUF(ch & 1);
        char* bptr = smp + OFF_BUF(ch & 1);
        if ((GMODE == 2) && (ch < 2)) {
            const int koff = ch * 64;
#pragma unroll
            for (int p = 0; p < 8; p++) {
                int idx = tid + 256 * p;
                int row = idx >> 4, f4 = idx & 15;
                int ri = min(blockRow + row, nRows - 1);
                float4 v = *(const float4*)&aggF[(size_t)ri * LAT + koff + f4 * 4];
                uint32_t h0, h1, l0, l1;
                split_pair(v.x, v.y, h0, l0);
                split_pair(v.z, v.w, h1, l1);
                uint32_t sw = swz((uint32_t)(row * 128 + f4 * 8));
                *(uint2*)(bptr + sw) = make_uint2(h0, h1);
                *(uint2*)(bptr + 16384 + sw) = make_uint2(l0, l1);
            }
        } else {
            const __nv_bfloat16 *pHi, *pLo;
            int koff, ibase = 0;
            bool useIdx = false;
            if constexpr (GMODE == 1) {
                int sel = ch >> 1;
                koff = (ch & 1) * 64;
                if (sel == 2) { pHi = eHi; pLo = eLo; }
                else { pHi = hHi; pLo = hLo; useIdx = true; ibase = sel * 128; }
            } else {
                pHi = hHi; pLo = hLo; koff = (ch - 2) * 64;
            }
#pragma unroll
            for (int p = 0; p < 4; p++) {
                int idx = tid + 256 * p;
                int row = idx >> 3, q = idx & 7;
                int ri = useIdx ? idxs[ibase + row] : min(blockRow + row, nRows - 1);
                size_t go = (size_t)ri * LAT + koff + q * 8;
                uint32_t sw = swz((uint32_t)(row * 128 + q * 16));
                cpa16(bbase + sw, pHi + go);
                cpa16(bbase + 16384 + sw, pLo + go);
            }
        }
#pragma unroll
        for (int p = 0; p < 4; p++) {
            int idx = tid + 256 * p;
            int row = idx >> 3, q = idx & 7;
            const size_t go = (size_t)row * KTOT + ch * 64 + q * 8;
            uint32_t sw = swz((uint32_t)(row * 128 + q * 16));
            cpa16(bbase + 32768 + sw, W1hi + go);
            cpa16(bbase + 49152 + sw, W1lo + go);
        }
    };
    auto fillW2 = [&]() {
#pragma unroll
        for (int p = 0; p < 8; p++) {
            int idx = tid + 256 * p;
            int row = idx >> 4, q = idx & 15;
            int c2 = q >> 3, qq = q & 7;
            size_t go = (size_t)row * 128 + c2 * 64 + qq * 8;
            uint32_t sw = swz((uint32_t)(row * 128 + qq * 16));
            cpa16(sb + OFF_W2(c2) + sw, W2hi + go);
            cpa16(sb + OFF_W2(c2) + 16384 + sw, W2lo + go);
        }
    };

    if constexpr (KTOT > 16) {
        constexpr int NC = KTOT / 64;
        fill(0); CPA_COMMIT();
        fill(1); CPA_COMMIT();
        for (int ch = 0; ch < NC; ch++) {
            if (ch < NC - 1) CPA_WAIT(1);
            else CPA_WAIT(0);
            __syncthreads();
            const uint32_t bbase = sb + OFF_BUF(ch & 1);
#pragma unroll
            for (int ks = 0; ks < 4; ks++) {
                const uint32_t kcA = (uint32_t)((ks * 2 + a_kx) * 16) ^ xm;
                const uint32_t kcB = (uint32_t)((ks * 2 + b_kx) * 16) ^ xm;
                uint32_t ah[2][4], al[2][4];
#pragma unroll
                for (int mt = 0; mt < 2; mt++) {
                    uint32_t ro = (uint32_t)((a_row0 + mt * 16) * 128);
                    ldsm4(bbase + ro + kcA, ah[mt]);
                    ldsm4(bbase + 16384 + ro + kcA, al[mt]);
                }
#pragma unroll
                for (int g = 0; g < 4; g++) {
                    uint32_t bh[4], bl[4];
                    uint32_t ro = (uint32_t)((b_row0 + g * 16) * 128);
                    ldsm4(bbase + 32768 + ro + kcB, bh);
                    ldsm4(bbase + 49152 + ro + kcB, bl);
#pragma unroll
                    for (int mt = 0; mt < 2; mt++)
#pragma unroll
                        for (int hf = 0; hf < 2; hf++) {
                            float* cc = c[mt][g * 2 + hf];
                            mma_bf16(cc, ah[mt], &bh[hf * 2]);
                            mma_bf16(cc, ah[mt], &bl[hf * 2]);
                            mma_bf16(cc, al[mt], &bh[hf * 2]);
                        }
                }
            }
            __syncthreads();
            if (ch + 2 < NC) { fill(ch + 2); CPA_COMMIT(); }
        }
        fillW2();
        CPA_COMMIT();
#pragma unroll
        for (int mt = 0; mt < 2; mt++)
#pragma unroll
            for (int idx = 0; idx < 8; idx++)
#pragma unroll
                for (int e = 0; e < 2; e++) {
                    int row = mwarp * 32 + mt * 16 + (lane >> 2) + 8 * e;
                    int col = nwarp * 64 + (idx >> 1) * 16 + (idx & 1) * 8 + 2 * (lane & 3);
                    float v0 = fmaxf(c[mt][idx][2 * e] + b1s[col], 0.f);
                    float v1 = fmaxf(c[mt][idx][2 * e + 1] + b1s[col + 1], 0.f);
                    uint32_t hi, lo;
                    split_pair(v0, v1, hi, lo);
                    uint32_t off = (uint32_t)(nwarp * 16384 + row * 128 +
                                              (((col & 63) * 2) ^ ((row & 7) << 4)));
                    *(uint32_t*)(smp + OFF_H_HI + off) = hi;
                    *(uint32_t*)(smp + OFF_H_LO + off) = lo;
                }
#pragma unroll
        for (int mt = 0; mt < 2; mt++)
#pragma unroll
            for (int i = 0; i < 8; i++)
#pragma unroll
                for (int j = 0; j < 4; j++) c[mt][i][j] = 0.f;
        CPA_WAIT(0);
        __syncthreads();
    } else {
        fillW2();
        CPA_COMMIT();
#pragma unroll
        for (int mt = 0; mt < 2; mt++)
#pragma unroll
            for (int e = 0; e < 2; e++) {
                int row = mwarp * 32 + mt * 16 + (lane >> 2) + 8 * e;
                int grc = min(blockRow + row, nRows - 1);
                float xv[4];
#pragma unroll
                for (int k = 0; k < 4; k++)
                    xv[k] = (k < kreal) ? raw[(size_t)grc * kreal + k] : 0.f;
#pragma unroll
                for (int idx = 0; idx < 8; idx++) {
                    int col = nwarp * 64 + (idx >> 1) * 16 + (idx & 1) * 8 + 2 * (lane & 3);
                    float v0 = b1s[col], v1 = b1s[col + 1];
                    for (int k = 0; k < kreal; k++) {
                        v0 = fmaf(xv[k], w1r[k * 128 + col], v0);
                        v1 = fmaf(xv[k], w1r[k * 128 + col + 1], v1);
                    }
                    v0 = fmaxf(v0, 0.f); v1 = fmaxf(v1, 0.f);
                    uint32_t hi, lo;
                    split_pair(v0, v1, hi, lo);
                    uint32_t off = (uint32_t)(nwarp * 16384 + row * 128 +
                                              (((col & 63) * 2) ^ ((row & 7) << 4)));
                    *(uint32_t*)(smp + OFF_H_HI + off) = hi;
                    *(uint32_t*)(smp + OFF_H_LO + off) = lo;
                }
            }
        CPA_WAIT(0);
        __syncthreads();
    }

#pragma unroll
    for (int c2 = 0; c2 < 2; c2++) {
        const uint32_t abH = sb + OFF_H_HI + c2 * 16384;
        const uint32_t abL = sb + OFF_H_LO + c2 * 16384;
        const uint32_t wb = sb + OFF_W2(c2);
#pragma unroll
        for (int ks = 0; ks < 4; ks++) {
            const uint32_t kcA = (uint32_t)((ks * 2 + a_kx) * 16) ^ xm;
            const uint32_t kcB = (uint32_t)((ks * 2 + b_kx) * 16) ^ xm;
            uint32_t ah[2][4], al[2][4];
#pragma unroll
            for (int mt = 0; mt < 2; mt++) {
                uint32_t ro = (uint32_t)((a_row0 + mt * 16) * 128);
                ldsm4(abH + ro + kcA, ah[mt]);
                ldsm4(abL + ro + kcA, al[mt]);
            }
#pragma unroll
            for (int g = 0; g < 4; g++) {
                uint32_t bh[4], bl[4];
                uint32_t ro = (uint32_t)((b_row0 + g * 16) * 128);
                ldsm4(wb + ro + kcB, bh);
                ldsm4(wb + 16384 + ro + kcB, bl);
#pragma unroll
                for (int mt = 0; mt < 2; mt++)
#pragma unroll
                    for (int hf = 0; hf < 2; hf++) {
                        float* cc = c[mt][g * 2 + hf];
                        mma_bf16(cc, ah[mt], &bh[hf * 2]);
                        mma_bf16(cc, ah[mt], &bl[hf * 2]);
                        mma_bf16(cc, al[mt], &bh[hf * 2]);
                    }
            }
        }
    }

#pragma unroll
    for (int mt = 0; mt < 2; mt++)
#pragma unroll
        for (int idx = 0; idx < 8; idx++) {
            int col = nwarp * 64 + (idx >> 1) * 16 + (idx & 1) * 8 + 2 * (lane & 3);
#pragma unroll
            for (int j = 0; j < 4; j++)
                c[mt][idx][j] = fmaxf(c[mt][idx][j] + b2s[col + (j & 1)], 0.f);
        }

#pragma unroll
    for (int mt = 0; mt < 2; mt++)
#pragma unroll
        for (int e = 0; e < 2; e++) {
            float s = 0.f;
#pragma unroll
            for (int idx = 0; idx < 8; idx++)
                s += c[mt][idx][2 * e] + c[mt][idx][2 * e + 1];
            s += __shfl_xor_sync(0xffffffffu, s, 1);
            s += __shfl_xor_sync(0xffffffffu, s, 2);
            if ((lane & 3) == 0) {
                int row = mwarp * 32 + mt * 16 + (lane >> 2) + 8 * e;
                lnb[row * 2 + nwarp] = s;
            }
        }
    __syncthreads();
    float mu[2][2], rs[2][2];
#pragma unroll
    for (int mt = 0; mt < 2; mt++)
#pragma unroll
        for (int e = 0; e < 2; e++) {
            int row = mwarp * 32 + mt * 16 + (lane >> 2) + 8 * e;
            mu[mt][e] = (lnb[row * 2] + lnb[row * 2 + 1]) * (1.0f / 128.0f);
            float sq = 0.f;
#pragma unroll
            for (int idx = 0; idx < 8; idx++) {
                float d0 = c[mt][idx][2 * e] - mu[mt][e];
                float d1 = c[mt][idx][2 * e + 1] - mu[mt][e];
                sq = fmaf(d0, d0, sq);
                sq = fmaf(d1, d1, sq);
            }
            sq += __shfl_xor_sync(0xffffffffu, sq, 1);
            sq += __shfl_xor_sync(0xffffffffu, sq, 2);
            if ((lane & 3) == 0) lnb[256 + row * 2 + nwarp] = sq;
        }
    __syncthreads();
#pragma unroll
    for (int mt = 0; mt < 2; mt++)
#pragma unroll
        for (int e = 0; e < 2; e++) {
            int row = mwarp * 32 + mt * 16 + (lane >> 2) + 8 * e;
            rs[mt][e] = rsqrtf((lnb[256 + row * 2] + lnb[256 + row * 2 + 1]) *
                                   (1.0f / 128.0f) + EPSV);
        }

#pragma unroll
    for (int mt = 0; mt < 2; mt++)
#pragma unroll
        for (int e = 0; e < 2; e++) {
            int row = mwarp * 32 + mt * 16 + (lane >> 2) + 8 * e;
            int gr = blockRow + row;
            if (gr >= nRows) continue;
            float m = mu[mt][e], q = rs[mt][e];
            if constexpr (ATOMIC) {
                const int drow = scatIdx[gr];
                float* op = outF + (size_t)drow * LAT;
#pragma unroll
                for (int idx = 0; idx < 8; idx++) {
                    int col = nwarp * 64 + (idx >> 1) * 16 + (idx & 1) * 8 + 2 * (lane & 3);
                    float v0 = (c[mt][idx][2 * e]     - m) * q * Gs[col]     + BEs[col];
                    float v1 = (c[mt][idx][2 * e + 1] - m) * q * Gs[col + 1] + BEs[col + 1];
                    red2(&op[col], v0, v1);
                }
            } else {
#pragma unroll
                for (int idx = 0; idx < 8; idx++) {
                    int col = nwarp * 64 + (idx >> 1) * 16 + (idx & 1) * 8 + 2 * (lane & 3);
                    float v0 = (c[mt][idx][2 * e]     - m) * q * Gs[col]     + BEs[col];
                    float v1 = (c[mt][idx][2 * e + 1] - m) * q * Gs[col + 1] + BEs[col + 1];
                    if (resHi) {
                        uint32_t rh = *(const uint32_t*)&resHi[(size_t)gr * LAT + col];
                        uint32_t rl = *(const uint32_t*)&resLo[(size_t)gr * LAT + col];
                        v0 += recon(rh, 0) + recon(rl, 0);
                        v1 += recon(rh, 1) + recon(rl, 1);
                    }
                    uint32_t hi, lo;
                    split_pair(v0, v1, hi, lo);
                    *(uint32_t*)&outHi[(size_t)gr * LAT + col] = hi;
                    *(uint32_t*)&outLo[(size_t)gr * LAT + col] = lo;
                }
            }
        }
}

__global__ void prep_all(
    const float* __restrict__ s0, __nv_bfloat16* __restrict__ h0b, __nv_bfloat16* __restrict__ l0b,
    const float* __restrict__ s1, __nv_bfloat16* __restrict__ h1b, __nv_bfloat16* __restrict__ l1b,
    const float* __restrict__ s2, __nv_bfloat16* __restrict__ h2b, __nv_bfloat16* __restrict__ l2b,
    const float* __restrict__ s3, __nv_bfloat16* __restrict__ h3b, __nv_bfloat16* __restrict__ l3b,
    const float* __restrict__ s4, __nv_bfloat16* __restrict__ h4b, __nv_bfloat16* __restrict__ l4b,
    const float* __restrict__ s5, __nv_bfloat16* __restrict__ h5b, __nv_bfloat16* __restrict__ l5b)
{
    int i = blockIdx.x * blockDim.x + threadIdx.x;
    const float* W; __nv_bfloat16 *hi, *lo; int K, j;
    if (i < 49152)       { W = s0; hi = h0b; lo = l0b; K = 384; j = i; }
    else if (i < 65536)  { W = s1; hi = h1b; lo = l1b; K = 128; j = i - 49152; }
    else if (i < 98304)  { W = s2; hi = h2b; lo = l2b; K = 256; j = i - 65536; }
    else if (i < 114688) { W = s3; hi = h3b; lo = l3b; K = 128; j = i - 98304; }
    else if (i < 131072) { W = s4; hi = h4b; lo = l4b; K = 128; j = i - 114688; }
    else if (i < 147456) { W = s5; hi = h5b; lo = l5b; K = 128; j = i - 131072; }
    else return;
    int k = j >> 7, n = j & 127;
    float v = W[j];
    __nv_bfloat16 h = __float2bfloat16(v);
    hi[(size_t)n * K + k] = h;
    lo[(size_t)n * K + k] = __float2bfloat16(v - __bfloat162float(h));
}

__global__ __launch_bounds__(256) void decoder_kernel(
    const __nv_bfloat16* __restrict__ hHi, const __nv_bfloat16* __restrict__ hLo,
    const float* __restrict__ W1, const float* __restrict__ B1,
    const float* __restrict__ W2, const float* __restrict__ B2,
    float* __restrict__ out, int n)
{
    extern __shared__ float s[];
    float* W1s = s;
    float* hs = s + 128 * 128;
    int tid = threadIdx.x;
#pragma unroll
    for (int it = 0; it < 16; it++) {
        int f = tid + 256 * it;
        *(float4*)&W1s[f * 4] = *(const float4*)&W1[f * 4];
    }
    int warp = tid >> 5, lane = tid & 31;
    int row = blockIdx.x * 8 + warp;
    int rc = min(row, n - 1);
#pragma unroll
    for (int q = 0; q < 4; q++) {
        int cc = lane + 32 * q;
        hs[warp * 128 + cc] = __bfloat162float(hHi[(size_t)rc * LAT + cc]) +
                              __bfloat162float(hLo[(size_t)rc * LAT + cc]);
    }
    __syncthreads();

    float acc[4];
#pragma unroll
    for (int q = 0; q < 4; q++) acc[q] = B1[lane + 32 * q];
    for (int k = 0; k < 128; k++) {
        float hv = hs[warp * 128 + k];
#pragma unroll
        for (int q = 0; q < 4; q++)
            acc[q] = fmaf(hv, W1s[k * 128 + lane + 32 * q], acc[q]);
    }
#pragma unroll
    for (int q = 0; q < 4; q++) acc[q] = fmaxf(acc[q], 0.f);

    float o[3];
#pragma unroll
    for (int oo = 0; oo < 3; oo++) {
        float p = 0.f;
#pragma unroll
        for (int q = 0; q < 4; q++)
            p = fmaf(acc[q], W2[(size_t)(lane + 32 * q) * 3 + oo], p);
#pragma unroll
        for (int off = 16; off > 0; off >>= 1)
            p += __shfl_xor_sync(0xffffffffu, p, off);
        o[oo] = p;
    }
    if (lane == 0 && row < n) {
        out[(size_t)row * 3 + 0] = o[0] + B2[0];
        out[(size_t)row * 3 + 1] = o[1] + B2[1];
        out[(size_t)row * 3 + 2] = o[2] + B2[2];
    }
}

__global__ void zero_kernel(float4* __restrict__ p, int n4)
{
    int i = blockIdx.x * blockDim.x + threadIdx.x;
    if (i < n4) p[i] = make_float4(0.f, 0.f, 0.f, 0.f);
}

extern "C" void kernel_launch(void* const* d_in, const int* in_sizes, int n_in,
                              void* d_out, int out_size)
{
    (void)in_sizes; (void)n_in; (void)out_size;
    const float* x  = (const float*)d_in[0];
    const float* ea = (const float*)d_in[1];
    const int*   ei = (const int*)d_in[2];
    const int* src = ei;
    const int* dst = ei + NEDGES;

    const float* ne_w1 = (const float*)d_in[3];
    const float* ne_b1 = (const float*)d_in[4];
    const float* ne_w2 = (const float*)d_in[5];
    const float* ne_b2 = (const float*)d_in[6];
    const float* ne_g  = (const float*)d_in[7];
    const float* ne_be = (const float*)d_in[8];
    const float* ee_w1 = (const float*)d_in[9];
    const float* ee_b1 = (const float*)d_in[10];
    const float* ee_w2 = (const float*)d_in[11];
    const float* ee_b2 = (const float*)d_in[12];
    const float* ee_g  = (const float*)d_in[13];
    const float* ee_be = (const float*)d_in[14];
    const float* em_w1 = (const float*)d_in[15];
    const float* em_b1 = (const float*)d_in[16];
    const float* em_w2 = (const float*)d_in[17];
    const float* em_b2 = (const float*)d_in[18];
    const float* em_g  = (const float*)d_in[19];
    const float* em_be = (const float*)d_in[20];
    const float* nm_w1 = (const float*)d_in[21];
    const float* nm_b1 = (const float*)d_in[22];
    const float* nm_w2 = (const float*)d_in[23];
    const float* nm_b2 = (const float*)d_in[24];
    const float* nm_g  = (const float*)d_in[25];
    const float* nm_be = (const float*)d_in[26];
    const float* dw1   = (const float*)d_in[27];
    const float* db1   = (const float*)d_in[28];
    const float* dw2   = (const float*)d_in[29];
    const float* db2   = (const float*)d_in[30];

    float* fb = nullptr;
    cudaGetSymbolAddress((void**)&fb, g_fbuf);
    float* agg = fb;
    float* Y1 = fb + (size_t)NNODES * LAT;
    float* Y2 = fb + (size_t)2 * NNODES * LAT;
    float* Ye = fb + (size_t)3 * NNODES * LAT;

    __nv_bfloat16* hp = nullptr;
    cudaGetSymbolAddress((void**)&hp, g_hpl);
    __nv_bfloat16* ep = nullptr;
    cudaGetSymbolAddress((void**)&ep, g_epl);
    const size_t HS = (size_t)NNODES * LAT, ES = (size_t)NEDGES * LAT;
    __nv_bfloat16 *hH0 = hp, *hL0 = hp + HS, *hH1 = hp + 2 * HS, *hL1 = hp + 3 * HS;
    __nv_bfloat16 *eH0 = ep, *eL0 = ep + ES, *eH1 = ep + 2 * ES, *eL1 = ep + 3 * ES;

    __nv_bfloat16* pl = nullptr;
    cudaGetSymbolAddress((void**)&pl, g_planes);
    __nv_bfloat16* emW1h = pl;
    __nv_bfloat16* emW1l = pl + 49152;
    __nv_bfloat16* emW2h = pl + 98304;
    __nv_bfloat16* emW2l = pl + 114688;
    __nv_bfloat16* nmW1h = pl + 131072;
    __nv_bfloat16* nmW1l = pl + 163840;
    __nv_bfloat16* nmW2h = pl + 196608;
    __nv_bfloat16* nmW2l = pl + 212992;
    __nv_bfloat16* neW2h = pl + 229376;
    __nv_bfloat16* neW2l = pl + 245760;
    __nv_bfloat16* eeW2h = pl + 262144;
    __nv_bfloat16* eeW2l = pl + 278528;

    cudaFuncSetAttribute(gnn_mma<16, 0, false>,
                         cudaFuncAttributeMaxDynamicSharedMemorySize, SMEM_DYN);
    cudaFuncSetAttribute(gnn_mma<256, 2, false>,
                         cudaFuncAttributeMaxDynamicSharedMemorySize, SMEM_DYN);
    cudaFuncSetAttribute(edge_fused,
                         cudaFuncAttributeMaxDynamicSharedMemorySize, SMEM_E);
    cudaFuncSetAttribute(gemm_k128<2>,
                         cudaFuncAttributeMaxDynamicSharedMemorySize, SMEM_G);
    cudaFuncSetAttribute(gemm_k128<4>,
                         cudaFuncAttributeMaxDynamicSharedMemorySize, SMEM_G);
    const int DSM = (128 * 128 + 8 * 128) * (int)sizeof(float);
    cudaFuncSetAttribute(decoder_kernel,
                         cudaFuncAttributeMaxDynamicSharedMemorySize, DSM);

    prep_all<<<(147456 + 255) / 256, 256>>>(
        em_w1, emW1h, emW1l, em_w2, emW2h, emW2l,
        nm_w1, nmW1h, nmW1l, nm_w2, nmW2h, nmW2l,
        ne_w2, neW2h, neW2l, ee_w2, eeW2h, eeW2l);

    dim3 blk(256);
    const int ntiles = (NNODES + 127) / 128;              // 391
    const int etiles = NEDGES / 128;                      // 3125
    const int ngrid2 = (NNODES + 255) / 256;              // 196
    const int egrid4 = (NEDGES + 511) / 512;              // 782

    gnn_mma<16, 0, false><<<ntiles, blk, SMEM_DYN>>>(
        x, ne_w1, 3, nullptr, nullptr, nullptr, nullptr, nullptr, nullptr, nullptr,
        nullptr, nullptr, ne_b1, neW2h, neW2l, ne_b2, ne_g, ne_be,
        nullptr, nullptr, hH0, hL0, nullptr, nullptr, NNODES);
    gnn_mma<16, 0, false><<<etiles, blk, SMEM_DYN>>>(
        ea, ee_w1, 4, nullptr, nullptr, nullptr, nullptr, nullptr, nullptr, nullptr,
        nullptr, nullptr, ee_b1, eeW2h, eeW2l, ee_b2, ee_g, ee_be,
        nullptr, nullptr, eH0, eL0, nullptr, nullptr, NEDGES);

    __nv_bfloat16 *hcH = hH0, *hcL = hL0, *hnH = hH1, *hnL = hL1;
    __nv_bfloat16 *ecH = eH0, *ecL = eL0, *enH = eH1, *enL = eL1;
    for (int s = 0; s < 5; s++) {
        gemm_k128<2><<<ngrid2, blk, SMEM_G>>>(hcH, hcL, emW1h, emW1l, 384, 0,
                                              nullptr, Y1, NNODES);
        gemm_k128<2><<<ngrid2, blk, SMEM_G>>>(hcH, hcL, emW1h, emW1l, 384, 128,
                                              nullptr, Y2, NNODES);
        gemm_k128<4><<<egrid4, blk, SMEM_G>>>(ecH, ecL, emW1h, emW1l, 384, 256,
                                              em_b1, Ye, NEDGES);
        zero_kernel<<<(NNODES * LAT / 4 + 255) / 256, 256>>>((float4*)agg,
                                                             NNODES * LAT / 4);
        edge_fused<<<etiles, blk, SMEM_E>>>(
            Y1, Y2, Ye, dst, src, emW2h, emW2l, em_b2, em_g, em_be,
            ecH, ecL, enH, enL, agg, NEDGES);
        gnn_mma<256, 2, false><<<ntiles, blk, SMEM_DYN>>>(
            nullptr, nullptr, 0, agg, hcH, hcL, nullptr, nullptr, nullptr, nullptr,
            nmW1h, nmW1l, nm_b1, nmW2h, nmW2l, nm_b2, nm_g, nm_be,
            hcH, hcL, hnH, hnL, nullptr, nullptr, NNODES);
        __nv_bfloat16* t;
        t = hcH; hcH = hnH; hnH = t;
        t = hcL; hcL = hnL; hnL = t;
        t = ecH; ecH = enH; enH = t;
        t = ecL; ecL = enL; enL = t;
    }

    decoder_kernel<<<(NNODES + 7) / 8, blk, DSM>>>(
        hcH, hcL, dw1, db1, dw2, db2, (float*)d_out, NNODES);
}

// round 10
// speedup vs baseline: 3.2728x; 1.0174x over previous
#include <cuda_runtime.h>
#include <cuda_bf16.h>
#include <cstdint>
#include <cstddef>

#define LAT 128
#define NNODES 50000
#define NEDGES 400000
#define EPSV 1e-5f

// fp32: agg | Y1 | Y2 | Ye
__device__ float g_fbuf[(size_t)(3 * NNODES + NEDGES) * LAT];
__device__ __align__(16) __nv_bfloat16 g_hpl[(size_t)4 * NNODES * LAT];
__device__ __align__(16) __nv_bfloat16 g_epl[(size_t)4 * NEDGES * LAT];
__device__ __align__(16) __nv_bfloat16 g_planes[294912];

__device__ __forceinline__ uint32_t smem_u32(const void* p) {
    uint32_t a;
    asm("{ .reg .u64 t; cvta.to.shared.u64 t, %1; cvt.u32.u64 %0, t; }" : "=r"(a) : "l"(p));
    return a;
}
__device__ __forceinline__ void ldsm4(uint32_t addr, uint32_t* r) {
    asm volatile("ldmatrix.sync.aligned.m8n8.x4.shared.b16 {%0,%1,%2,%3}, [%4];"
                 : "=r"(r[0]), "=r"(r[1]), "=r"(r[2]), "=r"(r[3]) : "r"(addr));
}
__device__ __forceinline__ void mma_bf16(float* d, const uint32_t* a, const uint32_t* b) {
    asm volatile("mma.sync.aligned.m16n8k16.row.col.f32.bf16.bf16.f32 "
                 "{%0,%1,%2,%3}, {%4,%5,%6,%7}, {%8,%9}, {%0,%1,%2,%3};"
                 : "+f"(d[0]), "+f"(d[1]), "+f"(d[2]), "+f"(d[3])
                 : "r"(a[0]), "r"(a[1]), "r"(a[2]), "r"(a[3]), "r"(b[0]), "r"(b[1]));
}
__device__ __forceinline__ void cpa16(uint32_t saddr, const void* g) {
    asm volatile("cp.async.cg.shared.global [%0], [%1], 16;"
                 :: "r"(saddr), "l"(g) : "memory");
}
#define CPA_COMMIT() asm volatile("cp.async.commit_group;" ::: "memory")
#define CPA_WAIT(N)  asm volatile("cp.async.wait_group %0;" :: "n"(N) : "memory")
__device__ __forceinline__ void red2(float* addr, float v0, float v1) {
    asm volatile("red.global.add.v2.f32 [%0], {%1, %2};"
                 :: "l"(addr), "f"(v0), "f"(v1) : "memory");
}
__device__ __forceinline__ uint32_t swz(uint32_t bo) { return bo ^ ((bo >> 3) & 0x70); }
__device__ __forceinline__ void split_pair(float a, float b, uint32_t& hi, uint32_t& lo) {
    __nv_bfloat16 ah = __float2bfloat16(a), bh = __float2bfloat16(b);
    __nv_bfloat162 hp; hp.x = ah; hp.y = bh;
    __nv_bfloat162 lp;
    lp.x = __float2bfloat16(a - __bfloat162float(ah));
    lp.y = __float2bfloat16(b - __bfloat162float(bh));
    hi = *reinterpret_cast<uint32_t*>(&hp);
    lo = *reinterpret_cast<uint32_t*>(&lp);
}
__device__ __forceinline__ float recon(uint32_t packed, int half) {
    __nv_bfloat162 v = *reinterpret_cast<__nv_bfloat162*>(&packed);
    return half ? __bfloat162float(v.y) : __bfloat162float(v.x);
}

// ============================================================================
// gemm_s: out[r,128] = A[r,128] @ B(k0,stride) (+bias), fp32 out.
// A resident (64KB); B streamed through one 32KB chunk buffer. 2 CTAs/SM.
// ============================================================================
#define S_A_HI 0
#define S_A_LO 32768
#define S_B_HI 65536
#define S_B_LO 81920
#define S_BIAS 98304
#define SMEM_S 98816

__global__ __launch_bounds__(256, 2) void gemm_s(
    const __nv_bfloat16* __restrict__ aHi, const __nv_bfloat16* __restrict__ aLo,
    const __nv_bfloat16* __restrict__ bHi, const __nv_bfloat16* __restrict__ bLo,
    int bStride, int bK0,
    const float* __restrict__ bias, float* __restrict__ out, int nRows)
{
    extern __shared__ char smp[];
    const uint32_t sb = smem_u32(smp);
    const int tid = threadIdx.x;
    const int wid = tid >> 5, lane = tid & 31;
    const int mwarp = wid & 3, nwarp = wid >> 2;
    const int blockRow = blockIdx.x * 128;

    float* bs = (float*)(smp + S_BIAS);
    if (tid < 128) bs[tid] = bias ? bias[tid] : 0.f;

    // A fill (both k-chunks, hi+lo)
#pragma unroll
    for (int p = 0; p < 8; p++) {
        int idx = tid + 256 * p;
        int row = idx >> 4, q = idx & 15;
        int c2 = q >> 3, qq = q & 7;
        int rc = min(blockRow + row, nRows - 1);
        size_t ga = (size_t)rc * 128 + q * 8;
        uint32_t sw = (uint32_t)(c2 * 16384) + swz((uint32_t)(row * 128 + qq * 16));
        cpa16(sb + S_A_HI + sw, aHi + ga);
        cpa16(sb + S_A_LO + sw, aLo + ga);
    }
    auto fillB = [&](int chunk) {
#pragma unroll
        for (int p = 0; p < 4; p++) {
            int idx = tid + 256 * p;
            int row = idx >> 3, qq = idx & 7;
            size_t gb = (size_t)row * bStride + bK0 + chunk * 64 + qq * 8;
            uint32_t sw = swz((uint32_t)(row * 128 + qq * 16));
            cpa16(sb + S_B_HI + sw, bHi + gb);
            cpa16(sb + S_B_LO + sw, bLo + gb);
        }
    };
    fillB(0);
    CPA_COMMIT();

    const int lrow = lane & 7, lg = lane >> 3;
    const uint32_t xm = (uint32_t)lrow << 4;
    const int a_row0 = mwarp * 32 + lrow + 8 * (lg & 1);
    const int a_kx = lg >> 1;
    const int b_row0 = nwarp * 64 + lrow + 8 * (lg >> 1);
    const int b_kx = lg & 1;

    float c[2][8][4];
#pragma unroll
    for (int mt = 0; mt < 2; mt++)
#pragma unroll
        for (int i = 0; i < 8; i++)
#pragma unroll
            for (int j = 0; j < 4; j++) c[mt][i][j] = 0.f;

    for (int c2 = 0; c2 < 2; c2++) {
        CPA_WAIT(0);
        __syncthreads();
        const uint32_t abH = sb + S_A_HI + c2 * 16384;
        const uint32_t abL = sb + S_A_LO + c2 * 16384;
#pragma unroll
        for (int ks = 0; ks < 4; ks++) {
            const uint32_t kcA = (uint32_t)((ks * 2 + a_kx) * 16) ^ xm;
            const uint32_t kcB = (uint32_t)((ks * 2 + b_kx) * 16) ^ xm;
            uint32_t ah[2][4], al[2][4];
#pragma unroll
            for (int mt = 0; mt < 2; mt++) {
                uint32_t ro = (uint32_t)((a_row0 + mt * 16) * 128);
                ldsm4(abH + ro + kcA, ah[mt]);
                ldsm4(abL + ro + kcA, al[mt]);
            }
#pragma unroll
            for (int g = 0; g < 4; g++) {
                uint32_t bh[4], bl[4];
                uint32_t ro = (uint32_t)((b_row0 + g * 16) * 128);
                ldsm4(sb + S_B_HI + ro + kcB, bh);
                ldsm4(sb + S_B_LO + ro + kcB, bl);
#pragma unroll
                for (int mt = 0; mt < 2; mt++)
#pragma unroll
                    for (int hf = 0; hf < 2; hf++) {
                        float* cc = c[mt][g * 2 + hf];
                        mma_bf16(cc, ah[mt], &bh[hf * 2]);
                        mma_bf16(cc, ah[mt], &bl[hf * 2]);
                        mma_bf16(cc, al[mt], &bh[hf * 2]);
                    }
            }
        }
        __syncthreads();
        if (c2 == 0) { fillB(1); CPA_COMMIT(); }
    }

#pragma unroll
    for (int mt = 0; mt < 2; mt++)
#pragma unroll
        for (int e = 0; e < 2; e++) {
            int row = mwarp * 32 + mt * 16 + (lane >> 2) + 8 * e;
            int gr = blockRow + row;
            if (gr >= nRows) continue;
#pragma unroll
            for (int idx = 0; idx < 8; idx++) {
                int col = nwarp * 64 + (idx >> 1) * 16 + (idx & 1) * 8 + 2 * (lane & 3);
                float2 o;
                o.x = c[mt][idx][2 * e] + bs[col];
                o.y = c[mt][idx][2 * e + 1] + bs[col + 1];
                *(float2*)&out[(size_t)gr * 128 + col] = o;
            }
        }
}

// ============================================================================
// encode_mlp: SIMT layer1 (kreal<=4) -> H planes -> streamed-W2 layer2 -> LN
//             -> bf16 hi/lo output planes. 2 CTAs/SM.
// ============================================================================
#define N_H_HI 0
#define N_H_LO 32768
#define N_W2   65536
#define N_B1   98304
#define N_B2   98816
#define N_G    99328
#define N_BE   99840
#define N_LN   100352
#define N_W1R  102400
#define SMEM_N 104448

__global__ __launch_bounds__(256, 2) void encode_mlp(
    const float* __restrict__ raw, const float* __restrict__ W1raw, int kreal,
    const float* __restrict__ B1,
    const __nv_bfloat16* __restrict__ W2hi, const __nv_bfloat16* __restrict__ W2lo,
    const float* __restrict__ B2,
    const float* __restrict__ G, const float* __restrict__ BE,
    __nv_bfloat16* __restrict__ outHi, __nv_bfloat16* __restrict__ outLo, int nRows)
{
    extern __shared__ char smp[];
    const uint32_t sb = smem_u32(smp);
    const int tid = threadIdx.x;
    const int wid = tid >> 5, lane = tid & 31;
    const int mwarp = wid & 3, nwarp = wid >> 2;
    const int blockRow = blockIdx.x * 128;

    float* b1s = (float*)(smp + N_B1);
    float* b2s = (float*)(smp + N_B2);
    float* Gs  = (float*)(smp + N_G);
    float* BEs = (float*)(smp + N_BE);
    float* lnb = (float*)(smp + N_LN);
    float* w1r = (float*)(smp + N_W1R);

    if (tid < 128) {
        b1s[tid] = B1[tid]; b2s[tid] = B2[tid];
        Gs[tid] = G[tid];   BEs[tid] = BE[tid];
    }
    for (int i = tid; i < kreal * 128; i += 256) w1r[i] = W1raw[i];
    __syncthreads();

    auto fillW2 = [&](int chunk) {
#pragma unroll
        for (int p = 0; p < 4; p++) {
            int idx = tid + 256 * p;
            int row = idx >> 3, qq = idx & 7;
            size_t go = (size_t)row * 128 + chunk * 64 + qq * 8;
            uint32_t sw = swz((uint32_t)(row * 128 + qq * 16));
            cpa16(sb + N_W2 + sw, W2hi + go);
            cpa16(sb + N_W2 + 16384 + sw, W2lo + go);
        }
    };
    fillW2(0); CPA_COMMIT();

    // SIMT layer1 -> H planes
#pragma unroll 4
    for (int p = 0; p < 16; p++) {
        int idx = tid + 256 * p;
        int row = idx >> 5, qf = idx & 31;
        int col = qf * 4;
        int rc = min(blockRow + row, nRows - 1);
        float xv[4];
#pragma unroll
        for (int k = 0; k < 4; k++)
            xv[k] = (k < kreal) ? raw[(size_t)rc * kreal + k] : 0.f;
        float v[4];
#pragma unroll
        for (int j = 0; j < 4; j++) {
            float acc = b1s[col + j];
            for (int k = 0; k < kreal; k++)
                acc = fmaf(xv[k], w1r[k * 128 + col + j], acc);
            v[j] = fmaxf(acc, 0.f);
        }
        uint32_t h0, h1, l0, l1;
        split_pair(v[0], v[1], h0, l0);
        split_pair(v[2], v[3], h1, l1);
        uint32_t off = (uint32_t)((col >> 6) * 16384) +
                       swz((uint32_t)(row * 128 + (col & 63) * 2));
        *(uint2*)(smp + N_H_HI + off) = make_uint2(h0, h1);
        *(uint2*)(smp + N_H_LO + off) = make_uint2(l0, l1);
    }

    const int lrow = lane & 7, lg = lane >> 3;
    const uint32_t xm = (uint32_t)lrow << 4;
    const int a_row0 = mwarp * 32 + lrow + 8 * (lg & 1);
    const int a_kx = lg >> 1;
    const int b_row0 = nwarp * 64 + lrow + 8 * (lg >> 1);
    const int b_kx = lg & 1;

    float c[2][8][4];
#pragma unroll
    for (int mt = 0; mt < 2; mt++)
#pragma unroll
        for (int i = 0; i < 8; i++)
#pragma unroll
            for (int j = 0; j < 4; j++) c[mt][i][j] = 0.f;

    for (int c2 = 0; c2 < 2; c2++) {
        CPA_WAIT(0);
        __syncthreads();
        const uint32_t abH = sb + N_H_HI + c2 * 16384;
        const uint32_t abL = sb + N_H_LO + c2 * 16384;
#pragma unroll
        for (int ks = 0; ks < 4; ks++) {
            const uint32_t kcA = (uint32_t)((ks * 2 + a_kx) * 16) ^ xm;
            const uint32_t kcB = (uint32_t)((ks * 2 + b_kx) * 16) ^ xm;
            uint32_t ah[2][4], al[2][4];
#pragma unroll
            for (int mt = 0; mt < 2; mt++) {
                uint32_t ro = (uint32_t)((a_row0 + mt * 16) * 128);
                ldsm4(abH + ro + kcA, ah[mt]);
                ldsm4(abL + ro + kcA, al[mt]);
            }
#pragma unroll
            for (int g = 0; g < 4; g++) {
                uint32_t bh[4], bl[4];
                uint32_t ro = (uint32_t)((b_row0 + g * 16) * 128);
                ldsm4(sb + N_W2 + ro + kcB, bh);
                ldsm4(sb + N_W2 + 16384 + ro + kcB, bl);
#pragma unroll
                for (int mt = 0; mt < 2; mt++)
#pragma unroll
                    for (int hf = 0; hf < 2; hf++) {
                        float* cc = c[mt][g * 2 + hf];
                        mma_bf16(cc, ah[mt], &bh[hf * 2]);
                        mma_bf16(cc, ah[mt], &bl[hf * 2]);
                        mma_bf16(cc, al[mt], &bh[hf * 2]);
                    }
            }
        }
        __syncthreads();
        if (c2 == 0) { fillW2(1); CPA_COMMIT(); }
    }

    // bias2 + ReLU + LN + output planes
#pragma unroll
    for (int mt = 0; mt < 2; mt++)
#pragma unroll
        for (int idx = 0; idx < 8; idx++) {
            int col = nwarp * 64 + (idx >> 1) * 16 + (idx & 1) * 8 + 2 * (lane & 3);
#pragma unroll
            for (int j = 0; j < 4; j++)
                c[mt][idx][j] = fmaxf(c[mt][idx][j] + b2s[col + (j & 1)], 0.f);
        }
#pragma unroll
    for (int mt = 0; mt < 2; mt++)
#pragma unroll
        for (int e = 0; e < 2; e++) {
            float s = 0.f;
#pragma unroll
            for (int idx = 0; idx < 8; idx++)
                s += c[mt][idx][2 * e] + c[mt][idx][2 * e + 1];
            s += __shfl_xor_sync(0xffffffffu, s, 1);
            s += __shfl_xor_sync(0xffffffffu, s, 2);
            if ((lane & 3) == 0) {
                int row = mwarp * 32 + mt * 16 + (lane >> 2) + 8 * e;
                lnb[row * 2 + nwarp] = s;
            }
        }
    __syncthreads();
    float mu[2][2], rs[2][2];
#pragma unroll
    for (int mt = 0; mt < 2; mt++)
#pragma unroll
        for (int e = 0; e < 2; e++) {
            int row = mwarp * 32 + mt * 16 + (lane >> 2) + 8 * e;
            mu[mt][e] = (lnb[row * 2] + lnb[row * 2 + 1]) * (1.0f / 128.0f);
            float sq = 0.f;
#pragma unroll
            for (int idx = 0; idx < 8; idx++) {
                float d0 = c[mt][idx][2 * e] - mu[mt][e];
                float d1 = c[mt][idx][2 * e + 1] - mu[mt][e];
                sq = fmaf(d0, d0, sq);
                sq = fmaf(d1, d1, sq);
            }
            sq += __shfl_xor_sync(0xffffffffu, sq, 1);
            sq += __shfl_xor_sync(0xffffffffu, sq, 2);
            if ((lane & 3) == 0) lnb[256 + row * 2 + nwarp] = sq;
        }
    __syncthreads();
#pragma unroll
    for (int mt = 0; mt < 2; mt++)
#pragma unroll
        for (int e = 0; e < 2; e++) {
            int row = mwarp * 32 + mt * 16 + (lane >> 2) + 8 * e;
            rs[mt][e] = rsqrtf((lnb[256 + row * 2] + lnb[256 + row * 2 + 1]) *
                                   (1.0f / 128.0f) + EPSV);
        }
#pragma unroll
    for (int mt = 0; mt < 2; mt++)
#pragma unroll
        for (int e = 0; e < 2; e++) {
            int row = mwarp * 32 + mt * 16 + (lane >> 2) + 8 * e;
            int gr = blockRow + row;
            if (gr >= nRows) continue;
            float m = mu[mt][e], q = rs[mt][e];
#pragma unroll
            for (int idx = 0; idx < 8; idx++) {
                int col = nwarp * 64 + (idx >> 1) * 16 + (idx & 1) * 8 + 2 * (lane & 3);
                float v0 = (c[mt][idx][2 * e]     - m) * q * Gs[col]     + BEs[col];
                float v1 = (c[mt][idx][2 * e + 1] - m) * q * Gs[col + 1] + BEs[col + 1];
                uint32_t hi, lo;
                split_pair(v0, v1, hi, lo);
                *(uint32_t*)&outHi[(size_t)gr * LAT + col] = hi;
                *(uint32_t*)&outLo[(size_t)gr * LAT + col] = lo;
            }
        }
}

// ============================================================================
// edge_fused (unchanged from round 9)
// ============================================================================
#define E_H_HI 0
#define E_H_LO 32768
#define E_W2   65536
#define E_IDX  98304
#define E_B2   99328
#define E_G    99840
#define E_BE   100352
#define E_LN   100864
#define SMEM_E 103424

__global__ __launch_bounds__(256, 2) void edge_fused(
    const float* __restrict__ Y1, const float* __restrict__ Y2,
    const float* __restrict__ Ye,
    const int* __restrict__ dst, const int* __restrict__ src,
    const __nv_bfloat16* __restrict__ W2hi, const __nv_bfloat16* __restrict__ W2lo,
    const float* __restrict__ B2, const float* __restrict__ G,
    const float* __restrict__ BE,
    const __nv_bfloat16* __restrict__ resHi, const __nv_bfloat16* __restrict__ resLo,
    __nv_bfloat16* __restrict__ outHi, __nv_bfloat16* __restrict__ outLo,
    float* __restrict__ aggF, int nRows)
{
    extern __shared__ char smp[];
    const uint32_t sb = smem_u32(smp);
    const int tid = threadIdx.x;
    const int wid = tid >> 5, lane = tid & 31;
    const int mwarp = wid & 3, nwarp = wid >> 2;
    const int blockRow = blockIdx.x * 128;

    int* idxs = (int*)(smp + E_IDX);
    float* b2s = (float*)(smp + E_B2);
    float* Gs  = (float*)(smp + E_G);
    float* BEs = (float*)(smp + E_BE);
    float* lnb = (float*)(smp + E_LN);

    if (tid < 128) {
        idxs[tid] = dst[min(blockRow + tid, nRows - 1)];
        b2s[tid] = B2[tid]; Gs[tid] = G[tid]; BEs[tid] = BE[tid];
    } else {
        idxs[tid] = src[min(blockRow + tid - 128, nRows - 1)];
    }
    __syncthreads();

    auto fillW2 = [&](int chunk) {
#pragma unroll
        for (int p = 0; p < 4; p++) {
            int idx = tid + 256 * p;
            int row = idx >> 3, qq = idx & 7;
            size_t go = (size_t)row * 128 + chunk * 64 + qq * 8;
            uint32_t sw = swz((uint32_t)(row * 128 + qq * 16));
            cpa16(sb + E_W2 + sw, W2hi + go);
            cpa16(sb + E_W2 + 16384 + sw, W2lo + go);
        }
    };
    fillW2(0); CPA_COMMIT();

    const int lrow = lane & 7, lg = lane >> 3;
    const uint32_t xm = (uint32_t)lrow << 4;
    const int a_row0 = mwarp * 32 + lrow + 8 * (lg & 1);
    const int a_kx = lg >> 1;
    const int b_row0 = nwarp * 64 + lrow + 8 * (lg >> 1);
    const int b_kx = lg & 1;

    for (int ph = 0; ph < 2; ph++) {
        const bool MSG = (ph == 0);
#pragma unroll 4
        for (int p = 0; p < 16; p++) {
            int idx = tid + 256 * p;
            int row = idx >> 5, qf = idx & 31;
            int col = qf * 4;
            int gr = min(blockRow + row, nRows - 1);
            int riA = MSG ? idxs[row] : idxs[128 + row];
            int riB = MSG ? idxs[128 + row] : idxs[row];
            float4 a = *(const float4*)&Y1[(size_t)riA * 128 + col];
            float4 b = *(const float4*)&Y2[(size_t)riB * 128 + col];
            float4 e4 = *(const float4*)&Ye[(size_t)gr * 128 + col];
            float v0 = fmaxf(a.x + b.x + e4.x, 0.f);
            float v1 = fmaxf(a.y + b.y + e4.y, 0.f);
            float v2 = fmaxf(a.z + b.z + e4.z, 0.f);
            float v3 = fmaxf(a.w + b.w + e4.w, 0.f);
            uint32_t h0, h1, l0, l1;
            split_pair(v0, v1, h0, l0);
            split_pair(v2, v3, h1, l1);
            uint32_t off = (uint32_t)((col >> 6) * 16384) +
                           swz((uint32_t)(row * 128 + (col & 63) * 2));
            *(uint2*)(smp + E_H_HI + off) = make_uint2(h0, h1);
            *(uint2*)(smp + E_H_LO + off) = make_uint2(l0, l1);
        }

        float c[2][8][4];
#pragma unroll
        for (int mt = 0; mt < 2; mt++)
#pragma unroll
            for (int i = 0; i < 8; i++)
#pragma unroll
                for (int j = 0; j < 4; j++) c[mt][i][j] = 0.f;

        for (int c2 = 0; c2 < 2; c2++) {
            CPA_WAIT(0);
            __syncthreads();
            const uint32_t abH = sb + E_H_HI + c2 * 16384;
            const uint32_t abL = sb + E_H_LO + c2 * 16384;
#pragma unroll
            for (int ks = 0; ks < 4; ks++) {
                const uint32_t kcA = (uint32_t)((ks * 2 + a_kx) * 16) ^ xm;
                const uint32_t kcB = (uint32_t)((ks * 2 + b_kx) * 16) ^ xm;
                uint32_t ah[2][4], al[2][4];
#pragma unroll
                for (int mt = 0; mt < 2; mt++) {
                    uint32_t ro = (uint32_t)((a_row0 + mt * 16) * 128);
                    ldsm4(abH + ro + kcA, ah[mt]);
                    ldsm4(abL + ro + kcA, al[mt]);
                }
#pragma unroll
                for (int g = 0; g < 4; g++) {
                    uint32_t bh[4], bl[4];
                    uint32_t ro = (uint32_t)((b_row0 + g * 16) * 128);
                    ldsm4(sb + E_W2 + ro + kcB, bh);
                    ldsm4(sb + E_W2 + 16384 + ro + kcB, bl);
#pragma unroll
                    for (int mt = 0; mt < 2; mt++)
#pragma unroll
                        for (int hf = 0; hf < 2; hf++) {
                            float* cc = c[mt][g * 2 + hf];
                            mma_bf16(cc, ah[mt], &bh[hf * 2]);
                            mma_bf16(cc, ah[mt], &bl[hf * 2]);
                            mma_bf16(cc, al[mt], &bh[hf * 2]);
                        }
                }
            }
            __syncthreads();
            int nxt = (c2 == 0) ? 1 : (MSG ? 0 : -1);
            if (nxt >= 0) { fillW2(nxt); CPA_COMMIT(); }
        }

#pragma unroll
        for (int mt = 0; mt < 2; mt++)
#pragma unroll
            for (int idx = 0; idx < 8; idx++) {
                int col = nwarp * 64 + (idx >> 1) * 16 + (idx & 1) * 8 + 2 * (lane & 3);
#pragma unroll
                for (int j = 0; j < 4; j++)
                    c[mt][idx][j] = fmaxf(c[mt][idx][j] + b2s[col + (j & 1)], 0.f);
            }

#pragma unroll
        for (int mt = 0; mt < 2; mt++)
#pragma unroll
            for (int e = 0; e < 2; e++) {
                float s = 0.f;
#pragma unroll
                for (int idx = 0; idx < 8; idx++)
                    s += c[mt][idx][2 * e] + c[mt][idx][2 * e + 1];
                s += __shfl_xor_sync(0xffffffffu, s, 1);
                s += __shfl_xor_sync(0xffffffffu, s, 2);
                if ((lane & 3) == 0) {
                    int row = mwarp * 32 + mt * 16 + (lane >> 2) + 8 * e;
                    lnb[row * 2 + nwarp] = s;
                }
            }
        __syncthreads();
        float mu[2][2], rs[2][2];
#pragma unroll
        for (int mt = 0; mt < 2; mt++)
#pragma unroll
            for (int e = 0; e < 2; e++) {
                int row = mwarp * 32 + mt * 16 + (lane >> 2) + 8 * e;
                mu[mt][e] = (lnb[row * 2] + lnb[row * 2 + 1]) * (1.0f / 128.0f);
                float sq = 0.f;
#pragma unroll
                for (int idx = 0; idx < 8; idx++) {
                    float d0 = c[mt][idx][2 * e] - mu[mt][e];
                    float d1 = c[mt][idx][2 * e + 1] - mu[mt][e];
                    sq = fmaf(d0, d0, sq);
                    sq = fmaf(d1, d1, sq);
                }
                sq += __shfl_xor_sync(0xffffffffu, sq, 1);
                sq += __shfl_xor_sync(0xffffffffu, sq, 2);
                if ((lane & 3) == 0) lnb[256 + row * 2 + nwarp] = sq;
            }
        __syncthreads();
#pragma unroll
        for (int mt = 0; mt < 2; mt++)
#pragma unroll
            for (int e = 0; e < 2; e++) {
                int row = mwarp * 32 + mt * 16 + (lane >> 2) + 8 * e;
                rs[mt][e] = rsqrtf((lnb[256 + row * 2] + lnb[256 + row * 2 + 1]) *
                                       (1.0f / 128.0f) + EPSV);
            }

#pragma unroll
        for (int mt = 0; mt < 2; mt++)
#pragma unroll
            for (int e = 0; e < 2; e++) {
                int row = mwarp * 32 + mt * 16 + (lane >> 2) + 8 * e;
                int gr = blockRow + row;
                if (gr >= nRows) continue;
                float m = mu[mt][e], q = rs[mt][e];
                if (MSG) {
                    const int drow = idxs[row];
                    float* op = aggF + (size_t)drow * LAT;
#pragma unroll
                    for (int idx = 0; idx < 8; idx++) {
                        int col = nwarp * 64 + (idx >> 1) * 16 + (idx & 1) * 8 + 2 * (lane & 3);
                        float v0 = (c[mt][idx][2 * e]     - m) * q * Gs[col]     + BEs[col];
                        float v1 = (c[mt][idx][2 * e + 1] - m) * q * Gs[col + 1] + BEs[col + 1];
                        red2(&op[col], v0, v1);
                    }
                } else {
#pragma unroll
                    for (int idx = 0; idx < 8; idx++) {
                        int col = nwarp * 64 + (idx >> 1) * 16 + (idx & 1) * 8 + 2 * (lane & 3);
                        float v0 = (c[mt][idx][2 * e]     - m) * q * Gs[col]     + BEs[col];
                        float v1 = (c[mt][idx][2 * e + 1] - m) * q * Gs[col + 1] + BEs[col + 1];
                        uint32_t rh = *(const uint32_t*)&resHi[(size_t)gr * LAT + col];
                        uint32_t rl = *(const uint32_t*)&resLo[(size_t)gr * LAT + col];
                        v0 += recon(rh, 0) + recon(rl, 0);
                        v1 += recon(rh, 1) + recon(rl, 1);
                        uint32_t hi, lo;
                        split_pair(v0, v1, hi, lo);
                        *(uint32_t*)&outHi[(size_t)gr * LAT + col] = hi;
                        *(uint32_t*)&outLo[(size_t)gr * LAT + col] = lo;
                    }
                }
            }
        __syncthreads();
    }
}

// ============================================================================
// node_update (gnn_mma GMODE 2 specialization, round-9 code): 1 CTA/SM pipelined
// ============================================================================
#define OFF_BUF(b) ((b) * 65536)
#define OFF_H_HI   0
#define OFF_H_LO   32768
#define OFF_W2(c)  (65536 + (c) * 32768)
#define OFF_B1     132096
#define OFF_B2     132608
#define OFF_G      133120
#define OFF_BE     133632
#define OFF_LN     134144
#define SMEM_DYN   136192

__global__ __launch_bounds__(256, 1) void node_update(
    const float* __restrict__ aggF,
    const __nv_bfloat16* __restrict__ hHi, const __nv_bfloat16* __restrict__ hLo,
    const __nv_bfloat16* __restrict__ W1hi, const __nv_bfloat16* __restrict__ W1lo,
    const float* __restrict__ B1,
    const __nv_bfloat16* __restrict__ W2hi, const __nv_bfloat16* __restrict__ W2lo,
    const float* __restrict__ B2,
    const float* __restrict__ G, const float* __restrict__ BE,
    const __nv_bfloat16* __restrict__ resHi, const __nv_bfloat16* __restrict__ resLo,
    __nv_bfloat16* __restrict__ outHi, __nv_bfloat16* __restrict__ outLo, int nRows)
{
    extern __shared__ char smp[];
    const uint32_t sb = smem_u32(smp);
    const int tid = threadIdx.x;
    const int wid = tid >> 5, lane = tid & 31;
    const int mwarp = wid & 3, nwarp = wid >> 2;
    const int blockRow = blockIdx.x * 128;
    constexpr int KTOT = 256;

    float* b1s = (float*)(smp + OFF_B1);
    float* b2s = (float*)(smp + OFF_B2);
    float* Gs  = (float*)(smp + OFF_G);
    float* BEs = (float*)(smp + OFF_BE);
    float* lnb = (float*)(smp + OFF_LN);

    if (tid < 128) {
        b1s[tid] = B1[tid]; b2s[tid] = B2[tid];
        Gs[tid] = G[tid];   BEs[tid] = BE[tid];
    }
    __syncthreads();

    const int lrow = lane & 7, lg = lane >> 3;
    const uint32_t xm = (uint32_t)lrow << 4;
    const int a_row0 = mwarp * 32 + lrow + 8 * (lg & 1);
    const int a_kx = lg >> 1;
    const int b_row0 = nwarp * 64 + lrow + 8 * (lg >> 1);
    const int b_kx = lg & 1;

    float c[2][8][4];
#pragma unroll
    for (int mt = 0; mt < 2; mt++)
#pragma unroll
        for (int i = 0; i < 8; i++)
#pragma unroll
            for (int j = 0; j < 4; j++) c[mt][i][j] = 0.f;

    auto fill = [&](int ch) {
        const uint32_t bbase = sb + OFF_BUF(ch & 1);
        char* bptr = smp + OFF_BUF(ch & 1);
        if (ch < 2) {
            const int koff = ch * 64;
#pragma unroll
            for (int p = 0; p < 8; p++) {
                int idx = tid + 256 * p;
                int row = idx >> 4, f4 = idx & 15;
                int ri = min(blockRow + row, nRows - 1);
                float4 v = *(const float4*)&aggF[(size_t)ri * LAT + koff + f4 * 4];
                uint32_t h0, h1, l0, l1;
                split_pair(v.x, v.y, h0, l0);
                split_pair(v.z, v.w, h1, l1);
                uint32_t sw = swz((uint32_t)(row * 128 + f4 * 8));
                *(uint2*)(bptr + sw) = make_uint2(h0, h1);
                *(uint2*)(bptr + 16384 + sw) = make_uint2(l0, l1);
            }
        } else {
            const int koff = (ch - 2) * 64;
#pragma unroll
            for (int p = 0; p < 4; p++) {
                int idx = tid + 256 * p;
                int row = idx >> 3, q = idx & 7;
                int ri = min(blockRow + row, nRows - 1);
                size_t go = (size_t)ri * LAT + koff + q * 8;
                uint32_t sw = swz((uint32_t)(row * 128 + q * 16));
                cpa16(bbase + sw, hHi + go);
                cpa16(bbase + 16384 + sw, hLo + go);
            }
        }
#pragma unroll
        for (int p = 0; p < 4; p++) {
            int idx = tid + 256 * p;
            int row = idx >> 3, q = idx & 7;
            const size_t go = (size_t)row * KTOT + ch * 64 + q * 8;
            uint32_t sw = swz((uint32_t)(row * 128 + q * 16));
            cpa16(bbase + 32768 + sw, W1hi + go);
            cpa16(bbase + 49152 + sw, W1lo + go);
        }
    };
    auto fillW2 = [&]() {
#pragma unroll
        for (int p = 0; p < 8; p++) {
            int idx = tid + 256 * p;
            int row = idx >> 4, q = idx & 15;
            int c2 = q >> 3, qq = q & 7;
            size_t go = (size_t)row * 128 + c2 * 64 + qq * 8;
            uint32_t sw = swz((uint32_t)(row * 128 + qq * 16));
            cpa16(sb + OFF_W2(c2) + sw, W2hi + go);
            cpa16(sb + OFF_W2(c2) + 16384 + sw, W2lo + go);
        }
    };

    constexpr int NC = KTOT / 64;
    fill(0); CPA_COMMIT();
    fill(1); CPA_COMMIT();
    for (int ch = 0; ch < NC; ch++) {
        if (ch < NC - 1) CPA_WAIT(1);
        else CPA_WAIT(0);
        __syncthreads();
        const uint32_t bbase = sb + OFF_BUF(ch & 1);
#pragma unroll
        for (int ks = 0; ks < 4; ks++) {
            const uint32_t kcA = (uint32_t)((ks * 2 + a_kx) * 16) ^ xm;
            const uint32_t kcB = (uint32_t)((ks * 2 + b_kx) * 16) ^ xm;
            uint32_t ah[2][4], al[2][4];
#pragma unroll
            for (int mt = 0; mt < 2; mt++) {
                uint32_t ro = (uint32_t)((a_row0 + mt * 16) * 128);
                ldsm4(bbase + ro + kcA, ah[mt]);
                ldsm4(bbase + 16384 + ro + kcA, al[mt]);
            }
#pragma unroll
            for (int g = 0; g < 4; g++) {
                uint32_t bh[4], bl[4];
                uint32_t ro = (uint32_t)((b_row0 + g * 16) * 128);
                ldsm4(bbase + 32768 + ro + kcB, bh);
                ldsm4(bbase + 49152 + ro + kcB, bl);
#pragma unroll
                for (int mt = 0; mt < 2; mt++)
#pragma unroll
                    for (int hf = 0; hf < 2; hf++) {
                        float* cc = c[mt][g * 2 + hf];
                        mma_bf16(cc, ah[mt], &bh[hf * 2]);
                        mma_bf16(cc, ah[mt], &bl[hf * 2]);
                        mma_bf16(cc, al[mt], &bh[hf * 2]);
                    }
            }
        }
        __syncthreads();
        if (ch + 2 < NC) { fill(ch + 2); CPA_COMMIT(); }
    }
    fillW2();
    CPA_COMMIT();
#pragma unroll
    for (int mt = 0; mt < 2; mt++)
#pragma unroll
        for (int idx = 0; idx < 8; idx++)
#pragma unroll
            for (int e = 0; e < 2; e++) {
                int row = mwarp * 32 + mt * 16 + (lane >> 2) + 8 * e;
                int col = nwarp * 64 + (idx >> 1) * 16 + (idx & 1) * 8 + 2 * (lane & 3);
                float v0 = fmaxf(c[mt][idx][2 * e] + b1s[col], 0.f);
                float v1 = fmaxf(c[mt][idx][2 * e + 1] + b1s[col + 1], 0.f);
                uint32_t hi, lo;
                split_pair(v0, v1, hi, lo);
                uint32_t off = (uint32_t)(nwarp * 16384 + row * 128 +
                                          (((col & 63) * 2) ^ ((row & 7) << 4)));
                *(uint32_t*)(smp + OFF_H_HI + off) = hi;
                *(uint32_t*)(smp + OFF_H_LO + off) = lo;
            }
#pragma unroll
    for (int mt = 0; mt < 2; mt++)
#pragma unroll
        for (int i = 0; i < 8; i++)
#pragma unroll
            for (int j = 0; j < 4; j++) c[mt][i][j] = 0.f;
    CPA_WAIT(0);
    __syncthreads();

#pragma unroll
    for (int c2 = 0; c2 < 2; c2++) {
        const uint32_t abH = sb + OFF_H_HI + c2 * 16384;
        const uint32_t abL = sb + OFF_H_LO + c2 * 16384;
        const uint32_t wb = sb + OFF_W2(c2);
#pragma unroll
        for (int ks = 0; ks < 4; ks++) {
            const uint32_t kcA = (uint32_t)((ks * 2 + a_kx) * 16) ^ xm;
            const uint32_t kcB = (uint32_t)((ks * 2 + b_kx) * 16) ^ xm;
            uint32_t ah[2][4], al[2][4];
#pragma unroll
            for (int mt = 0; mt < 2; mt++) {
                uint32_t ro = (uint32_t)((a_row0 + mt * 16) * 128);
                ldsm4(abH + ro + kcA, ah[mt]);
                ldsm4(abL + ro + kcA, al[mt]);
            }
#pragma unroll
            for (int g = 0; g < 4; g++) {
                uint32_t bh[4], bl[4];
                uint32_t ro = (uint32_t)((b_row0 + g * 16) * 128);
                ldsm4(wb + ro + kcB, bh);
                ldsm4(wb + 16384 + ro + kcB, bl);
#pragma unroll
                for (int mt = 0; mt < 2; mt++)
#pragma unroll
                    for (int hf = 0; hf < 2; hf++) {
                        float* cc = c[mt][g * 2 + hf];
                        mma_bf16(cc, ah[mt], &bh[hf * 2]);
                        mma_bf16(cc, ah[mt], &bl[hf * 2]);
                        mma_bf16(cc, al[mt], &bh[hf * 2]);
                    }
            }
        }
    }

#pragma unroll
    for (int mt = 0; mt < 2; mt++)
#pragma unroll
        for (int idx = 0; idx < 8; idx++) {
            int col = nwarp * 64 + (idx >> 1) * 16 + (idx & 1) * 8 + 2 * (lane & 3);
#pragma unroll
            for (int j = 0; j < 4; j++)
                c[mt][idx][j] = fmaxf(c[mt][idx][j] + b2s[col + (j & 1)], 0.f);
        }

#pragma unroll
    for (int mt = 0; mt < 2; mt++)
#pragma unroll
        for (int e = 0; e < 2; e++) {
            float s = 0.f;
#pragma unroll
            for (int idx = 0; idx < 8; idx++)
                s += c[mt][idx][2 * e] + c[mt][idx][2 * e + 1];
            s += __shfl_xor_sync(0xffffffffu, s, 1);
            s += __shfl_xor_sync(0xffffffffu, s, 2);
            if ((lane & 3) == 0) {
                int row = mwarp * 32 + mt * 16 + (lane >> 2) + 8 * e;
                lnb[row * 2 + nwarp] = s;
            }
        }
    __syncthreads();
    float mu[2][2], rs[2][2];
#pragma unroll
    for (int mt = 0; mt < 2; mt++)
#pragma unroll
        for (int e = 0; e < 2; e++) {
            int row = mwarp * 32 + mt * 16 + (lane >> 2) + 8 * e;
            mu[mt][e] = (lnb[row * 2] + lnb[row * 2 + 1]) * (1.0f / 128.0f);
            float sq = 0.f;
#pragma unroll
            for (int idx = 0; idx < 8; idx++) {
                float d0 = c[mt][idx][2 * e] - mu[mt][e];
                float d1 = c[mt][idx][2 * e + 1] - mu[mt][e];
                sq = fmaf(d0, d0, sq);
                sq = fmaf(d1, d1, sq);
            }
            sq += __shfl_xor_sync(0xffffffffu, sq, 1);
            sq += __shfl_xor_sync(0xffffffffu, sq, 2);
            if ((lane & 3) == 0) lnb[256 + row * 2 + nwarp] = sq;
        }
    __syncthreads();
#pragma unroll
    for (int mt = 0; mt < 2; mt++)
#pragma unroll
        for (int e = 0; e < 2; e++) {
            int row = mwarp * 32 + mt * 16 + (lane >> 2) + 8 * e;
            rs[mt][e] = rsqrtf((lnb[256 + row * 2] + lnb[256 + row * 2 + 1]) *
                                   (1.0f / 128.0f) + EPSV);
        }

#pragma unroll
    for (int mt = 0; mt < 2; mt++)
#pragma unroll
        for (int e = 0; e < 2; e++) {
            int row = mwarp * 32 + mt * 16 + (lane >> 2) + 8 * e;
            int gr = blockRow + row;
            if (gr >= nRows) continue;
            float m = mu[mt][e], q = rs[mt][e];
#pragma unroll
            for (int idx = 0; idx < 8; idx++) {
                int col = nwarp * 64 + (idx >> 1) * 16 + (idx & 1) * 8 + 2 * (lane & 3);
                float v0 = (c[mt][idx][2 * e]     - m) * q * Gs[col]     + BEs[col];
                float v1 = (c[mt][idx][2 * e + 1] - m) * q * Gs[col + 1] + BEs[col + 1];
                uint32_t rh = *(const uint32_t*)&resHi[(size_t)gr * LAT + col];
                uint32_t rl = *(const uint32_t*)&resLo[(size_t)gr * LAT + col];
                v0 += recon(rh, 0) + recon(rl, 0);
                v1 += recon(rh, 1) + recon(rl, 1);
                uint32_t hi, lo;
                split_pair(v0, v1, hi, lo);
                *(uint32_t*)&outHi[(size_t)gr * LAT + col] = hi;
                *(uint32_t*)&outLo[(size_t)gr * LAT + col] = lo;
            }
        }
}

__global__ void prep_all(
    const float* __restrict__ s0, __nv_bfloat16* __restrict__ h0b, __nv_bfloat16* __restrict__ l0b,
    const float* __restrict__ s1, __nv_bfloat16* __restrict__ h1b, __nv_bfloat16* __restrict__ l1b,
    const float* __restrict__ s2, __nv_bfloat16* __restrict__ h2b, __nv_bfloat16* __restrict__ l2b,
    const float* __restrict__ s3, __nv_bfloat16* __restrict__ h3b, __nv_bfloat16* __restrict__ l3b,
    const float* __restrict__ s4, __nv_bfloat16* __restrict__ h4b, __nv_bfloat16* __restrict__ l4b,
    const float* __restrict__ s5, __nv_bfloat16* __restrict__ h5b, __nv_bfloat16* __restrict__ l5b)
{
    int i = blockIdx.x * blockDim.x + threadIdx.x;
    const float* W; __nv_bfloat16 *hi, *lo; int K, j;
    if (i < 49152)       { W = s0; hi = h0b; lo = l0b; K = 384; j = i; }
    else if (i < 65536)  { W = s1; hi = h1b; lo = l1b; K = 128; j = i - 49152; }
    else if (i < 98304)  { W = s2; hi = h2b; lo = l2b; K = 256; j = i - 65536; }
    else if (i < 114688) { W = s3; hi = h3b; lo = l3b; K = 128; j = i - 98304; }
    else if (i < 131072) { W = s4; hi = h4b; lo = l4b; K = 128; j = i - 114688; }
    else if (i < 147456) { W = s5; hi = h5b; lo = l5b; K = 128; j = i - 131072; }
    else return;
    int k = j >> 7, n = j & 127;
    float v = W[j];
    __nv_bfloat16 h = __float2bfloat16(v);
    hi[(size_t)n * K + k] = h;
    lo[(size_t)n * K + k] = __float2bfloat16(v - __bfloat162float(h));
}

__global__ __launch_bounds__(256) void decoder_kernel(
    const __nv_bfloat16* __restrict__ hHi, const __nv_bfloat16* __restrict__ hLo,
    const float* __restrict__ W1, const float* __restrict__ B1,
    const float* __restrict__ W2, const float* __restrict__ B2,
    float* __restrict__ out, int n)
{
    extern __shared__ float s[];
    float* W1s = s;
    float* hs = s + 128 * 128;
    int tid = threadIdx.x;
#pragma unroll
    for (int it = 0; it < 16; it++) {
        int f = tid + 256 * it;
        *(float4*)&W1s[f * 4] = *(const float4*)&W1[f * 4];
    }
    int warp = tid >> 5, lane = tid & 31;
    int row = blockIdx.x * 8 + warp;
    int rc = min(row, n - 1);
#pragma unroll
    for (int q = 0; q < 4; q++) {
        int cc = lane + 32 * q;
        hs[warp * 128 + cc] = __bfloat162float(hHi[(size_t)rc * LAT + cc]) +
                              __bfloat162float(hLo[(size_t)rc * LAT + cc]);
    }
    __syncthreads();

    float acc[4];
#pragma unroll
    for (int q = 0; q < 4; q++) acc[q] = B1[lane + 32 * q];
    for (int k = 0; k < 128; k++) {
        float hv = hs[warp * 128 + k];
#pragma unroll
        for (int q = 0; q < 4; q++)
            acc[q] = fmaf(hv, W1s[k * 128 + lane + 32 * q], acc[q]);
    }
#pragma unroll
    for (int q = 0; q < 4; q++) acc[q] = fmaxf(acc[q], 0.f);

    float o[3];
#pragma unroll
    for (int oo = 0; oo < 3; oo++) {
        float p = 0.f;
#pragma unroll
        for (int q = 0; q < 4; q++)
            p = fmaf(acc[q], W2[(size_t)(lane + 32 * q) * 3 + oo], p);
#pragma unroll
        for (int off = 16; off > 0; off >>= 1)
            p += __shfl_xor_sync(0xffffffffu, p, off);
        o[oo] = p;
    }
    if (lane == 0 && row < n) {
        out[(size_t)row * 3 + 0] = o[0] + B2[0];
        out[(size_t)row * 3 + 1] = o[1] + B2[1];
        out[(size_t)row * 3 + 2] = o[2] + B2[2];
    }
}

__global__ void zero_kernel(float4* __restrict__ p, int n4)
{
    int i = blockIdx.x * blockDim.x + threadIdx.x;
    if (i < n4) p[i] = make_float4(0.f, 0.f, 0.f, 0.f);
}

extern "C" void kernel_launch(void* const* d_in, const int* in_sizes, int n_in,
                              void* d_out, int out_size)
{
    (void)in_sizes; (void)n_in; (void)out_size;
    const float* x  = (const float*)d_in[0];
    const float* ea = (const float*)d_in[1];
    const int*   ei = (const int*)d_in[2];
    const int* src = ei;
    const int* dst = ei + NEDGES;

    const float* ne_w1 = (const float*)d_in[3];
    const float* ne_b1 = (const float*)d_in[4];
    const float* ne_w2 = (const float*)d_in[5];
    const float* ne_b2 = (const float*)d_in[6];
    const float* ne_g  = (const float*)d_in[7];
    const float* ne_be = (const float*)d_in[8];
    const float* ee_w1 = (const float*)d_in[9];
    const float* ee_b1 = (const float*)d_in[10];
    const float* ee_w2 = (const float*)d_in[11];
    const float* ee_b2 = (const float*)d_in[12];
    const float* ee_g  = (const float*)d_in[13];
    const float* ee_be = (const float*)d_in[14];
    const float* em_w1 = (const float*)d_in[15];
    const float* em_b1 = (const float*)d_in[16];
    const float* em_w2 = (const float*)d_in[17];
    const float* em_b2 = (const float*)d_in[18];
    const float* em_g  = (const float*)d_in[19];
    const float* em_be = (const float*)d_in[20];
    const float* nm_w1 = (const float*)d_in[21];
    const float* nm_b1 = (const float*)d_in[22];
    const float* nm_w2 = (const float*)d_in[23];
    const float* nm_b2 = (const float*)d_in[24];
    const float* nm_g  = (const float*)d_in[25];
    const float* nm_be = (const float*)d_in[26];
    const float* dw1   = (const float*)d_in[27];
    const float* db1   = (const float*)d_in[28];
    const float* dw2   = (const float*)d_in[29];
    const float* db2   = (const float*)d_in[30];

    float* fb = nullptr;
    cudaGetSymbolAddress((void**)&fb, g_fbuf);
    float* agg = fb;
    float* Y1 = fb + (size_t)NNODES * LAT;
    float* Y2 = fb + (size_t)2 * NNODES * LAT;
    float* Ye = fb + (size_t)3 * NNODES * LAT;

    __nv_bfloat16* hp = nullptr;
    cudaGetSymbolAddress((void**)&hp, g_hpl);
    __nv_bfloat16* ep = nullptr;
    cudaGetSymbolAddress((void**)&ep, g_epl);
    const size_t HS = (size_t)NNODES * LAT, ES = (size_t)NEDGES * LAT;
    __nv_bfloat16 *hH0 = hp, *hL0 = hp + HS, *hH1 = hp + 2 * HS, *hL1 = hp + 3 * HS;
    __nv_bfloat16 *eH0 = ep, *eL0 = ep + ES, *eH1 = ep + 2 * ES, *eL1 = ep + 3 * ES;

    __nv_bfloat16* pl = nullptr;
    cudaGetSymbolAddress((void**)&pl, g_planes);
    __nv_bfloat16* emW1h = pl;
    __nv_bfloat16* emW1l = pl + 49152;
    __nv_bfloat16* emW2h = pl + 98304;
    __nv_bfloat16* emW2l = pl + 114688;
    __nv_bfloat16* nmW1h = pl + 131072;
    __nv_bfloat16* nmW1l = pl + 163840;
    __nv_bfloat16* nmW2h = pl + 196608;
    __nv_bfloat16* nmW2l = pl + 212992;
    __nv_bfloat16* neW2h = pl + 229376;
    __nv_bfloat16* neW2l = pl + 245760;
    __nv_bfloat16* eeW2h = pl + 262144;
    __nv_bfloat16* eeW2l = pl + 278528;

    cudaFuncSetAttribute(node_update,
                         cudaFuncAttributeMaxDynamicSharedMemorySize, SMEM_DYN);
    cudaFuncSetAttribute(edge_fused,
                         cudaFuncAttributeMaxDynamicSharedMemorySize, SMEM_E);
    cudaFuncSetAttribute(gemm_s,
                         cudaFuncAttributeMaxDynamicSharedMemorySize, SMEM_S);
    cudaFuncSetAttribute(encode_mlp,
                         cudaFuncAttributeMaxDynamicSharedMemorySize, SMEM_N);
    const int DSM = (128 * 128 + 8 * 128) * (int)sizeof(float);
    cudaFuncSetAttribute(decoder_kernel,
                         cudaFuncAttributeMaxDynamicSharedMemorySize, DSM);

    prep_all<<<(147456 + 255) / 256, 256>>>(
        em_w1, emW1h, emW1l, em_w2, emW2h, emW2l,
        nm_w1, nmW1h, nmW1l, nm_w2, nmW2h, nmW2l,
        ne_w2, neW2h, neW2l, ee_w2, eeW2h, eeW2l);

    dim3 blk(256);
    const int ntiles = (NNODES + 127) / 128;  // 391
    const int etiles = NEDGES / 128;          // 3125

    encode_mlp<<<ntiles, blk, SMEM_N>>>(
        x, ne_w1, 3, ne_b1, neW2h, neW2l, ne_b2, ne_g, ne_be, hH0, hL0, NNODES);
    encode_mlp<<<etiles, blk, SMEM_N>>>(
        ea, ee_w1, 4, ee_b1, eeW2h, eeW2l, ee_b2, ee_g, ee_be, eH0, eL0, NEDGES);

    __nv_bfloat16 *hcH = hH0, *hcL = hL0, *hnH = hH1, *hnL = hL1;
    __nv_bfloat16 *ecH = eH0, *ecL = eL0, *enH = eH1, *enL = eL1;
    for (int s = 0; s < 5; s++) {
        gemm_s<<<ntiles, blk, SMEM_S>>>(hcH, hcL, emW1h, emW1l, 384, 0,
                                        nullptr, Y1, NNODES);
        gemm_s<<<ntiles, blk, SMEM_S>>>(hcH, hcL, emW1h, emW1l, 384, 128,
                                        nullptr, Y2, NNODES);
        gemm_s<<<etiles, blk, SMEM_S>>>(ecH, ecL, emW1h, emW1l, 384, 256,
                                        em_b1, Ye, NEDGES);
        zero_kernel<<<(NNODES * LAT / 4 + 255) / 256, 256>>>((float4*)agg,
                                                             NNODES * LAT / 4);
        edge_fused<<<etiles, blk, SMEM_E>>>(
            Y1, Y2, Ye, dst, src, emW2h, emW2l, em_b2, em_g, em_be,
            ecH, ecL, enH, enL, agg, NEDGES);
        node_update<<<ntiles, blk, SMEM_DYN>>>(
            agg, hcH, hcL, nmW1h, nmW1l, nm_b1, nmW2h, nmW2l, nm_b2, nm_g, nm_be,
            hcH, hcL, hnH, hnL, NNODES);
        __nv_bfloat16* t;
        t = hcH; hcH = hnH; hnH = t;
        t = hcL; hcL = hnL; hnL = t;
        t = ecH; ecH = enH; enH = t;
        t = ecL; ecL = enL; enL = t;
    }

    decoder_kernel<<<(NNODES + 7) / 8, blk, DSM>>>(
        hcH, hcL, dw1, db1, dw2, db2, (float*)d_out, NNODES);
}

// round 11
// speedup vs baseline: 3.3337x; 1.0186x over previous
#include <cuda_runtime.h>
#include <cuda_bf16.h>
#include <cstdint>
#include <cstddef>

#define LAT 128
#define NNODES 50000
#define NEDGES 400000
#define EPSV 1e-5f

// fp32: agg | Y12 [N,256] | Ye [E,128]
__device__ float g_fbuf[(size_t)(3 * NNODES + NEDGES) * LAT];
__device__ __align__(16) __nv_bfloat16 g_hpl[(size_t)4 * NNODES * LAT];
__device__ __align__(16) __nv_bfloat16 g_epl[(size_t)4 * NEDGES * LAT];
__device__ __align__(16) __nv_bfloat16 g_planes[294912];

__device__ __forceinline__ uint32_t smem_u32(const void* p) {
    uint32_t a;
    asm("{ .reg .u64 t; cvta.to.shared.u64 t, %1; cvt.u32.u64 %0, t; }" : "=r"(a) : "l"(p));
    return a;
}
__device__ __forceinline__ void ldsm4(uint32_t addr, uint32_t* r) {
    asm volatile("ldmatrix.sync.aligned.m8n8.x4.shared.b16 {%0,%1,%2,%3}, [%4];"
                 : "=r"(r[0]), "=r"(r[1]), "=r"(r[2]), "=r"(r[3]) : "r"(addr));
}
__device__ __forceinline__ void mma_bf16(float* d, const uint32_t* a, const uint32_t* b) {
    asm volatile("mma.sync.aligned.m16n8k16.row.col.f32.bf16.bf16.f32 "
                 "{%0,%1,%2,%3}, {%4,%5,%6,%7}, {%8,%9}, {%0,%1,%2,%3};"
                 : "+f"(d[0]), "+f"(d[1]), "+f"(d[2]), "+f"(d[3])
                 : "r"(a[0]), "r"(a[1]), "r"(a[2]), "r"(a[3]), "r"(b[0]), "r"(b[1]));
}
__device__ __forceinline__ void cpa16(uint32_t saddr, const void* g) {
    asm volatile("cp.async.cg.shared.global [%0], [%1], 16;"
                 :: "r"(saddr), "l"(g) : "memory");
}
#define CPA_COMMIT() asm volatile("cp.async.commit_group;" ::: "memory")
#define CPA_WAIT(N)  asm volatile("cp.async.wait_group %0;" :: "n"(N) : "memory")
__device__ __forceinline__ void red2(float* addr, float v0, float v1) {
    asm volatile("red.global.add.v2.f32 [%0], {%1, %2};"
                 :: "l"(addr), "f"(v0), "f"(v1) : "memory");
}
__device__ __forceinline__ uint32_t swz(uint32_t bo) { return bo ^ ((bo >> 3) & 0x70); }
__device__ __forceinline__ void split_pair(float a, float b, uint32_t& hi, uint32_t& lo) {
    __nv_bfloat16 ah = __float2bfloat16(a), bh = __float2bfloat16(b);
    __nv_bfloat162 hp; hp.x = ah; hp.y = bh;
    __nv_bfloat162 lp;
    lp.x = __float2bfloat16(a - __bfloat162float(ah));
    lp.y = __float2bfloat16(b - __bfloat162float(bh));
    hi = *reinterpret_cast<uint32_t*>(&hp);
    lo = *reinterpret_cast<uint32_t*>(&lp);
}
__device__ __forceinline__ float recon(uint32_t packed, int half) {
    __nv_bfloat162 v = *reinterpret_cast<__nv_bfloat162*>(&packed);
    return half ? __bfloat162float(v.y) : __bfloat162float(v.x);
}

// ============================================================================
// gemm_y12: Y12[r, 0:128] = h[r]@W1a ; Y12[r, 128:256] = h[r]@W1b  (no bias)
// A resident; W streamed in 4 chunks through one 32KB buffer. 2 CTAs/SM.
// ============================================================================
#define Y_A_HI 0
#define Y_A_LO 32768
#define Y_B_HI 65536
#define Y_B_LO 81920
#define SMEM_Y 98304

__global__ __launch_bounds__(256, 2) void gemm_y12(
    const __nv_bfloat16* __restrict__ aHi, const __nv_bfloat16* __restrict__ aLo,
    const __nv_bfloat16* __restrict__ bHi, const __nv_bfloat16* __restrict__ bLo,
    float* __restrict__ out, int nRows)
{
    extern __shared__ char smp[];
    const uint32_t sb = smem_u32(smp);
    const int tid = threadIdx.x;
    const int wid = tid >> 5, lane = tid & 31;
    const int mwarp = wid & 3, nwarp = wid >> 2;
    const int blockRow = blockIdx.x * 128;

#pragma unroll
    for (int p = 0; p < 8; p++) {
        int idx = tid + 256 * p;
        int row = idx >> 4, q = idx & 15;
        int c2 = q >> 3, qq = q & 7;
        int rc = min(blockRow + row, nRows - 1);
        size_t ga = (size_t)rc * 128 + q * 8;
        uint32_t sw = (uint32_t)(c2 * 16384) + swz((uint32_t)(row * 128 + qq * 16));
        cpa16(sb + Y_A_HI + sw, aHi + ga);
        cpa16(sb + Y_A_LO + sw, aLo + ga);
    }
    auto fillB = [&](int m) {
#pragma unroll
        for (int p = 0; p < 4; p++) {
            int idx = tid + 256 * p;
            int row = idx >> 3, qq = idx & 7;
            size_t gb = (size_t)row * 384 + m * 64 + qq * 8;
            uint32_t sw = swz((uint32_t)(row * 128 + qq * 16));
            cpa16(sb + Y_B_HI + sw, bHi + gb);
            cpa16(sb + Y_B_LO + sw, bLo + gb);
        }
    };
    fillB(0);
    CPA_COMMIT();

    const int lrow = lane & 7, lg = lane >> 3;
    const uint32_t xm = (uint32_t)lrow << 4;
    const int a_row0 = mwarp * 32 + lrow + 8 * (lg & 1);
    const int a_kx = lg >> 1;
    const int b_row0 = nwarp * 64 + lrow + 8 * (lg >> 1);
    const int b_kx = lg & 1;

    for (int blk = 0; blk < 2; blk++) {
        float c[2][8][4];
#pragma unroll
        for (int mt = 0; mt < 2; mt++)
#pragma unroll
            for (int i = 0; i < 8; i++)
#pragma unroll
                for (int j = 0; j < 4; j++) c[mt][i][j] = 0.f;

        for (int c2 = 0; c2 < 2; c2++) {
            CPA_WAIT(0);
            __syncthreads();
            const uint32_t abH = sb + Y_A_HI + c2 * 16384;
            const uint32_t abL = sb + Y_A_LO + c2 * 16384;
#pragma unroll
            for (int ks = 0; ks < 4; ks++) {
                const uint32_t kcA = (uint32_t)((ks * 2 + a_kx) * 16) ^ xm;
                const uint32_t kcB = (uint32_t)((ks * 2 + b_kx) * 16) ^ xm;
                uint32_t ah[2][4], al[2][4];
#pragma unroll
                for (int mt = 0; mt < 2; mt++) {
                    uint32_t ro = (uint32_t)((a_row0 + mt * 16) * 128);
                    ldsm4(abH + ro + kcA, ah[mt]);
                    ldsm4(abL + ro + kcA, al[mt]);
                }
#pragma unroll
                for (int g = 0; g < 4; g++) {
                    uint32_t bh[4], bl[4];
                    uint32_t ro = (uint32_t)((b_row0 + g * 16) * 128);
                    ldsm4(sb + Y_B_HI + ro + kcB, bh);
                    ldsm4(sb + Y_B_LO + ro + kcB, bl);
#pragma unroll
                    for (int mt = 0; mt < 2; mt++)
#pragma unroll
                        for (int hf = 0; hf < 2; hf++) {
                            float* cc = c[mt][g * 2 + hf];
                            mma_bf16(cc, ah[mt], &bh[hf * 2]);
                            mma_bf16(cc, ah[mt], &bl[hf * 2]);
                            mma_bf16(cc, al[mt], &bh[hf * 2]);
                        }
                }
            }
            __syncthreads();
            int m = blk * 2 + c2;
            if (m < 3) { fillB(m + 1); CPA_COMMIT(); }
        }

#pragma unroll
        for (int mt = 0; mt < 2; mt++)
#pragma unroll
            for (int e = 0; e < 2; e++) {
                int row = mwarp * 32 + mt * 16 + (lane >> 2) + 8 * e;
                int gr = blockRow + row;
                if (gr >= nRows) continue;
#pragma unroll
                for (int idx = 0; idx < 8; idx++) {
                    int col = nwarp * 64 + (idx >> 1) * 16 + (idx & 1) * 8 + 2 * (lane & 3);
                    float2 o;
                    o.x = c[mt][idx][2 * e];
                    o.y = c[mt][idx][2 * e + 1];
                    *(float2*)&out[(size_t)gr * 256 + blk * 128 + col] = o;
                }
            }
    }
}

// ============================================================================
// edge_fused: per 128-edge tile:
//  MSG : hid=relu(Y12[dst,:128]+Y12[src,128:]+Ye) -> LN -> red2 agg[dst]
//  EDGE: hid=relu(Y12[src,:128]+Y12[dst,128:]+Ye) -> LN + e -> planes
//  tail (doYe): Ye_next = e_new @ W1c + b1   (e_new splits reuse H buffer)
// ============================================================================
#define E_H_HI 0
#define E_H_LO 32768
#define E_W2   65536
#define E_IDX  98304
#define E_B2   99328
#define E_G    99840
#define E_BE   100352
#define E_B1   100864
#define E_LN   101376
#define SMEM_E 103424

__global__ __launch_bounds__(256, 2) void edge_fused(
    const float* __restrict__ Y12, float* __restrict__ Ye,
    const int* __restrict__ dst, const int* __restrict__ src,
    const __nv_bfloat16* __restrict__ W2hi, const __nv_bfloat16* __restrict__ W2lo,
    const float* __restrict__ B2, const float* __restrict__ G,
    const float* __restrict__ BE,
    const __nv_bfloat16* __restrict__ W1hi, const __nv_bfloat16* __restrict__ W1lo,
    const float* __restrict__ B1,
    const __nv_bfloat16* __restrict__ resHi, const __nv_bfloat16* __restrict__ resLo,
    __nv_bfloat16* __restrict__ outHi, __nv_bfloat16* __restrict__ outLo,
    float* __restrict__ aggF, int doYe, int nRows)
{
    extern __shared__ char smp[];
    const uint32_t sb = smem_u32(smp);
    const int tid = threadIdx.x;
    const int wid = tid >> 5, lane = tid & 31;
    const int mwarp = wid & 3, nwarp = wid >> 2;
    const int blockRow = blockIdx.x * 128;

    int* idxs = (int*)(smp + E_IDX);
    float* b2s = (float*)(smp + E_B2);
    float* Gs  = (float*)(smp + E_G);
    float* BEs = (float*)(smp + E_BE);
    float* b1s = (float*)(smp + E_B1);
    float* lnb = (float*)(smp + E_LN);

    if (tid < 128) {
        idxs[tid] = dst[min(blockRow + tid, nRows - 1)];
        b2s[tid] = B2[tid]; Gs[tid] = G[tid]; BEs[tid] = BE[tid];
        b1s[tid] = B1[tid];
    } else {
        idxs[tid] = src[min(blockRow + tid - 128, nRows - 1)];
    }
    __syncthreads();

    auto fillW2 = [&](int chunk) {
#pragma unroll
        for (int p = 0; p < 4; p++) {
            int idx = tid + 256 * p;
            int row = idx >> 3, qq = idx & 7;
            size_t go = (size_t)row * 128 + chunk * 64 + qq * 8;
            uint32_t sw = swz((uint32_t)(row * 128 + qq * 16));
            cpa16(sb + E_W2 + sw, W2hi + go);
            cpa16(sb + E_W2 + 16384 + sw, W2lo + go);
        }
    };
    auto fillW1c = [&](int chunk) {
#pragma unroll
        for (int p = 0; p < 4; p++) {
            int idx = tid + 256 * p;
            int row = idx >> 3, qq = idx & 7;
            size_t go = (size_t)row * 384 + 256 + chunk * 64 + qq * 8;
            uint32_t sw = swz((uint32_t)(row * 128 + qq * 16));
            cpa16(sb + E_W2 + sw, W1hi + go);
            cpa16(sb + E_W2 + 16384 + sw, W1lo + go);
        }
    };
    fillW2(0); CPA_COMMIT();

    const int lrow = lane & 7, lg = lane >> 3;
    const uint32_t xm = (uint32_t)lrow << 4;
    const int a_row0 = mwarp * 32 + lrow + 8 * (lg & 1);
    const int a_kx = lg >> 1;
    const int b_row0 = nwarp * 64 + lrow + 8 * (lg >> 1);
    const int b_kx = lg & 1;

    for (int ph = 0; ph < 2; ph++) {
        const bool MSG = (ph == 0);
        // H fill
#pragma unroll 4
        for (int p = 0; p < 16; p++) {
            int idx = tid + 256 * p;
            int row = idx >> 5, qf = idx & 31;
            int col = qf * 4;
            int gr = min(blockRow + row, nRows - 1);
            int riA = MSG ? idxs[row] : idxs[128 + row];
            int riB = MSG ? idxs[128 + row] : idxs[row];
            float4 a = *(const float4*)&Y12[(size_t)riA * 256 + col];
            float4 b = *(const float4*)&Y12[(size_t)riB * 256 + 128 + col];
            float4 e4 = *(const float4*)&Ye[(size_t)gr * 128 + col];
            float v0 = fmaxf(a.x + b.x + e4.x, 0.f);
            float v1 = fmaxf(a.y + b.y + e4.y, 0.f);
            float v2 = fmaxf(a.z + b.z + e4.z, 0.f);
            float v3 = fmaxf(a.w + b.w + e4.w, 0.f);
            uint32_t h0, h1, l0, l1;
            split_pair(v0, v1, h0, l0);
            split_pair(v2, v3, h1, l1);
            uint32_t off = (uint32_t)((col >> 6) * 16384) +
                           swz((uint32_t)(row * 128 + (col & 63) * 2));
            *(uint2*)(smp + E_H_HI + off) = make_uint2(h0, h1);
            *(uint2*)(smp + E_H_LO + off) = make_uint2(l0, l1);
        }

        float c[2][8][4];
#pragma unroll
        for (int mt = 0; mt < 2; mt++)
#pragma unroll
            for (int i = 0; i < 8; i++)
#pragma unroll
                for (int j = 0; j < 4; j++) c[mt][i][j] = 0.f;

        for (int c2 = 0; c2 < 2; c2++) {
            CPA_WAIT(0);
            __syncthreads();
            const uint32_t abH = sb + E_H_HI + c2 * 16384;
            const uint32_t abL = sb + E_H_LO + c2 * 16384;
#pragma unroll
            for (int ks = 0; ks < 4; ks++) {
                const uint32_t kcA = (uint32_t)((ks * 2 + a_kx) * 16) ^ xm;
                const uint32_t kcB = (uint32_t)((ks * 2 + b_kx) * 16) ^ xm;
                uint32_t ah[2][4], al[2][4];
#pragma unroll
                for (int mt = 0; mt < 2; mt++) {
                    uint32_t ro = (uint32_t)((a_row0 + mt * 16) * 128);
                    ldsm4(abH + ro + kcA, ah[mt]);
                    ldsm4(abL + ro + kcA, al[mt]);
                }
#pragma unroll
                for (int g = 0; g < 4; g++) {
                    uint32_t bh[4], bl[4];
                    uint32_t ro = (uint32_t)((b_row0 + g * 16) * 128);
                    ldsm4(sb + E_W2 + ro + kcB, bh);
                    ldsm4(sb + E_W2 + 16384 + ro + kcB, bl);
#pragma unroll
                    for (int mt = 0; mt < 2; mt++)
#pragma unroll
                        for (int hf = 0; hf < 2; hf++) {
                            float* cc = c[mt][g * 2 + hf];
                            mma_bf16(cc, ah[mt], &bh[hf * 2]);
                            mma_bf16(cc, ah[mt], &bl[hf * 2]);
                            mma_bf16(cc, al[mt], &bh[hf * 2]);
                        }
                }
            }
            __syncthreads();
            if (c2 == 0) { fillW2(1); CPA_COMMIT(); }
            else if (MSG) { fillW2(0); CPA_COMMIT(); }
            else if (doYe) { fillW1c(0); CPA_COMMIT(); }
        }

        // bias2 + ReLU
#pragma unroll
        for (int mt = 0; mt < 2; mt++)
#pragma unroll
            for (int idx = 0; idx < 8; idx++) {
                int col = nwarp * 64 + (idx >> 1) * 16 + (idx & 1) * 8 + 2 * (lane & 3);
#pragma unroll
                for (int j = 0; j < 4; j++)
                    c[mt][idx][j] = fmaxf(c[mt][idx][j] + b2s[col + (j & 1)], 0.f);
            }

        // LayerNorm
#pragma unroll
        for (int mt = 0; mt < 2; mt++)
#pragma unroll
            for (int e = 0; e < 2; e++) {
                float s = 0.f;
#pragma unroll
                for (int idx = 0; idx < 8; idx++)
                    s += c[mt][idx][2 * e] + c[mt][idx][2 * e + 1];
                s += __shfl_xor_sync(0xffffffffu, s, 1);
                s += __shfl_xor_sync(0xffffffffu, s, 2);
                if ((lane & 3) == 0) {
                    int row = mwarp * 32 + mt * 16 + (lane >> 2) + 8 * e;
                    lnb[row * 2 + nwarp] = s;
                }
            }
        __syncthreads();
        float mu[2][2], rs[2][2];
#pragma unroll
        for (int mt = 0; mt < 2; mt++)
#pragma unroll
            for (int e = 0; e < 2; e++) {
                int row = mwarp * 32 + mt * 16 + (lane >> 2) + 8 * e;
                mu[mt][e] = (lnb[row * 2] + lnb[row * 2 + 1]) * (1.0f / 128.0f);
                float sq = 0.f;
#pragma unroll
                for (int idx = 0; idx < 8; idx++) {
                    float d0 = c[mt][idx][2 * e] - mu[mt][e];
                    float d1 = c[mt][idx][2 * e + 1] - mu[mt][e];
                    sq = fmaf(d0, d0, sq);
                    sq = fmaf(d1, d1, sq);
                }
                sq += __shfl_xor_sync(0xffffffffu, sq, 1);
                sq += __shfl_xor_sync(0xffffffffu, sq, 2);
                if ((lane & 3) == 0) lnb[256 + row * 2 + nwarp] = sq;
            }
        __syncthreads();
#pragma unroll
        for (int mt = 0; mt < 2; mt++)
#pragma unroll
            for (int e = 0; e < 2; e++) {
                int row = mwarp * 32 + mt * 16 + (lane >> 2) + 8 * e;
                rs[mt][e] = rsqrtf((lnb[256 + row * 2] + lnb[256 + row * 2 + 1]) *
                                       (1.0f / 128.0f) + EPSV);
            }

        // output
#pragma unroll
        for (int mt = 0; mt < 2; mt++)
#pragma unroll
            for (int e = 0; e < 2; e++) {
                int row = mwarp * 32 + mt * 16 + (lane >> 2) + 8 * e;
                int gr = blockRow + row;
                if (gr >= nRows) continue;
                float m = mu[mt][e], q = rs[mt][e];
                if (MSG) {
                    const int drow = idxs[row];
                    float* op = aggF + (size_t)drow * LAT;
#pragma unroll
                    for (int idx = 0; idx < 8; idx++) {
                        int col = nwarp * 64 + (idx >> 1) * 16 + (idx & 1) * 8 + 2 * (lane & 3);
                        float v0 = (c[mt][idx][2 * e]     - m) * q * Gs[col]     + BEs[col];
                        float v1 = (c[mt][idx][2 * e + 1] - m) * q * Gs[col + 1] + BEs[col + 1];
                        red2(&op[col], v0, v1);
                    }
                } else {
#pragma unroll
                    for (int idx = 0; idx < 8; idx++) {
                        int col = nwarp * 64 + (idx >> 1) * 16 + (idx & 1) * 8 + 2 * (lane & 3);
                        float v0 = (c[mt][idx][2 * e]     - m) * q * Gs[col]     + BEs[col];
                        float v1 = (c[mt][idx][2 * e + 1] - m) * q * Gs[col + 1] + BEs[col + 1];
                        uint32_t rh = *(const uint32_t*)&resHi[(size_t)gr * LAT + col];
                        uint32_t rl = *(const uint32_t*)&resLo[(size_t)gr * LAT + col];
                        v0 += recon(rh, 0) + recon(rl, 0);
                        v1 += recon(rh, 1) + recon(rl, 1);
                        uint32_t hi, lo;
                        split_pair(v0, v1, hi, lo);
                        *(uint32_t*)&outHi[(size_t)gr * LAT + col] = hi;
                        *(uint32_t*)&outLo[(size_t)gr * LAT + col] = lo;
                        // stash e_new splits in H buffer for the Ye tail
                        uint32_t off = (uint32_t)((col >> 6) * 16384) +
                                       swz((uint32_t)(row * 128 + (col & 63) * 2));
                        *(uint32_t*)(smp + E_H_HI + off) = hi;
                        *(uint32_t*)(smp + E_H_LO + off) = lo;
                    }
                }
            }
        __syncthreads();
    }

    // ---- Ye tail: Ye_next = e_new @ W1c + b1 ----
    if (doYe) {
        float c[2][8][4];
#pragma unroll
        for (int mt = 0; mt < 2; mt++)
#pragma unroll
            for (int i = 0; i < 8; i++)
#pragma unroll
                for (int j = 0; j < 4; j++) c[mt][i][j] = 0.f;

        for (int k2 = 0; k2 < 2; k2++) {
            CPA_WAIT(0);
            __syncthreads();
            const uint32_t abH = sb + E_H_HI + k2 * 16384;
            const uint32_t abL = sb + E_H_LO + k2 * 16384;
#pragma unroll
            for (int ks = 0; ks < 4; ks++) {
                const uint32_t kcA = (uint32_t)((ks * 2 + a_kx) * 16) ^ xm;
                const uint32_t kcB = (uint32_t)((ks * 2 + b_kx) * 16) ^ xm;
                uint32_t ah[2][4], al[2][4];
#pragma unroll
                for (int mt = 0; mt < 2; mt++) {
                    uint32_t ro = (uint32_t)((a_row0 + mt * 16) * 128);
                    ldsm4(abH + ro + kcA, ah[mt]);
                    ldsm4(abL + ro + kcA, al[mt]);
                }
#pragma unroll
                for (int g = 0; g < 4; g++) {
                    uint32_t bh[4], bl[4];
                    uint32_t ro = (uint32_t)((b_row0 + g * 16) * 128);
                    ldsm4(sb + E_W2 + ro + kcB, bh);
                    ldsm4(sb + E_W2 + 16384 + ro + kcB, bl);
#pragma unroll
                    for (int mt = 0; mt < 2; mt++)
#pragma unroll
                        for (int hf = 0; hf < 2; hf++) {
                            float* cc = c[mt][g * 2 + hf];
                            mma_bf16(cc, ah[mt], &bh[hf * 2]);
                            mma_bf16(cc, ah[mt], &bl[hf * 2]);
                            mma_bf16(cc, al[mt], &bh[hf * 2]);
                        }
                }
            }
            __syncthreads();
            if (k2 == 0) { fillW1c(1); CPA_COMMIT(); }
        }
#pragma unroll
        for (int mt = 0; mt < 2; mt++)
#pragma unroll
            for (int e = 0; e < 2; e++) {
                int row = mwarp * 32 + mt * 16 + (lane >> 2) + 8 * e;
                int gr = blockRow + row;
                if (gr >= nRows) continue;
#pragma unroll
                for (int idx = 0; idx < 8; idx++) {
                    int col = nwarp * 64 + (idx >> 1) * 16 + (idx & 1) * 8 + 2 * (lane & 3);
                    float2 o;
                    o.x = c[mt][idx][2 * e] + b1s[col];
                    o.y = c[mt][idx][2 * e + 1] + b1s[col + 1];
                    *(float2*)&Ye[(size_t)gr * 128 + col] = o;
                }
            }
    }
}

// ============================================================================
// encode_mlp: SIMT layer1 -> streamed-W2 layer2 -> LN -> planes [+Ye tail]
// ============================================================================
#define N_H_HI 0
#define N_H_LO 32768
#define N_W2   65536
#define N_B1   98304
#define N_B2   98816
#define N_G    99328
#define N_BE   99840
#define N_LN   100352
#define N_W1R  102400
#define N_EB1  104448
#define SMEM_N 104960

__global__ __launch_bounds__(256, 2) void encode_mlp(
    const float* __restrict__ raw, const float* __restrict__ W1raw, int kreal,
    const float* __restrict__ B1,
    const __nv_bfloat16* __restrict__ W2hi, const __nv_bfloat16* __restrict__ W2lo,
    const float* __restrict__ B2,
    const float* __restrict__ G, const float* __restrict__ BE,
    const __nv_bfloat16* __restrict__ eW1hi, const __nv_bfloat16* __restrict__ eW1lo,
    const float* __restrict__ eB1, float* __restrict__ Ye, int doYe,
    __nv_bfloat16* __restrict__ outHi, __nv_bfloat16* __restrict__ outLo, int nRows)
{
    extern __shared__ char smp[];
    const uint32_t sb = smem_u32(smp);
    const int tid = threadIdx.x;
    const int wid = tid >> 5, lane = tid & 31;
    const int mwarp = wid & 3, nwarp = wid >> 2;
    const int blockRow = blockIdx.x * 128;

    float* b1s = (float*)(smp + N_B1);
    float* b2s = (float*)(smp + N_B2);
    float* Gs  = (float*)(smp + N_G);
    float* BEs = (float*)(smp + N_BE);
    float* lnb = (float*)(smp + N_LN);
    float* w1r = (float*)(smp + N_W1R);
    float* eb1 = (float*)(smp + N_EB1);

    if (tid < 128) {
        b1s[tid] = B1[tid]; b2s[tid] = B2[tid];
        Gs[tid] = G[tid];   BEs[tid] = BE[tid];
        if (doYe) eb1[tid] = eB1[tid];
    }
    for (int i = tid; i < kreal * 128; i += 256) w1r[i] = W1raw[i];
    __syncthreads();

    auto fillW2 = [&](int chunk) {
#pragma unroll
        for (int p = 0; p < 4; p++) {
            int idx = tid + 256 * p;
            int row = idx >> 3, qq = idx & 7;
            size_t go = (size_t)row * 128 + chunk * 64 + qq * 8;
            uint32_t sw = swz((uint32_t)(row * 128 + qq * 16));
            cpa16(sb + N_W2 + sw, W2hi + go);
            cpa16(sb + N_W2 + 16384 + sw, W2lo + go);
        }
    };
    auto fillW1c = [&](int chunk) {
#pragma unroll
        for (int p = 0; p < 4; p++) {
            int idx = tid + 256 * p;
            int row = idx >> 3, qq = idx & 7;
            size_t go = (size_t)row * 384 + 256 + chunk * 64 + qq * 8;
            uint32_t sw = swz((uint32_t)(row * 128 + qq * 16));
            cpa16(sb + N_W2 + sw, eW1hi + go);
            cpa16(sb + N_W2 + 16384 + sw, eW1lo + go);
        }
    };
    fillW2(0); CPA_COMMIT();

    // SIMT layer1 -> H planes
#pragma unroll 4
    for (int p = 0; p < 16; p++) {
        int idx = tid + 256 * p;
        int row = idx >> 5, qf = idx & 31;
        int col = qf * 4;
        int rc = min(blockRow + row, nRows - 1);
        float xv[4];
#pragma unroll
        for (int k = 0; k < 4; k++)
            xv[k] = (k < kreal) ? raw[(size_t)rc * kreal + k] : 0.f;
        float v[4];
#pragma unroll
        for (int j = 0; j < 4; j++) {
            float acc = b1s[col + j];
            for (int k = 0; k < kreal; k++)
                acc = fmaf(xv[k], w1r[k * 128 + col + j], acc);
            v[j] = fmaxf(acc, 0.f);
        }
        uint32_t h0, h1, l0, l1;
        split_pair(v[0], v[1], h0, l0);
        split_pair(v[2], v[3], h1, l1);
        uint32_t off = (uint32_t)((col >> 6) * 16384) +
                       swz((uint32_t)(row * 128 + (col & 63) * 2));
        *(uint2*)(smp + N_H_HI + off) = make_uint2(h0, h1);
        *(uint2*)(smp + N_H_LO + off) = make_uint2(l0, l1);
    }

    const int lrow = lane & 7, lg = lane >> 3;
    const uint32_t xm = (uint32_t)lrow << 4;
    const int a_row0 = mwarp * 32 + lrow + 8 * (lg & 1);
    const int a_kx = lg >> 1;
    const int b_row0 = nwarp * 64 + lrow + 8 * (lg >> 1);
    const int b_kx = lg & 1;

    float c[2][8][4];
#pragma unroll
    for (int mt = 0; mt < 2; mt++)
#pragma unroll
        for (int i = 0; i < 8; i++)
#pragma unroll
            for (int j = 0; j < 4; j++) c[mt][i][j] = 0.f;

    for (int c2 = 0; c2 < 2; c2++) {
        CPA_WAIT(0);
        __syncthreads();
        const uint32_t abH = sb + N_H_HI + c2 * 16384;
        const uint32_t abL = sb + N_H_LO + c2 * 16384;
#pragma unroll
        for (int ks = 0; ks < 4; ks++) {
            const uint32_t kcA = (uint32_t)((ks * 2 + a_kx) * 16) ^ xm;
            const uint32_t kcB = (uint32_t)((ks * 2 + b_kx) * 16) ^ xm;
            uint32_t ah[2][4], al[2][4];
#pragma unroll
            for (int mt = 0; mt < 2; mt++) {
                uint32_t ro = (uint32_t)((a_row0 + mt * 16) * 128);
                ldsm4(abH + ro + kcA, ah[mt]);
                ldsm4(abL + ro + kcA, al[mt]);
            }
#pragma unroll
            for (int g = 0; g < 4; g++) {
                uint32_t bh[4], bl[4];
                uint32_t ro = (uint32_t)((b_row0 + g * 16) * 128);
                ldsm4(sb + N_W2 + ro + kcB, bh);
                ldsm4(sb + N_W2 + 16384 + ro + kcB, bl);
#pragma unroll
                for (int mt = 0; mt < 2; mt++)
#pragma unroll
                    for (int hf = 0; hf < 2; hf++) {
                        float* cc = c[mt][g * 2 + hf];
                        mma_bf16(cc, ah[mt], &bh[hf * 2]);
                        mma_bf16(cc, ah[mt], &bl[hf * 2]);
                        mma_bf16(cc, al[mt], &bh[hf * 2]);
                    }
            }
        }
        __syncthreads();
        if (c2 == 0) { fillW2(1); CPA_COMMIT(); }
        else if (doYe) { fillW1c(0); CPA_COMMIT(); }
    }

#pragma unroll
    for (int mt = 0; mt < 2; mt++)
#pragma unroll
        for (int idx = 0; idx < 8; idx++) {
            int col = nwarp * 64 + (idx >> 1) * 16 + (idx & 1) * 8 + 2 * (lane & 3);
#pragma unroll
            for (int j = 0; j < 4; j++)
                c[mt][idx][j] = fmaxf(c[mt][idx][j] + b2s[col + (j & 1)], 0.f);
        }
#pragma unroll
    for (int mt = 0; mt < 2; mt++)
#pragma unroll
        for (int e = 0; e < 2; e++) {
            float s = 0.f;
#pragma unroll
            for (int idx = 0; idx < 8; idx++)
                s += c[mt][idx][2 * e] + c[mt][idx][2 * e + 1];
            s += __shfl_xor_sync(0xffffffffu, s, 1);
            s += __shfl_xor_sync(0xffffffffu, s, 2);
            if ((lane & 3) == 0) {
                int row = mwarp * 32 + mt * 16 + (lane >> 2) + 8 * e;
                lnb[row * 2 + nwarp] = s;
            }
        }
    __syncthreads();
    float mu[2][2], rs[2][2];
#pragma unroll
    for (int mt = 0; mt < 2; mt++)
#pragma unroll
        for (int e = 0; e < 2; e++) {
            int row = mwarp * 32 + mt * 16 + (lane >> 2) + 8 * e;
            mu[mt][e] = (lnb[row * 2] + lnb[row * 2 + 1]) * (1.0f / 128.0f);
            float sq = 0.f;
#pragma unroll
            for (int idx = 0; idx < 8; idx++) {
                float d0 = c[mt][idx][2 * e] - mu[mt][e];
                float d1 = c[mt][idx][2 * e + 1] - mu[mt][e];
                sq = fmaf(d0, d0, sq);
                sq = fmaf(d1, d1, sq);
            }
            sq += __shfl_xor_sync(0xffffffffu, sq, 1);
            sq += __shfl_xor_sync(0xffffffffu, sq, 2);
            if ((lane & 3) == 0) lnb[256 + row * 2 + nwarp] = sq;
        }
    __syncthreads();
#pragma unroll
    for (int mt = 0; mt < 2; mt++)
#pragma unroll
        for (int e = 0; e < 2; e++) {
            int row = mwarp * 32 + mt * 16 + (lane >> 2) + 8 * e;
            rs[mt][e] = rsqrtf((lnb[256 + row * 2] + lnb[256 + row * 2 + 1]) *
                                   (1.0f / 128.0f) + EPSV);
        }
#pragma unroll
    for (int mt = 0; mt < 2; mt++)
#pragma unroll
        for (int e = 0; e < 2; e++) {
            int row = mwarp * 32 + mt * 16 + (lane >> 2) + 8 * e;
            int gr = blockRow + row;
            if (gr >= nRows) continue;
            float m = mu[mt][e], q = rs[mt][e];
#pragma unroll
            for (int idx = 0; idx < 8; idx++) {
                int col = nwarp * 64 + (idx >> 1) * 16 + (idx & 1) * 8 + 2 * (lane & 3);
                float v0 = (c[mt][idx][2 * e]     - m) * q * Gs[col]     + BEs[col];
                float v1 = (c[mt][idx][2 * e + 1] - m) * q * Gs[col + 1] + BEs[col + 1];
                uint32_t hi, lo;
                split_pair(v0, v1, hi, lo);
                *(uint32_t*)&outHi[(size_t)gr * LAT + col] = hi;
                *(uint32_t*)&outLo[(size_t)gr * LAT + col] = lo;
                if (doYe) {
                    uint32_t off = (uint32_t)((col >> 6) * 16384) +
                                   swz((uint32_t)(row * 128 + (col & 63) * 2));
                    *(uint32_t*)(smp + N_H_HI + off) = hi;
                    *(uint32_t*)(smp + N_H_LO + off) = lo;
                }
            }
        }
    __syncthreads();

    if (doYe) {
#pragma unroll
        for (int mt = 0; mt < 2; mt++)
#pragma unroll
            for (int i = 0; i < 8; i++)
#pragma unroll
                for (int j = 0; j < 4; j++) c[mt][i][j] = 0.f;
        for (int k2 = 0; k2 < 2; k2++) {
            CPA_WAIT(0);
            __syncthreads();
            const uint32_t abH = sb + N_H_HI + k2 * 16384;
            const uint32_t abL = sb + N_H_LO + k2 * 16384;
#pragma unroll
            for (int ks = 0; ks < 4; ks++) {
                const uint32_t kcA = (uint32_t)((ks * 2 + a_kx) * 16) ^ xm;
                const uint32_t kcB = (uint32_t)((ks * 2 + b_kx) * 16) ^ xm;
                uint32_t ah[2][4], al[2][4];
#pragma unroll
                for (int mt = 0; mt < 2; mt++) {
                    uint32_t ro = (uint32_t)((a_row0 + mt * 16) * 128);
                    ldsm4(abH + ro + kcA, ah[mt]);
                    ldsm4(abL + ro + kcA, al[mt]);
                }
#pragma unroll
                for (int g = 0; g < 4; g++) {
                    uint32_t bh[4], bl[4];
                    uint32_t ro = (uint32_t)((b_row0 + g * 16) * 128);
                    ldsm4(sb + N_W2 + ro + kcB, bh);
                    ldsm4(sb + N_W2 + 16384 + ro + kcB, bl);
#pragma unroll
                    for (int mt = 0; mt < 2; mt++)
#pragma unroll
                        for (int hf = 0; hf < 2; hf++) {
                            float* cc = c[mt][g * 2 + hf];
                            mma_bf16(cc, ah[mt], &bh[hf * 2]);
                            mma_bf16(cc, ah[mt], &bl[hf * 2]);
                            mma_bf16(cc, al[mt], &bh[hf * 2]);
                        }
                }
            }
            __syncthreads();
            if (k2 == 0) { fillW1c(1); CPA_COMMIT(); }
        }
#pragma unroll
        for (int mt = 0; mt < 2; mt++)
#pragma unroll
            for (int e = 0; e < 2; e++) {
                int row = mwarp * 32 + mt * 16 + (lane >> 2) + 8 * e;
                int gr = blockRow + row;
                if (gr >= nRows) continue;
#pragma unroll
                for (int idx = 0; idx < 8; idx++) {
                    int col = nwarp * 64 + (idx >> 1) * 16 + (idx & 1) * 8 + 2 * (lane & 3);
                    float2 o;
                    o.x = c[mt][idx][2 * e] + eb1[col];
                    o.y = c[mt][idx][2 * e + 1] + eb1[col + 1];
                    *(float2*)&Ye[(size_t)gr * 128 + col] = o;
                }
            }
    }
}

// ============================================================================
// node_update (unchanged, 1 CTA/SM pipelined)
// ============================================================================
#define OFF_BUF(b) ((b) * 65536)
#define OFF_H_HI   0
#define OFF_H_LO   32768
#define OFF_W2(c)  (65536 + (c) * 32768)
#define OFF_B1     132096
#define OFF_B2     132608
#define OFF_G      133120
#define OFF_BE     133632
#define OFF_LN     134144
#define SMEM_DYN   136192

__global__ __launch_bounds__(256, 1) void node_update(
    const float* __restrict__ aggF,
    const __nv_bfloat16* __restrict__ hHi, const __nv_bfloat16* __restrict__ hLo,
    const __nv_bfloat16* __restrict__ W1hi, const __nv_bfloat16* __restrict__ W1lo,
    const float* __restrict__ B1,
    const __nv_bfloat16* __restrict__ W2hi, const __nv_bfloat16* __restrict__ W2lo,
    const float* __restrict__ B2,
    const float* __restrict__ G, const float* __restrict__ BE,
    const __nv_bfloat16* __restrict__ resHi, const __nv_bfloat16* __restrict__ resLo,
    __nv_bfloat16* __restrict__ outHi, __nv_bfloat16* __restrict__ outLo, int nRows)
{
    extern __shared__ char smp[];
    const uint32_t sb = smem_u32(smp);
    const int tid = threadIdx.x;
    const int wid = tid >> 5, lane = tid & 31;
    const int mwarp = wid & 3, nwarp = wid >> 2;
    const int blockRow = blockIdx.x * 128;
    constexpr int KTOT = 256;

    float* b1s = (float*)(smp + OFF_B1);
    float* b2s = (float*)(smp + OFF_B2);
    float* Gs  = (float*)(smp + OFF_G);
    float* BEs = (float*)(smp + OFF_BE);
    float* lnb = (float*)(smp + OFF_LN);

    if (tid < 128) {
        b1s[tid] = B1[tid]; b2s[tid] = B2[tid];
        Gs[tid] = G[tid];   BEs[tid] = BE[tid];
    }
    __syncthreads();

    const int lrow = lane & 7, lg = lane >> 3;
    const uint32_t xm = (uint32_t)lrow << 4;
    const int a_row0 = mwarp * 32 + lrow + 8 * (lg & 1);
    const int a_kx = lg >> 1;
    const int b_row0 = nwarp * 64 + lrow + 8 * (lg >> 1);
    const int b_kx = lg & 1;

    float c[2][8][4];
#pragma unroll
    for (int mt = 0; mt < 2; mt++)
#pragma unroll
        for (int i = 0; i < 8; i++)
#pragma unroll
            for (int j = 0; j < 4; j++) c[mt][i][j] = 0.f;

    auto fill = [&](int ch) {
        const uint32_t bbase = sb + OFF_BUF(ch & 1);
        char* bptr = smp + OFF_BUF(ch & 1);
        if (ch < 2) {
            const int koff = ch * 64;
#pragma unroll
            for (int p = 0; p < 8; p++) {
                int idx = tid + 256 * p;
                int row = idx >> 4, f4 = idx & 15;
                int ri = min(blockRow + row, nRows - 1);
                float4 v = *(const float4*)&aggF[(size_t)ri * LAT + koff + f4 * 4];
                uint32_t h0, h1, l0, l1;
                split_pair(v.x, v.y, h0, l0);
                split_pair(v.z, v.w, h1, l1);
                uint32_t sw = swz((uint32_t)(row * 128 + f4 * 8));
                *(uint2*)(bptr + sw) = make_uint2(h0, h1);
                *(uint2*)(bptr + 16384 + sw) = make_uint2(l0, l1);
            }
        } else {
            const int koff = (ch - 2) * 64;
#pragma unroll
            for (int p = 0; p < 4; p++) {
                int idx = tid + 256 * p;
                int row = idx >> 3, q = idx & 7;
                int ri = min(blockRow + row, nRows - 1);
                size_t go = (size_t)ri * LAT + koff + q * 8;
                uint32_t sw = swz((uint32_t)(row * 128 + q * 16));
                cpa16(bbase + sw, hHi + go);
                cpa16(bbase + 16384 + sw, hLo + go);
            }
        }
#pragma unroll
        for (int p = 0; p < 4; p++) {
            int idx = tid + 256 * p;
            int row = idx >> 3, q = idx & 7;
            const size_t go = (size_t)row * KTOT + ch * 64 + q * 8;
            uint32_t sw = swz((uint32_t)(row * 128 + q * 16));
            cpa16(bbase + 32768 + sw, W1hi + go);
            cpa16(bbase + 49152 + sw, W1lo + go);
        }
    };
    auto fillW2 = [&]() {
#pragma unroll
        for (int p = 0; p < 8; p++) {
            int idx = tid + 256 * p;
            int row = idx >> 4, q = idx & 15;
            int c2 = q >> 3, qq = q & 7;
            size_t go = (size_t)row * 128 + c2 * 64 + qq * 8;
            uint32_t sw = swz((uint32_t)(row * 128 + qq * 16));
            cpa16(sb + OFF_W2(c2) + sw, W2hi + go);
            cpa16(sb + OFF_W2(c2) + 16384 + sw, W2lo + go);
        }
    };

    constexpr int NC = KTOT / 64;
    fill(0); CPA_COMMIT();
    fill(1); CPA_COMMIT();
    for (int ch = 0; ch < NC; ch++) {
        if (ch < NC - 1) CPA_WAIT(1);
        else CPA_WAIT(0);
        __syncthreads();
        const uint32_t bbase = sb + OFF_BUF(ch & 1);
#pragma unroll
        for (int ks = 0; ks < 4; ks++) {
            const uint32_t kcA = (uint32_t)((ks * 2 + a_kx) * 16) ^ xm;
            const uint32_t kcB = (uint32_t)((ks * 2 + b_kx) * 16) ^ xm;
            uint32_t ah[2][4], al[2][4];
#pragma unroll
            for (int mt = 0; mt < 2; mt++) {
                uint32_t ro = (uint32_t)((a_row0 + mt * 16) * 128);
                ldsm4(bbase + ro + kcA, ah[mt]);
                ldsm4(bbase + 16384 + ro + kcA, al[mt]);
            }
#pragma unroll
            for (int g = 0; g < 4; g++) {
                uint32_t bh[4], bl[4];
                uint32_t ro = (uint32_t)((b_row0 + g * 16) * 128);
                ldsm4(bbase + 32768 + ro + kcB, bh);
                ldsm4(bbase + 49152 + ro + kcB, bl);
#pragma unroll
                for (int mt = 0; mt < 2; mt++)
#pragma unroll
                    for (int hf = 0; hf < 2; hf++) {
                        float* cc = c[mt][g * 2 + hf];
                        mma_bf16(cc, ah[mt], &bh[hf * 2]);
                        mma_bf16(cc, ah[mt], &bl[hf * 2]);
                        mma_bf16(cc, al[mt], &bh[hf * 2]);
                    }
            }
        }
        __syncthreads();
        if (ch + 2 < NC) { fill(ch + 2); CPA_COMMIT(); }
    }
    fillW2();
    CPA_COMMIT();
#pragma unroll
    for (int mt = 0; mt < 2; mt++)
#pragma unroll
        for (int idx = 0; idx < 8; idx++)
#pragma unroll
            for (int e = 0; e < 2; e++) {
                int row = mwarp * 32 + mt * 16 + (lane >> 2) + 8 * e;
                int col = nwarp * 64 + (idx >> 1) * 16 + (idx & 1) * 8 + 2 * (lane & 3);
                float v0 = fmaxf(c[mt][idx][2 * e] + b1s[col], 0.f);
                float v1 = fmaxf(c[mt][idx][2 * e + 1] + b1s[col + 1], 0.f);
                uint32_t hi, lo;
                split_pair(v0, v1, hi, lo);
                uint32_t off = (uint32_t)(nwarp * 16384 + row * 128 +
                                          (((col & 63) * 2) ^ ((row & 7) << 4)));
                *(uint32_t*)(smp + OFF_H_HI + off) = hi;
                *(uint32_t*)(smp + OFF_H_LO + off) = lo;
            }
#pragma unroll
    for (int mt = 0; mt < 2; mt++)
#pragma unroll
        for (int i = 0; i < 8; i++)
#pragma unroll
            for (int j = 0; j < 4; j++) c[mt][i][j] = 0.f;
    CPA_WAIT(0);
    __syncthreads();

#pragma unroll
    for (int c2 = 0; c2 < 2; c2++) {
        const uint32_t abH = sb + OFF_H_HI + c2 * 16384;
        const uint32_t abL = sb + OFF_H_LO + c2 * 16384;
        const uint32_t wb = sb + OFF_W2(c2);
#pragma unroll
        for (int ks = 0; ks < 4; ks++) {
            const uint32_t kcA = (uint32_t)((ks * 2 + a_kx) * 16) ^ xm;
            const uint32_t kcB = (uint32_t)((ks * 2 + b_kx) * 16) ^ xm;
            uint32_t ah[2][4], al[2][4];
#pragma unroll
            for (int mt = 0; mt < 2; mt++) {
                uint32_t ro = (uint32_t)((a_row0 + mt * 16) * 128);
                ldsm4(abH + ro + kcA, ah[mt]);
                ldsm4(abL + ro + kcA, al[mt]);
            }
#pragma unroll
            for (int g = 0; g < 4; g++) {
                uint32_t bh[4], bl[4];
                uint32_t ro = (uint32_t)((b_row0 + g * 16) * 128);
                ldsm4(wb + ro + kcB, bh);
                ldsm4(wb + 16384 + ro + kcB, bl);
#pragma unroll
                for (int mt = 0; mt < 2; mt++)
#pragma unroll
                    for (int hf = 0; hf < 2; hf++) {
                        float* cc = c[mt][g * 2 + hf];
                        mma_bf16(cc, ah[mt], &bh[hf * 2]);
                        mma_bf16(cc, ah[mt], &bl[hf * 2]);
                        mma_bf16(cc, al[mt], &bh[hf * 2]);
                    }
            }
        }
    }

#pragma unroll
    for (int mt = 0; mt < 2; mt++)
#pragma unroll
        for (int idx = 0; idx < 8; idx++) {
            int col = nwarp * 64 + (idx >> 1) * 16 + (idx & 1) * 8 + 2 * (lane & 3);
#pragma unroll
            for (int j = 0; j < 4; j++)
                c[mt][idx][j] = fmaxf(c[mt][idx][j] + b2s[col + (j & 1)], 0.f);
        }

#pragma unroll
    for (int mt = 0; mt < 2; mt++)
#pragma unroll
        for (int e = 0; e < 2; e++) {
            float s = 0.f;
#pragma unroll
            for (int idx = 0; idx < 8; idx++)
                s += c[mt][idx][2 * e] + c[mt][idx][2 * e + 1];
            s += __shfl_xor_sync(0xffffffffu, s, 1);
            s += __shfl_xor_sync(0xffffffffu, s, 2);
            if ((lane & 3) == 0) {
                int row = mwarp * 32 + mt * 16 + (lane >> 2) + 8 * e;
                lnb[row * 2 + nwarp] = s;
            }
        }
    __syncthreads();
    float mu[2][2], rs[2][2];
#pragma unroll
    for (int mt = 0; mt < 2; mt++)
#pragma unroll
        for (int e = 0; e < 2; e++) {
            int row = mwarp * 32 + mt * 16 + (lane >> 2) + 8 * e;
            mu[mt][e] = (lnb[row * 2] + lnb[row * 2 + 1]) * (1.0f / 128.0f);
            float sq = 0.f;
#pragma unroll
            for (int idx = 0; idx < 8; idx++) {
                float d0 = c[mt][idx][2 * e] - mu[mt][e];
                float d1 = c[mt][idx][2 * e + 1] - mu[mt][e];
                sq = fmaf(d0, d0, sq);
                sq = fmaf(d1, d1, sq);
            }
            sq += __shfl_xor_sync(0xffffffffu, sq, 1);
            sq += __shfl_xor_sync(0xffffffffu, sq, 2);
            if ((lane & 3) == 0) lnb[256 + row * 2 + nwarp] = sq;
        }
    __syncthreads();
#pragma unroll
    for (int mt = 0; mt < 2; mt++)
#pragma unroll
        for (int e = 0; e < 2; e++) {
            int row = mwarp * 32 + mt * 16 + (lane >> 2) + 8 * e;
            rs[mt][e] = rsqrtf((lnb[256 + row * 2] + lnb[256 + row * 2 + 1]) *
                                   (1.0f / 128.0f) + EPSV);
        }

#pragma unroll
    for (int mt = 0; mt < 2; mt++)
#pragma unroll
        for (int e = 0; e < 2; e++) {
            int row = mwarp * 32 + mt * 16 + (lane >> 2) + 8 * e;
            int gr = blockRow + row;
            if (gr >= nRows) continue;
            float m = mu[mt][e], q = rs[mt][e];
#pragma unroll
            for (int idx = 0; idx < 8; idx++) {
                int col = nwarp * 64 + (idx >> 1) * 16 + (idx & 1) * 8 + 2 * (lane & 3);
                float v0 = (c[mt][idx][2 * e]     - m) * q * Gs[col]     + BEs[col];
                float v1 = (c[mt][idx][2 * e + 1] - m) * q * Gs[col + 1] + BEs[col + 1];
                uint32_t rh = *(const uint32_t*)&resHi[(size_t)gr * LAT + col];
                uint32_t rl = *(const uint32_t*)&resLo[(size_t)gr * LAT + col];
                v0 += recon(rh, 0) + recon(rl, 0);
                v1 += recon(rh, 1) + recon(rl, 1);
                uint32_t hi, lo;
                split_pair(v0, v1, hi, lo);
                *(uint32_t*)&outHi[(size_t)gr * LAT + col] = hi;
                *(uint32_t*)&outLo[(size_t)gr * LAT + col] = lo;
            }
        }
}

__global__ void prep_all(
    const float* __restrict__ s0, __nv_bfloat16* __restrict__ h0b, __nv_bfloat16* __restrict__ l0b,
    const float* __restrict__ s1, __nv_bfloat16* __restrict__ h1b, __nv_bfloat16* __restrict__ l1b,
    const float* __restrict__ s2, __nv_bfloat16* __restrict__ h2b, __nv_bfloat16* __restrict__ l2b,
    const float* __restrict__ s3, __nv_bfloat16* __restrict__ h3b, __nv_bfloat16* __restrict__ l3b,
    const float* __restrict__ s4, __nv_bfloat16* __restrict__ h4b, __nv_bfloat16* __restrict__ l4b,
    const float* __restrict__ s5, __nv_bfloat16* __restrict__ h5b, __nv_bfloat16* __restrict__ l5b)
{
    int i = blockIdx.x * blockDim.x + threadIdx.x;
    const float* W; __nv_bfloat16 *hi, *lo; int K, j;
    if (i < 49152)       { W = s0; hi = h0b; lo = l0b; K = 384; j = i; }
    else if (i < 65536)  { W = s1; hi = h1b; lo = l1b; K = 128; j = i - 49152; }
    else if (i < 98304)  { W = s2; hi = h2b; lo = l2b; K = 256; j = i - 65536; }
    else if (i < 114688) { W = s3; hi = h3b; lo = l3b; K = 128; j = i - 98304; }
    else if (i < 131072) { W = s4; hi = h4b; lo = l4b; K = 128; j = i - 114688; }
    else if (i < 147456) { W = s5; hi = h5b; lo = l5b; K = 128; j = i - 131072; }
    else return;
    int k = j >> 7, n = j & 127;
    float v = W[j];
    __nv_bfloat16 h = __float2bfloat16(v);
    hi[(size_t)n * K + k] = h;
    lo[(size_t)n * K + k] = __float2bfloat16(v - __bfloat162float(h));
}

__global__ __launch_bounds__(256) void decoder_kernel(
    const __nv_bfloat16* __restrict__ hHi, const __nv_bfloat16* __restrict__ hLo,
    const float* __restrict__ W1, const float* __restrict__ B1,
    const float* __restrict__ W2, const float* __restrict__ B2,
    float* __restrict__ out, int n)
{
    extern __shared__ float s[];
    float* W1s = s;
    float* hs = s + 128 * 128;
    int tid = threadIdx.x;
#pragma unroll
    for (int it = 0; it < 16; it++) {
        int f = tid + 256 * it;
        *(float4*)&W1s[f * 4] = *(const float4*)&W1[f * 4];
    }
    int warp = tid >> 5, lane = tid & 31;
    int row = blockIdx.x * 8 + warp;
    int rc = min(row, n - 1);
#pragma unroll
    for (int q = 0; q < 4; q++) {
        int cc = lane + 32 * q;
        hs[warp * 128 + cc] = __bfloat162float(hHi[(size_t)rc * LAT + cc]) +
                              __bfloat162float(hLo[(size_t)rc * LAT + cc]);
    }
    __syncthreads();

    float acc[4];
#pragma unroll
    for (int q = 0; q < 4; q++) acc[q] = B1[lane + 32 * q];
    for (int k = 0; k < 128; k++) {
        float hv = hs[warp * 128 + k];
#pragma unroll
        for (int q = 0; q < 4; q++)
            acc[q] = fmaf(hv, W1s[k * 128 + lane + 32 * q], acc[q]);
    }
#pragma unroll
    for (int q = 0; q < 4; q++) acc[q] = fmaxf(acc[q], 0.f);

    float o[3];
#pragma unroll
    for (int oo = 0; oo < 3; oo++) {
        float p = 0.f;
#pragma unroll
        for (int q = 0; q < 4; q++)
            p = fmaf(acc[q], W2[(size_t)(lane + 32 * q) * 3 + oo], p);
#pragma unroll
        for (int off = 16; off > 0; off >>= 1)
            p += __shfl_xor_sync(0xffffffffu, p, off);
        o[oo] = p;
    }
    if (lane == 0 && row < n) {
        out[(size_t)row * 3 + 0] = o[0] + B2[0];
        out[(size_t)row * 3 + 1] = o[1] + B2[1];
        out[(size_t)row * 3 + 2] = o[2] + B2[2];
    }
}

__global__ void zero_kernel(float4* __restrict__ p, int n4)
{
    int i = blockIdx.x * blockDim.x + threadIdx.x;
    if (i < n4) p[i] = make_float4(0.f, 0.f, 0.f, 0.f);
}

extern "C" void kernel_launch(void* const* d_in, const int* in_sizes, int n_in,
                              void* d_out, int out_size)
{
    (void)in_sizes; (void)n_in; (void)out_size;
    const float* x  = (const float*)d_in[0];
    const float* ea = (const float*)d_in[1];
    const int*   ei = (const int*)d_in[2];
    const int* src = ei;
    const int* dst = ei + NEDGES;

    const float* ne_w1 = (const float*)d_in[3];
    const float* ne_b1 = (const float*)d_in[4];
    const float* ne_w2 = (const float*)d_in[5];
    const float* ne_b2 = (const float*)d_in[6];
    const float* ne_g  = (const float*)d_in[7];
    const float* ne_be = (const float*)d_in[8];
    const float* ee_w1 = (const float*)d_in[9];
    const float* ee_b1 = (const float*)d_in[10];
    const float* ee_w2 = (const float*)d_in[11];
    const float* ee_b2 = (const float*)d_in[12];
    const float* ee_g  = (const float*)d_in[13];
    const float* ee_be = (const float*)d_in[14];
    const float* em_w1 = (const float*)d_in[15];
    const float* em_b1 = (const float*)d_in[16];
    const float* em_w2 = (const float*)d_in[17];
    const float* em_b2 = (const float*)d_in[18];
    const float* em_g  = (const float*)d_in[19];
    const float* em_be = (const float*)d_in[20];
    const float* nm_w1 = (const float*)d_in[21];
    const float* nm_b1 = (const float*)d_in[22];
    const float* nm_w2 = (const float*)d_in[23];
    const float* nm_b2 = (const float*)d_in[24];
    const float* nm_g  = (const float*)d_in[25];
    const float* nm_be = (const float*)d_in[26];
    const float* dw1   = (const float*)d_in[27];
    const float* db1   = (const float*)d_in[28];
    const float* dw2   = (const float*)d_in[29];
    const float* db2   = (const float*)d_in[30];

    float* fb = nullptr;
    cudaGetSymbolAddress((void**)&fb, g_fbuf);
    float* agg = fb;
    float* Y12 = fb + (size_t)NNODES * LAT;                 // [N,256]
    float* Ye  = fb + (size_t)3 * NNODES * LAT;             // [E,128]

    __nv_bfloat16* hp = nullptr;
    cudaGetSymbolAddress((void**)&hp, g_hpl);
    __nv_bfloat16* ep = nullptr;
    cudaGetSymbolAddress((void**)&ep, g_epl);
    const size_t HS = (size_t)NNODES * LAT, ES = (size_t)NEDGES * LAT;
    __nv_bfloat16 *hH0 = hp, *hL0 = hp + HS, *hH1 = hp + 2 * HS, *hL1 = hp + 3 * HS;
    __nv_bfloat16 *eH0 = ep, *eL0 = ep + ES, *eH1 = ep + 2 * ES, *eL1 = ep + 3 * ES;

    __nv_bfloat16* pl = nullptr;
    cudaGetSymbolAddress((void**)&pl, g_planes);
    __nv_bfloat16* emW1h = pl;
    __nv_bfloat16* emW1l = pl + 49152;
    __nv_bfloat16* emW2h = pl + 98304;
    __nv_bfloat16* emW2l = pl + 114688;
    __nv_bfloat16* nmW1h = pl + 131072;
    __nv_bfloat16* nmW1l = pl + 163840;
    __nv_bfloat16* nmW2h = pl + 196608;
    __nv_bfloat16* nmW2l = pl + 212992;
    __nv_bfloat16* neW2h = pl + 229376;
    __nv_bfloat16* neW2l = pl + 245760;
    __nv_bfloat16* eeW2h = pl + 262144;
    __nv_bfloat16* eeW2l = pl + 278528;

    cudaFuncSetAttribute(node_update,
                         cudaFuncAttributeMaxDynamicSharedMemorySize, SMEM_DYN);
    cudaFuncSetAttribute(edge_fused,
                         cudaFuncAttributeMaxDynamicSharedMemorySize, SMEM_E);
    cudaFuncSetAttribute(gemm_y12,
                         cudaFuncAttributeMaxDynamicSharedMemorySize, SMEM_Y);
    cudaFuncSetAttribute(encode_mlp,
                         cudaFuncAttributeMaxDynamicSharedMemorySize, SMEM_N);
    const int DSM = (128 * 128 + 8 * 128) * (int)sizeof(float);
    cudaFuncSetAttribute(decoder_kernel,
                         cudaFuncAttributeMaxDynamicSharedMemorySize, DSM);

    prep_all<<<(147456 + 255) / 256, 256>>>(
        em_w1, emW1h, emW1l, em_w2, emW2h, emW2l,
        nm_w1, nmW1h, nmW1l, nm_w2, nmW2h, nmW2l,
        ne_w2, neW2h, neW2l, ee_w2, eeW2h, eeW2l);

    dim3 blk(256);
    const int ntiles = (NNODES + 127) / 128;  // 391
    const int etiles = NEDGES / 128;          // 3125

    // encoders; edge encoder also produces Ye for step 0
    encode_mlp<<<ntiles, blk, SMEM_N>>>(
        x, ne_w1, 3, ne_b1, neW2h, neW2l, ne_b2, ne_g, ne_be,
        nullptr, nullptr, nullptr, nullptr, 0, hH0, hL0, NNODES);
    encode_mlp<<<etiles, blk, SMEM_N>>>(
        ea, ee_w1, 4, ee_b1, eeW2h, eeW2l, ee_b2, ee_g, ee_be,
        emW1h, emW1l, em_b1, Ye, 1, eH0, eL0, NEDGES);

    __nv_bfloat16 *hcH = hH0, *hcL = hL0, *hnH = hH1, *hnL = hL1;
    __nv_bfloat16 *ecH = eH0, *ecL = eL0, *enH = eH1, *enL = eL1;
    for (int s = 0; s < 5; s++) {
        gemm_y12<<<ntiles, blk, SMEM_Y>>>(hcH, hcL, emW1h, emW1l, Y12, NNODES);
        zero_kernel<<<(NNODES * LAT / 4 + 255) / 256, 256>>>((float4*)agg,
                                                             NNODES * LAT / 4);
        edge_fused<<<etiles, blk, SMEM_E>>>(
            Y12, Ye, dst, src, emW2h, emW2l, em_b2, em_g, em_be,
            emW1h, emW1l, em_b1,
            ecH, ecL, enH, enL, agg, (s < 4) ? 1 : 0, NEDGES);
        node_update<<<ntiles, blk, SMEM_DYN>>>(
            agg, hcH, hcL, nmW1h, nmW1l, nm_b1, nmW2h, nmW2l, nm_b2, nm_g, nm_be,
            hcH, hcL, hnH, hnL, NNODES);
        __nv_bfloat16* t;
        t = hcH; hcH = hnH; hnH = t;
        t = hcL; hcL = hnL; hnL = t;
        t = ecH; ecH = enH; enH = t;
        t = ecL; ecL = enL; enL = t;
    }

    decoder_kernel<<<(NNODES + 7) / 8, blk, DSM>>>(
        hcH, hcL, dw1, db1, dw2, db2, (float*)d_out, NNODES);
}